// round 2
// baseline (speedup 1.0000x reference)
#include <cuda_runtime.h>
#include <math.h>

#define D_MODEL 2048
#define N_HEADS 16
#define D_HEAD  128
#define BATCH   2
#define SEQ     2048
#define M_TOT   (BATCH*SEQ)      /* 4096 */
#define NQKV    (3*D_MODEL)      /* 6144 */
#define EPSF    1e-6f

// ---------------- scratch (device globals; no allocs allowed) ----------------
__device__ float g_qkv[(size_t)M_TOT * NQKV];     // 100 MB
__device__ float g_qn [(size_t)M_TOT * D_MODEL];  // 32 MB
__device__ float g_kn [(size_t)M_TOT * D_MODEL];  // 32 MB
__device__ float g_z  [(size_t)M_TOT * D_MODEL];  // 32 MB

// ---------------- SGEMM: C[M,N] = A[M,K] * B[N,K]^T + bias[N] ----------------
// BM=BN=128, BK=8, 256 threads, 8x8 per thread.
__global__ __launch_bounds__(256) void sgemm_bias(
    const float* __restrict__ A, const float* __restrict__ B,
    const float* __restrict__ bias, float* __restrict__ C,
    int N, int K)
{
    __shared__ float As[8][128];
    __shared__ float Bs[8][128];
    const int bm = blockIdx.y * 128;
    const int bn = blockIdx.x * 128;
    const int tid = threadIdx.x;
    const int tx = tid & 15, ty = tid >> 4;
    const int lrow = tid >> 1;
    const int lk   = (tid & 1) * 4;

    const float* Ap = A + (size_t)(bm + lrow) * K + lk;
    const float* Bp = B + (size_t)(bn + lrow) * K + lk;

    float acc[8][8];
    #pragma unroll
    for (int i = 0; i < 8; ++i)
        #pragma unroll
        for (int j = 0; j < 8; ++j) acc[i][j] = 0.f;

    for (int k0 = 0; k0 < K; k0 += 8) {
        float4 av = *(const float4*)(Ap + k0);
        float4 bv = *(const float4*)(Bp + k0);
        __syncthreads();
        As[lk+0][lrow] = av.x; As[lk+1][lrow] = av.y;
        As[lk+2][lrow] = av.z; As[lk+3][lrow] = av.w;
        Bs[lk+0][lrow] = bv.x; Bs[lk+1][lrow] = bv.y;
        Bs[lk+2][lrow] = bv.z; Bs[lk+3][lrow] = bv.w;
        __syncthreads();
        #pragma unroll
        for (int kk = 0; kk < 8; ++kk) {
            float4 a0 = *(const float4*)&As[kk][ty*8];
            float4 a1 = *(const float4*)&As[kk][ty*8+4];
            float4 b0 = *(const float4*)&Bs[kk][tx*8];
            float4 b1 = *(const float4*)&Bs[kk][tx*8+4];
            float a[8] = {a0.x,a0.y,a0.z,a0.w,a1.x,a1.y,a1.z,a1.w};
            float b[8] = {b0.x,b0.y,b0.z,b0.w,b1.x,b1.y,b1.z,b1.w};
            #pragma unroll
            for (int i = 0; i < 8; ++i)
                #pragma unroll
                for (int j = 0; j < 8; ++j)
                    acc[i][j] += a[i] * b[j];
        }
    }

    #pragma unroll
    for (int i = 0; i < 8; ++i) {
        const int row = bm + ty*8 + i;
        float* dst = C + (size_t)row * N + bn + tx*8;
        const float* bp = bias + bn + tx*8;
        float4 o0, o1;
        o0.x = acc[i][0] + bp[0]; o0.y = acc[i][1] + bp[1];
        o0.z = acc[i][2] + bp[2]; o0.w = acc[i][3] + bp[3];
        o1.x = acc[i][4] + bp[4]; o1.y = acc[i][5] + bp[5];
        o1.z = acc[i][6] + bp[6]; o1.w = acc[i][7] + bp[7];
        *(float4*)(dst)     = o0;
        *(float4*)(dst + 4) = o1;
    }
}

// --------------- norm/split: q->rmsnorm(g_qn), k->(k_out, g_kn), v->v_out ----
__global__ __launch_bounds__(128) void norm_split(
    const float* __restrict__ wq, const float* __restrict__ wk,
    float* __restrict__ k_out, float* __restrict__ v_out)
{
    const int m = blockIdx.x;   // 0..4095
    const int h = blockIdx.y;   // 0..15
    const int t = threadIdx.x;  // 0..127
    const float* row = g_qkv + (size_t)m * NQKV;
    const float q = row[h*D_HEAD + t];
    const float k = row[D_MODEL   + h*D_HEAD + t];
    const float v = row[2*D_MODEL + h*D_HEAD + t];

    const size_t oidx = (size_t)m * D_MODEL + h*D_HEAD + t;
    k_out[oidx] = k;   // pre-norm k is an output
    v_out[oidx] = v;

    float sq = q*q, sk = k*k;
    #pragma unroll
    for (int off = 16; off > 0; off >>= 1) {
        sq += __shfl_xor_sync(0xffffffffu, sq, off);
        sk += __shfl_xor_sync(0xffffffffu, sk, off);
    }
    __shared__ float bufq[4], bufk[4];
    if ((t & 31) == 0) { bufq[t>>5] = sq; bufk[t>>5] = sk; }
    __syncthreads();
    sq = bufq[0] + bufq[1] + bufq[2] + bufq[3];
    sk = bufk[0] + bufk[1] + bufk[2] + bufk[3];
    const float rq = rsqrtf(sq * (1.f/128.f) + EPSF);
    const float rk = rsqrtf(sk * (1.f/128.f) + EPSF);
    g_qn[oidx] = q * rq * wq[t];
    g_kn[oidx] = k * rk * wk[t];
}

// --------------- flash attention: fp32, BQ=64, BK=64, D=128 ------------------
// smem: Qt[128][64] | Kt[128][64] | Vs[64][132] | Ps[64][65]
#define ATT_SMEM ((128*64 + 128*64 + 64*132 + 64*65) * 4)

__global__ __launch_bounds__(256) void attn_kernel(const float* __restrict__ vsrc_base)
{
    extern __shared__ float sm[];
    float* Qt = sm;                   // [d][r]  8192
    float* Kt = Qt + 128*64;          // [d][r]  8192
    float* Vs = Kt + 128*64;          // [r][c] stride 132 -> 8448
    float* Ps = Vs + 64*132;          // [r][j] stride 65  -> 4160

    const int qt = blockIdx.x;        // 0..31 query tiles
    const int bh = blockIdx.y;        // 0..31
    const int b  = bh >> 4, h = bh & 15;
    const int tid = threadIdx.x;
    const int tx = tid & 15, ty = tid >> 4;
    const size_t baserow = (size_t)b * SEQ;
    const int colbase = h * D_HEAD;
    const int q0 = qt * 64;

    // load Q tile transposed
    {
        const int r  = tid >> 2;
        const int c0 = (tid & 3) * 32;
        const float* src = g_qn + (baserow + q0 + r) * (size_t)D_MODEL + colbase + c0;
        #pragma unroll
        for (int i = 0; i < 32; i += 4) {
            float4 v4 = *(const float4*)(src + i);
            Qt[(c0+i+0)*64 + r] = v4.x;
            Qt[(c0+i+1)*64 + r] = v4.y;
            Qt[(c0+i+2)*64 + r] = v4.z;
            Qt[(c0+i+3)*64 + r] = v4.w;
        }
    }

    float m_i[4], l_i[4], O[4][8];
    #pragma unroll
    for (int i = 0; i < 4; ++i) {
        m_i[i] = -1e30f; l_i[i] = 0.f;
        #pragma unroll
        for (int c = 0; c < 8; ++c) O[i][c] = 0.f;
    }

    for (int kt = 0; kt < SEQ/64; ++kt) {
        __syncthreads();   // previous PV done; Ks/Vs/Ps reusable
        {
            const int r  = tid >> 2;
            const int c0 = (tid & 3) * 32;
            const float* ks = g_kn      + (baserow + kt*64 + r) * (size_t)D_MODEL + colbase + c0;
            const float* vs = vsrc_base + (baserow + kt*64 + r) * (size_t)D_MODEL + colbase + c0;
            #pragma unroll
            for (int i = 0; i < 32; i += 4) {
                float4 kv = *(const float4*)(ks + i);
                Kt[(c0+i+0)*64 + r] = kv.x;
                Kt[(c0+i+1)*64 + r] = kv.y;
                Kt[(c0+i+2)*64 + r] = kv.z;
                Kt[(c0+i+3)*64 + r] = kv.w;
                float4 vv = *(const float4*)(vs + i);
                *(float4*)&Vs[r*132 + c0 + i] = vv;
            }
        }
        __syncthreads();

        // S = Qn * Kn^T (64x64), 4x4 per thread
        float s[4][4];
        #pragma unroll
        for (int i = 0; i < 4; ++i)
            #pragma unroll
            for (int j = 0; j < 4; ++j) s[i][j] = 0.f;
        #pragma unroll 8
        for (int d = 0; d < 128; ++d) {
            float4 aq = *(const float4*)&Qt[d*64 + ty*4];
            float4 bk = *(const float4*)&Kt[d*64 + tx*4];
            float ar[4] = {aq.x, aq.y, aq.z, aq.w};
            float br[4] = {bk.x, bk.y, bk.z, bk.w};
            #pragma unroll
            for (int i = 0; i < 4; ++i)
                #pragma unroll
                for (int j = 0; j < 4; ++j)
                    s[i][j] += ar[i] * br[j];
        }

        // online softmax (row groups = same ty, reduce across 16 tx lanes)
        #pragma unroll
        for (int i = 0; i < 4; ++i) {
            float mx = fmaxf(fmaxf(s[i][0], s[i][1]), fmaxf(s[i][2], s[i][3]));
            #pragma unroll
            for (int off = 8; off > 0; off >>= 1)
                mx = fmaxf(mx, __shfl_xor_sync(0xffffffffu, mx, off, 16));
            const float mnew = fmaxf(m_i[i], mx);
            const float corr = __expf(m_i[i] - mnew);
            m_i[i] = mnew;
            float rs = 0.f;
            #pragma unroll
            for (int j = 0; j < 4; ++j) {
                s[i][j] = __expf(s[i][j] - mnew);
                rs += s[i][j];
            }
            #pragma unroll
            for (int off = 8; off > 0; off >>= 1)
                rs += __shfl_xor_sync(0xffffffffu, rs, off, 16);
            l_i[i] = l_i[i] * corr + rs;
            #pragma unroll
            for (int c = 0; c < 8; ++c) O[i][c] *= corr;
            #pragma unroll
            for (int j = 0; j < 4; ++j)
                Ps[(ty*4+i)*65 + tx*4+j] = s[i][j];
        }
        __syncthreads();

        // O += P * V  (rows ty*4.., cols tx*8..)
        #pragma unroll 4
        for (int j = 0; j < 64; ++j) {
            float4 v0 = *(const float4*)&Vs[j*132 + tx*8];
            float4 v1 = *(const float4*)&Vs[j*132 + tx*8 + 4];
            float vv[8] = {v0.x,v0.y,v0.z,v0.w,v1.x,v1.y,v1.z,v1.w};
            #pragma unroll
            for (int i = 0; i < 4; ++i) {
                const float p = Ps[(ty*4+i)*65 + j];
                #pragma unroll
                for (int c = 0; c < 8; ++c) O[i][c] += p * vv[c];
            }
        }
    }

    // epilogue
    #pragma unroll
    for (int i = 0; i < 4; ++i) {
        const float inv = 1.f / l_i[i];
        const size_t row = baserow + q0 + ty*4 + i;
        float* dst = g_z + row * D_MODEL + colbase + tx*8;
        float4 o0, o1;
        o0.x = O[i][0]*inv; o0.y = O[i][1]*inv; o0.z = O[i][2]*inv; o0.w = O[i][3]*inv;
        o1.x = O[i][4]*inv; o1.y = O[i][5]*inv; o1.z = O[i][6]*inv; o1.w = O[i][7]*inv;
        *(float4*)(dst)     = o0;
        *(float4*)(dst + 4) = o1;
    }
}

// -----------------------------------------------------------------------------
extern "C" void kernel_launch(void* const* d_in, const int* in_sizes, int n_in,
                              void* d_out, int out_size)
{
    const float* x     = (const float*)d_in[0];
    const float* W_qkv = (const float*)d_in[1];
    const float* b_qkv = (const float*)d_in[2];
    const float* W_o   = (const float*)d_in[3];
    const float* b_o   = (const float*)d_in[4];
    const float* wq    = (const float*)d_in[5];
    const float* wk    = (const float*)d_in[6];

    float* out   = (float*)d_out;
    float* k_out = out   + (size_t)M_TOT * D_MODEL;
    float* v_out = k_out + (size_t)M_TOT * D_MODEL;

    float* qkv; cudaGetSymbolAddress((void**)&qkv, g_qkv);
    float* z;   cudaGetSymbolAddress((void**)&z,   g_z);

    // 1) qkv = x @ W_qkv^T + b_qkv
    sgemm_bias<<<dim3(NQKV/128, M_TOT/128), 256>>>(x, W_qkv, b_qkv, qkv, NQKV, D_MODEL);

    // 2) split + rms-norm
    norm_split<<<dim3(M_TOT, N_HEADS), 128>>>(wq, wk, k_out, v_out);

    // 3) attention -> g_z
    cudaFuncSetAttribute(attn_kernel, cudaFuncAttributeMaxDynamicSharedMemorySize, ATT_SMEM);
    attn_kernel<<<dim3(SEQ/64, BATCH*N_HEADS), 256, ATT_SMEM>>>(v_out);

    // 4) out = z @ W_o^T + b_o
    sgemm_bias<<<dim3(D_MODEL/128, M_TOT/128), 256>>>(z, W_o, b_o, out, D_MODEL, D_MODEL);
}

// round 5
// speedup vs baseline: 1.4167x; 1.4167x over previous
#include <cuda_runtime.h>
#include <cuda_bf16.h>
#include <math.h>
#include <stdint.h>

#define D_MODEL 2048
#define N_HEADS 16
#define D_HEAD  128
#define BATCH   2
#define SEQ     2048
#define M_TOT   (BATCH*SEQ)      /* 4096 */
#define NQKV    (3*D_MODEL)      /* 6144 */
#define EPSF    1e-6f

// ---------------- scratch (device globals; no allocs allowed) ----------------
__device__ float g_qkv[(size_t)M_TOT * NQKV];     // 100 MB
__device__ float g_qn [(size_t)M_TOT * D_MODEL];
__device__ float g_kn [(size_t)M_TOT * D_MODEL];
__device__ float g_z  [(size_t)M_TOT * D_MODEL];

__device__ __nv_bfloat16 g_xh[(size_t)M_TOT * D_MODEL];
__device__ __nv_bfloat16 g_xl[(size_t)M_TOT * D_MODEL];
__device__ __nv_bfloat16 g_wqkvh[(size_t)NQKV * D_MODEL];
__device__ __nv_bfloat16 g_wqkvl[(size_t)NQKV * D_MODEL];
__device__ __nv_bfloat16 g_woh[(size_t)D_MODEL * D_MODEL];
__device__ __nv_bfloat16 g_wol[(size_t)D_MODEL * D_MODEL];
__device__ __nv_bfloat16 g_zh[(size_t)M_TOT * D_MODEL];
__device__ __nv_bfloat16 g_zl[(size_t)M_TOT * D_MODEL];

// ---------------- fp32 -> bf16 hi/lo split ----------------------------------
__global__ __launch_bounds__(256) void conv_split(
    const float* __restrict__ s, __nv_bfloat16* __restrict__ hi,
    __nv_bfloat16* __restrict__ lo, int n4)
{
    int i = blockIdx.x * blockDim.x + threadIdx.x;
    if (i >= n4) return;
    float4 v = ((const float4*)s)[i];
    __nv_bfloat162 h01, h23, l01, l23;
    h01.x = __float2bfloat16(v.x); h01.y = __float2bfloat16(v.y);
    h23.x = __float2bfloat16(v.z); h23.y = __float2bfloat16(v.w);
    l01.x = __float2bfloat16(v.x - __bfloat162float(h01.x));
    l01.y = __float2bfloat16(v.y - __bfloat162float(h01.y));
    l23.x = __float2bfloat16(v.z - __bfloat162float(h23.x));
    l23.y = __float2bfloat16(v.w - __bfloat162float(h23.y));
    ((__nv_bfloat162*)hi)[i*2]   = h01;
    ((__nv_bfloat162*)hi)[i*2+1] = h23;
    ((__nv_bfloat162*)lo)[i*2]   = l01;
    ((__nv_bfloat162*)lo)[i*2+1] = l23;
}

// ---------------- HMMA split-bf16 GEMM ---------------------------------------
// C[M,N] = A[M,K]*B[N,K]^T + bias, A/B given as bf16 hi/lo pairs, 3 passes.
// CTA 128x128, BK=32, 8 warps (4x2), warp tile 32x64, 2-stage cp.async.
__device__ __forceinline__ uint32_t smem_u32(const void* p) {
    uint32_t a;
    asm("{ .reg .u64 t; cvta.to.shared.u64 t, %1; cvt.u32.u64 %0, t; }"
        : "=r"(a) : "l"(p));
    return a;
}

#define MMA(c, a, b) \
    asm volatile("mma.sync.aligned.m16n8k16.row.col.f32.bf16.bf16.f32 " \
                 "{%0,%1,%2,%3},{%4,%5,%6,%7},{%8,%9},{%0,%1,%2,%3};" \
                 : "+f"((c)[0]), "+f"((c)[1]), "+f"((c)[2]), "+f"((c)[3]) \
                 : "r"((a)[0]), "r"((a)[1]), "r"((a)[2]), "r"((a)[3]), \
                   "r"((b)[0]), "r"((b)[1]))

#define TILE_E 5120                 /* 128 rows * 40 elems */
#define STG_E  (4*TILE_E)           /* Ah,Al,Bh,Bl */
#define GEMM_SMEM (2*STG_E*2)       /* bytes: 81920 */

__global__ __launch_bounds__(256) void gemm_tc(
    const __nv_bfloat16* __restrict__ pAh, const __nv_bfloat16* __restrict__ pAl,
    const __nv_bfloat16* __restrict__ pBh, const __nv_bfloat16* __restrict__ pBl,
    const float* __restrict__ bias, float* __restrict__ C, int N, int K)
{
    extern __shared__ __nv_bfloat16 sm[];
    const int tid = threadIdx.x, lane = tid & 31, wid = tid >> 5;
    const int wm = wid >> 1, wn = wid & 1;
    const int bm = blockIdx.y * 128, bn = blockIdx.x * 128;
    const uint32_t smb = smem_u32(sm);

    float acc[2][8][4];
    #pragma unroll
    for (int mt = 0; mt < 2; ++mt)
        #pragma unroll
        for (int nt = 0; nt < 8; ++nt)
            #pragma unroll
            for (int j = 0; j < 4; ++j) acc[mt][nt][j] = 0.f;

    const int nch = K / 32;

    const __nv_bfloat16* srcs[4] = {
        pAh + (size_t)bm * K, pAl + (size_t)bm * K,
        pBh + (size_t)bn * K, pBl + (size_t)bn * K };

    const int lrow = tid >> 2, lcc = tid & 3;       // chunk 0
    const int lrow2 = (tid + 256) >> 2;             // chunk 1 (cc same)

    #define ISSUE(st, ch) do {                                             \
        const int _k0 = (ch) * 32;                                         \
        _Pragma("unroll")                                                  \
        for (int _t = 0; _t < 4; ++_t) {                                   \
            const __nv_bfloat16* _s0 = srcs[_t] + _k0 + lcc * 8;           \
            uint32_t _d0 = smb + (uint32_t)(((st)*4 + _t) * (TILE_E*2));   \
            const void* _sp1 = _s0 + (size_t)lrow * K;                     \
            uint32_t _dp1 = _d0 + (uint32_t)(lrow * 80 + lcc * 16);        \
            asm volatile("cp.async.cg.shared.global [%0], [%1], 16;"       \
                         :: "r"(_dp1), "l"(_sp1));                         \
            const void* _sp2 = _s0 + (size_t)lrow2 * K;                    \
            uint32_t _dp2 = _d0 + (uint32_t)(lrow2 * 80 + lcc * 16);       \
            asm volatile("cp.async.cg.shared.global [%0], [%1], 16;"       \
                         :: "r"(_dp2), "l"(_sp2));                         \
        }                                                                  \
        asm volatile("cp.async.commit_group;" ::: "memory");               \
    } while (0)

    ISSUE(0, 0);

    for (int ch = 0; ch < nch; ++ch) {
        const int st = ch & 1;
        if (ch + 1 < nch) {
            ISSUE(st ^ 1, ch + 1);
            asm volatile("cp.async.wait_group 1;" ::: "memory");
        } else {
            asm volatile("cp.async.wait_group 0;" ::: "memory");
        }
        __syncthreads();

        const __nv_bfloat16* sAh = sm + st * STG_E;
        const __nv_bfloat16* sAl = sAh + TILE_E;
        const __nv_bfloat16* sBh = sAh + 2 * TILE_E;
        const __nv_bfloat16* sBl = sAh + 3 * TILE_E;

        #pragma unroll
        for (int k16 = 0; k16 < 2; ++k16) {
            const int c = (lane & 3) * 2 + k16 * 16;
            uint32_t ah[2][4], al[2][4], bh[8][2], bl[8][2];
            #pragma unroll
            for (int mt = 0; mt < 2; ++mt) {
                const int r1 = wm * 32 + mt * 16 + (lane >> 2);
                ah[mt][0] = *(const uint32_t*)&sAh[r1 * 40 + c];
                ah[mt][1] = *(const uint32_t*)&sAh[(r1 + 8) * 40 + c];
                ah[mt][2] = *(const uint32_t*)&sAh[r1 * 40 + c + 8];
                ah[mt][3] = *(const uint32_t*)&sAh[(r1 + 8) * 40 + c + 8];
                al[mt][0] = *(const uint32_t*)&sAl[r1 * 40 + c];
                al[mt][1] = *(const uint32_t*)&sAl[(r1 + 8) * 40 + c];
                al[mt][2] = *(const uint32_t*)&sAl[r1 * 40 + c + 8];
                al[mt][3] = *(const uint32_t*)&sAl[(r1 + 8) * 40 + c + 8];
            }
            #pragma unroll
            for (int nt = 0; nt < 8; ++nt) {
                const int n = wn * 64 + nt * 8 + (lane >> 2);
                bh[nt][0] = *(const uint32_t*)&sBh[n * 40 + c];
                bh[nt][1] = *(const uint32_t*)&sBh[n * 40 + c + 8];
                bl[nt][0] = *(const uint32_t*)&sBl[n * 40 + c];
                bl[nt][1] = *(const uint32_t*)&sBl[n * 40 + c + 8];
            }
            #pragma unroll
            for (int mt = 0; mt < 2; ++mt)
                #pragma unroll
                for (int nt = 0; nt < 8; ++nt) {
                    MMA(acc[mt][nt], ah[mt], bh[nt]);
                    MMA(acc[mt][nt], ah[mt], bl[nt]);
                    MMA(acc[mt][nt], al[mt], bh[nt]);
                }
        }
        __syncthreads();
    }

    // epilogue: bias + store
    #pragma unroll
    for (int mt = 0; mt < 2; ++mt) {
        const int r1 = bm + wm * 32 + mt * 16 + (lane >> 2);
        const int r2 = r1 + 8;
        #pragma unroll
        for (int nt = 0; nt < 8; ++nt) {
            const int cb = bn + wn * 64 + nt * 8 + (lane & 3) * 2;
            const float b0 = bias[cb], b1 = bias[cb + 1];
            float2 o1, o2;
            o1.x = acc[mt][nt][0] + b0; o1.y = acc[mt][nt][1] + b1;
            o2.x = acc[mt][nt][2] + b0; o2.y = acc[mt][nt][3] + b1;
            *(float2*)&C[(size_t)r1 * N + cb] = o1;
            *(float2*)&C[(size_t)r2 * N + cb] = o2;
        }
    }
}

// --------------- norm/split: q->rmsnorm(g_qn), k->(k_out, g_kn), v->v_out ----
__global__ __launch_bounds__(128) void norm_split(
    const float* __restrict__ wq, const float* __restrict__ wk,
    float* __restrict__ k_out, float* __restrict__ v_out)
{
    const int m = blockIdx.x;
    const int h = blockIdx.y;
    const int t = threadIdx.x;
    const float* row = g_qkv + (size_t)m * NQKV;
    const float q = row[h*D_HEAD + t];
    const float k = row[D_MODEL   + h*D_HEAD + t];
    const float v = row[2*D_MODEL + h*D_HEAD + t];

    const size_t oidx = (size_t)m * D_MODEL + h*D_HEAD + t;
    k_out[oidx] = k;
    v_out[oidx] = v;

    float sq = q*q, sk = k*k;
    #pragma unroll
    for (int off = 16; off > 0; off >>= 1) {
        sq += __shfl_xor_sync(0xffffffffu, sq, off);
        sk += __shfl_xor_sync(0xffffffffu, sk, off);
    }
    __shared__ float bufq[4], bufk[4];
    if ((t & 31) == 0) { bufq[t>>5] = sq; bufk[t>>5] = sk; }
    __syncthreads();
    sq = bufq[0] + bufq[1] + bufq[2] + bufq[3];
    sk = bufk[0] + bufk[1] + bufk[2] + bufk[3];
    const float rq = rsqrtf(sq * (1.f/128.f) + EPSF);
    const float rk = rsqrtf(sk * (1.f/128.f) + EPSF);
    g_qn[oidx] = q * rq * wq[t];
    g_kn[oidx] = k * rk * wk[t];
}

// --------------- flash attention: fp32, BQ=64, BK=64, D=128 ------------------
#define ATT_SMEM ((128*64 + 128*64 + 64*132 + 64*65) * 4)

__global__ __launch_bounds__(256) void attn_kernel(const float* __restrict__ vsrc_base)
{
    extern __shared__ float smf[];
    float* Qt = smf;
    float* Kt = Qt + 128*64;
    float* Vs = Kt + 128*64;
    float* Ps = Vs + 64*132;

    const int qt = blockIdx.x;
    const int bh = blockIdx.y;
    const int b  = bh >> 4, h = bh & 15;
    const int tid = threadIdx.x;
    const int tx = tid & 15, ty = tid >> 4;
    const size_t baserow = (size_t)b * SEQ;
    const int colbase = h * D_HEAD;
    const int q0 = qt * 64;

    {
        const int r  = tid >> 2;
        const int c0 = (tid & 3) * 32;
        const float* src = g_qn + (baserow + q0 + r) * (size_t)D_MODEL + colbase + c0;
        #pragma unroll
        for (int i = 0; i < 32; i += 4) {
            float4 v4 = *(const float4*)(src + i);
            Qt[(c0+i+0)*64 + r] = v4.x;
            Qt[(c0+i+1)*64 + r] = v4.y;
            Qt[(c0+i+2)*64 + r] = v4.z;
            Qt[(c0+i+3)*64 + r] = v4.w;
        }
    }

    float m_i[4], l_i[4], O[4][8];
    #pragma unroll
    for (int i = 0; i < 4; ++i) {
        m_i[i] = -1e30f; l_i[i] = 0.f;
        #pragma unroll
        for (int c = 0; c < 8; ++c) O[i][c] = 0.f;
    }

    for (int kt = 0; kt < SEQ/64; ++kt) {
        __syncthreads();
        {
            const int r  = tid >> 2;
            const int c0 = (tid & 3) * 32;
            const float* ks = g_kn      + (baserow + kt*64 + r) * (size_t)D_MODEL + colbase + c0;
            const float* vs = vsrc_base + (baserow + kt*64 + r) * (size_t)D_MODEL + colbase + c0;
            #pragma unroll
            for (int i = 0; i < 32; i += 4) {
                float4 kv = *(const float4*)(ks + i);
                Kt[(c0+i+0)*64 + r] = kv.x;
                Kt[(c0+i+1)*64 + r] = kv.y;
                Kt[(c0+i+2)*64 + r] = kv.z;
                Kt[(c0+i+3)*64 + r] = kv.w;
                float4 vv = *(const float4*)(vs + i);
                *(float4*)&Vs[r*132 + c0 + i] = vv;
            }
        }
        __syncthreads();

        float s[4][4];
        #pragma unroll
        for (int i = 0; i < 4; ++i)
            #pragma unroll
            for (int j = 0; j < 4; ++j) s[i][j] = 0.f;
        #pragma unroll 8
        for (int d = 0; d < 128; ++d) {
            float4 aq = *(const float4*)&Qt[d*64 + ty*4];
            float4 bk = *(const float4*)&Kt[d*64 + tx*4];
            float ar[4] = {aq.x, aq.y, aq.z, aq.w};
            float br[4] = {bk.x, bk.y, bk.z, bk.w};
            #pragma unroll
            for (int i = 0; i < 4; ++i)
                #pragma unroll
                for (int j = 0; j < 4; ++j)
                    s[i][j] += ar[i] * br[j];
        }

        #pragma unroll
        for (int i = 0; i < 4; ++i) {
            float mx = fmaxf(fmaxf(s[i][0], s[i][1]), fmaxf(s[i][2], s[i][3]));
            #pragma unroll
            for (int off = 8; off > 0; off >>= 1)
                mx = fmaxf(mx, __shfl_xor_sync(0xffffffffu, mx, off, 16));
            const float mnew = fmaxf(m_i[i], mx);
            const float corr = __expf(m_i[i] - mnew);
            m_i[i] = mnew;
            float rs = 0.f;
            #pragma unroll
            for (int j = 0; j < 4; ++j) {
                s[i][j] = __expf(s[i][j] - mnew);
                rs += s[i][j];
            }
            #pragma unroll
            for (int off = 8; off > 0; off >>= 1)
                rs += __shfl_xor_sync(0xffffffffu, rs, off, 16);
            l_i[i] = l_i[i] * corr + rs;
            #pragma unroll
            for (int c = 0; c < 8; ++c) O[i][c] *= corr;
            #pragma unroll
            for (int j = 0; j < 4; ++j)
                Ps[(ty*4+i)*65 + tx*4+j] = s[i][j];
        }
        __syncthreads();

        #pragma unroll 4
        for (int j = 0; j < 64; ++j) {
            float4 v0 = *(const float4*)&Vs[j*132 + tx*8];
            float4 v1 = *(const float4*)&Vs[j*132 + tx*8 + 4];
            float vv[8] = {v0.x,v0.y,v0.z,v0.w,v1.x,v1.y,v1.z,v1.w};
            #pragma unroll
            for (int i = 0; i < 4; ++i) {
                const float p = Ps[(ty*4+i)*65 + j];
                #pragma unroll
                for (int c = 0; c < 8; ++c) O[i][c] += p * vv[c];
            }
        }
    }

    #pragma unroll
    for (int i = 0; i < 4; ++i) {
        const float inv = 1.f / l_i[i];
        const size_t row = baserow + q0 + ty*4 + i;
        float* dst = g_z + row * D_MODEL + colbase + tx*8;
        float4 o0, o1;
        o0.x = O[i][0]*inv; o0.y = O[i][1]*inv; o0.z = O[i][2]*inv; o0.w = O[i][3]*inv;
        o1.x = O[i][4]*inv; o1.y = O[i][5]*inv; o1.z = O[i][6]*inv; o1.w = O[i][7]*inv;
        *(float4*)(dst)     = o0;
        *(float4*)(dst + 4) = o1;
    }
}

// -----------------------------------------------------------------------------
extern "C" void kernel_launch(void* const* d_in, const int* in_sizes, int n_in,
                              void* d_out, int out_size)
{
    const float* x     = (const float*)d_in[0];
    const float* W_qkv = (const float*)d_in[1];
    const float* b_qkv = (const float*)d_in[2];
    const float* W_o   = (const float*)d_in[3];
    const float* b_o   = (const float*)d_in[4];
    const float* wq    = (const float*)d_in[5];
    const float* wk    = (const float*)d_in[6];

    float* out   = (float*)d_out;
    float* k_out = out   + (size_t)M_TOT * D_MODEL;
    float* v_out = k_out + (size_t)M_TOT * D_MODEL;

    float *qkv, *z;
    cudaGetSymbolAddress((void**)&qkv, g_qkv);
    cudaGetSymbolAddress((void**)&z,   g_z);
    __nv_bfloat16 *xh, *xl, *wqh, *wql, *woh, *wol, *zh, *zl;
    cudaGetSymbolAddress((void**)&xh,  g_xh);
    cudaGetSymbolAddress((void**)&xl,  g_xl);
    cudaGetSymbolAddress((void**)&wqh, g_wqkvh);
    cudaGetSymbolAddress((void**)&wql, g_wqkvl);
    cudaGetSymbolAddress((void**)&woh, g_woh);
    cudaGetSymbolAddress((void**)&wol, g_wol);
    cudaGetSymbolAddress((void**)&zh,  g_zh);
    cudaGetSymbolAddress((void**)&zl,  g_zl);

    static bool attr_set = false;
    if (!attr_set) {
        cudaFuncSetAttribute(gemm_tc, cudaFuncAttributeMaxDynamicSharedMemorySize, GEMM_SMEM);
        cudaFuncSetAttribute(attn_kernel, cudaFuncAttributeMaxDynamicSharedMemorySize, ATT_SMEM);
        attr_set = true;
    }

    // 0) split fp32 operands to bf16 hi/lo
    conv_split<<<(M_TOT*D_MODEL/4 + 255)/256, 256>>>(x, xh, xl, M_TOT*D_MODEL/4);
    conv_split<<<(NQKV*D_MODEL/4 + 255)/256, 256>>>(W_qkv, wqh, wql, NQKV*D_MODEL/4);
    conv_split<<<(D_MODEL*D_MODEL/4 + 255)/256, 256>>>(W_o, woh, wol, D_MODEL*D_MODEL/4);

    // 1) qkv = x @ W_qkv^T + b_qkv   (HMMA, split-bf16 x3)
    gemm_tc<<<dim3(NQKV/128, M_TOT/128), 256, GEMM_SMEM>>>(xh, xl, wqh, wql, b_qkv, qkv, NQKV, D_MODEL);

    // 2) split + rms-norm
    norm_split<<<dim3(M_TOT, N_HEADS), 128>>>(wq, wk, k_out, v_out);

    // 3) attention -> g_z
    attn_kernel<<<dim3(SEQ/64, BATCH*N_HEADS), 256, ATT_SMEM>>>(v_out);

    // 4) out = z @ W_o^T + b_o
    conv_split<<<(M_TOT*D_MODEL/4 + 255)/256, 256>>>(z, zh, zl, M_TOT*D_MODEL/4);
    gemm_tc<<<dim3(D_MODEL/128, M_TOT/128), 256, GEMM_SMEM>>>(zh, zl, woh, wol, b_o, out, D_MODEL, D_MODEL);
}

// round 7
// speedup vs baseline: 1.9046x; 1.3444x over previous
#include <cuda_runtime.h>
#include <cuda_bf16.h>
#include <math.h>
#include <stdint.h>

#define D_MODEL 2048
#define N_HEADS 16
#define D_HEAD  128
#define BATCH   2
#define SEQ     2048
#define M_TOT   (BATCH*SEQ)      /* 4096 */
#define NQKV    (3*D_MODEL)      /* 6144 */
#define EPSF    1e-6f

// ---------------- scratch (device globals; no allocs allowed) ----------------
__device__ float g_qkv[(size_t)M_TOT * NQKV];     // 100 MB

__device__ __nv_bfloat16 g_xh[(size_t)M_TOT * D_MODEL];
__device__ __nv_bfloat16 g_xl[(size_t)M_TOT * D_MODEL];
__device__ __nv_bfloat16 g_wqkvh[(size_t)NQKV * D_MODEL];
__device__ __nv_bfloat16 g_wqkvl[(size_t)NQKV * D_MODEL];
__device__ __nv_bfloat16 g_woh[(size_t)D_MODEL * D_MODEL];
__device__ __nv_bfloat16 g_wol[(size_t)D_MODEL * D_MODEL];
__device__ __nv_bfloat16 g_zh[(size_t)M_TOT * D_MODEL];
__device__ __nv_bfloat16 g_zl[(size_t)M_TOT * D_MODEL];

// attention operands, bf16 hi/lo, [m][2048] layout
__device__ __nv_bfloat16 g_qh[(size_t)M_TOT * D_MODEL];
__device__ __nv_bfloat16 g_ql[(size_t)M_TOT * D_MODEL];
__device__ __nv_bfloat16 g_kh[(size_t)M_TOT * D_MODEL];
__device__ __nv_bfloat16 g_kl[(size_t)M_TOT * D_MODEL];
__device__ __nv_bfloat16 g_vh[(size_t)M_TOT * D_MODEL];
__device__ __nv_bfloat16 g_vl[(size_t)M_TOT * D_MODEL];

// ---------------- helpers ----------------------------------------------------
__device__ __forceinline__ uint32_t smem_u32(const void* p) {
    uint32_t a;
    asm("{ .reg .u64 t; cvta.to.shared.u64 t, %1; cvt.u32.u64 %0, t; }"
        : "=r"(a) : "l"(p));
    return a;
}

#define MMA(c, a, b) \
    asm volatile("mma.sync.aligned.m16n8k16.row.col.f32.bf16.bf16.f32 " \
                 "{%0,%1,%2,%3},{%4,%5,%6,%7},{%8,%9},{%0,%1,%2,%3};" \
                 : "+f"((c)[0]), "+f"((c)[1]), "+f"((c)[2]), "+f"((c)[3]) \
                 : "r"((a)[0]), "r"((a)[1]), "r"((a)[2]), "r"((a)[3]), \
                   "r"((b)[0]), "r"((b)[1]))

#define CPA16(dst, src) \
    asm volatile("cp.async.cg.shared.global [%0], [%1], 16;" :: "r"(dst), "l"(src))

// ---------------- fp32 -> bf16 hi/lo split ----------------------------------
__global__ __launch_bounds__(256) void conv_split(
    const float* __restrict__ s, __nv_bfloat16* __restrict__ hi,
    __nv_bfloat16* __restrict__ lo, int n4)
{
    int i = blockIdx.x * blockDim.x + threadIdx.x;
    if (i >= n4) return;
    float4 v = ((const float4*)s)[i];
    __nv_bfloat162 h01, h23, l01, l23;
    h01.x = __float2bfloat16(v.x); h01.y = __float2bfloat16(v.y);
    h23.x = __float2bfloat16(v.z); h23.y = __float2bfloat16(v.w);
    l01.x = __float2bfloat16(v.x - __bfloat162float(h01.x));
    l01.y = __float2bfloat16(v.y - __bfloat162float(h01.y));
    l23.x = __float2bfloat16(v.z - __bfloat162float(h23.x));
    l23.y = __float2bfloat16(v.w - __bfloat162float(h23.y));
    ((__nv_bfloat162*)hi)[i*2]   = h01;
    ((__nv_bfloat162*)hi)[i*2+1] = h23;
    ((__nv_bfloat162*)lo)[i*2]   = l01;
    ((__nv_bfloat162*)lo)[i*2+1] = l23;
}

// ---------------- HMMA split-bf16 GEMM (unchanged, validated) ----------------
#define TILE_E 5120
#define STG_E  (4*TILE_E)
#define GEMM_SMEM (2*STG_E*2)

__global__ __launch_bounds__(256) void gemm_tc(
    const __nv_bfloat16* __restrict__ pAh, const __nv_bfloat16* __restrict__ pAl,
    const __nv_bfloat16* __restrict__ pBh, const __nv_bfloat16* __restrict__ pBl,
    const float* __restrict__ bias, float* __restrict__ C, int N, int K)
{
    extern __shared__ __nv_bfloat16 sm[];
    const int tid = threadIdx.x, lane = tid & 31, wid = tid >> 5;
    const int wm = wid >> 1, wn = wid & 1;
    const int bm = blockIdx.y * 128, bn = blockIdx.x * 128;
    const uint32_t smb = smem_u32(sm);

    float acc[2][8][4];
    #pragma unroll
    for (int mt = 0; mt < 2; ++mt)
        #pragma unroll
        for (int nt = 0; nt < 8; ++nt)
            #pragma unroll
            for (int j = 0; j < 4; ++j) acc[mt][nt][j] = 0.f;

    const int nch = K / 32;
    const __nv_bfloat16* srcs[4] = {
        pAh + (size_t)bm * K, pAl + (size_t)bm * K,
        pBh + (size_t)bn * K, pBl + (size_t)bn * K };

    const int lrow = tid >> 2, lcc = tid & 3;
    const int lrow2 = (tid + 256) >> 2;

    #define ISSUE(st, ch) do {                                             \
        const int _k0 = (ch) * 32;                                         \
        _Pragma("unroll")                                                  \
        for (int _t = 0; _t < 4; ++_t) {                                   \
            const __nv_bfloat16* _s0 = srcs[_t] + _k0 + lcc * 8;           \
            uint32_t _d0 = smb + (uint32_t)(((st)*4 + _t) * (TILE_E*2));   \
            const void* _sp1 = _s0 + (size_t)lrow * K;                     \
            uint32_t _dp1 = _d0 + (uint32_t)(lrow * 80 + lcc * 16);        \
            CPA16(_dp1, _sp1);                                             \
            const void* _sp2 = _s0 + (size_t)lrow2 * K;                    \
            uint32_t _dp2 = _d0 + (uint32_t)(lrow2 * 80 + lcc * 16);       \
            CPA16(_dp2, _sp2);                                             \
        }                                                                  \
        asm volatile("cp.async.commit_group;" ::: "memory");               \
    } while (0)

    ISSUE(0, 0);

    for (int ch = 0; ch < nch; ++ch) {
        const int st = ch & 1;
        if (ch + 1 < nch) {
            ISSUE(st ^ 1, ch + 1);
            asm volatile("cp.async.wait_group 1;" ::: "memory");
        } else {
            asm volatile("cp.async.wait_group 0;" ::: "memory");
        }
        __syncthreads();

        const __nv_bfloat16* sAh = sm + st * STG_E;
        const __nv_bfloat16* sAl = sAh + TILE_E;
        const __nv_bfloat16* sBh = sAh + 2 * TILE_E;
        const __nv_bfloat16* sBl = sAh + 3 * TILE_E;

        #pragma unroll
        for (int k16 = 0; k16 < 2; ++k16) {
            const int c = (lane & 3) * 2 + k16 * 16;
            uint32_t ah[2][4], al[2][4], bh[8][2], bl[8][2];
            #pragma unroll
            for (int mt = 0; mt < 2; ++mt) {
                const int r1 = wm * 32 + mt * 16 + (lane >> 2);
                ah[mt][0] = *(const uint32_t*)&sAh[r1 * 40 + c];
                ah[mt][1] = *(const uint32_t*)&sAh[(r1 + 8) * 40 + c];
                ah[mt][2] = *(const uint32_t*)&sAh[r1 * 40 + c + 8];
                ah[mt][3] = *(const uint32_t*)&sAh[(r1 + 8) * 40 + c + 8];
                al[mt][0] = *(const uint32_t*)&sAl[r1 * 40 + c];
                al[mt][1] = *(const uint32_t*)&sAl[(r1 + 8) * 40 + c];
                al[mt][2] = *(const uint32_t*)&sAl[r1 * 40 + c + 8];
                al[mt][3] = *(const uint32_t*)&sAl[(r1 + 8) * 40 + c + 8];
            }
            #pragma unroll
            for (int nt = 0; nt < 8; ++nt) {
                const int n = wn * 64 + nt * 8 + (lane >> 2);
                bh[nt][0] = *(const uint32_t*)&sBh[n * 40 + c];
                bh[nt][1] = *(const uint32_t*)&sBh[n * 40 + c + 8];
                bl[nt][0] = *(const uint32_t*)&sBl[n * 40 + c];
                bl[nt][1] = *(const uint32_t*)&sBl[n * 40 + c + 8];
            }
            #pragma unroll
            for (int mt = 0; mt < 2; ++mt)
                #pragma unroll
                for (int nt = 0; nt < 8; ++nt) {
                    MMA(acc[mt][nt], ah[mt], bh[nt]);
                    MMA(acc[mt][nt], ah[mt], bl[nt]);
                    MMA(acc[mt][nt], al[mt], bh[nt]);
                }
        }
        __syncthreads();
    }

    #pragma unroll
    for (int mt = 0; mt < 2; ++mt) {
        const int r1 = bm + wm * 32 + mt * 16 + (lane >> 2);
        const int r2 = r1 + 8;
        #pragma unroll
        for (int nt = 0; nt < 8; ++nt) {
            const int cb = bn + wn * 64 + nt * 8 + (lane & 3) * 2;
            const float b0 = bias[cb], b1 = bias[cb + 1];
            float2 o1, o2;
            o1.x = acc[mt][nt][0] + b0; o1.y = acc[mt][nt][1] + b1;
            o2.x = acc[mt][nt][2] + b0; o2.y = acc[mt][nt][3] + b1;
            *(float2*)&C[(size_t)r1 * N + cb] = o1;
            *(float2*)&C[(size_t)r2 * N + cb] = o2;
        }
    }
}

// --------------- norm/split -> bf16 hi/lo operands + fp32 k/v outputs --------
__global__ __launch_bounds__(128) void norm_split(
    const float* __restrict__ wq, const float* __restrict__ wk,
    float* __restrict__ k_out, float* __restrict__ v_out)
{
    const int m = blockIdx.x;
    const int h = blockIdx.y;
    const int t = threadIdx.x;
    const float* row = g_qkv + (size_t)m * NQKV;
    const float q = row[h*D_HEAD + t];
    const float k = row[D_MODEL   + h*D_HEAD + t];
    const float v = row[2*D_MODEL + h*D_HEAD + t];

    const size_t oidx = (size_t)m * D_MODEL + h*D_HEAD + t;
    k_out[oidx] = k;
    v_out[oidx] = v;

    float sq = q*q, sk = k*k;
    #pragma unroll
    for (int off = 16; off > 0; off >>= 1) {
        sq += __shfl_xor_sync(0xffffffffu, sq, off);
        sk += __shfl_xor_sync(0xffffffffu, sk, off);
    }
    __shared__ float bufq[4], bufk[4];
    if ((t & 31) == 0) { bufq[t>>5] = sq; bufk[t>>5] = sk; }
    __syncthreads();
    sq = bufq[0] + bufq[1] + bufq[2] + bufq[3];
    sk = bufk[0] + bufk[1] + bufk[2] + bufk[3];
    const float rq = rsqrtf(sq * (1.f/128.f) + EPSF);
    const float rk = rsqrtf(sk * (1.f/128.f) + EPSF);
    const float qn = q * rq * wq[t];
    const float kn = k * rk * wk[t];

    __nv_bfloat16 qh = __float2bfloat16(qn);
    __nv_bfloat16 kh = __float2bfloat16(kn);
    __nv_bfloat16 vh = __float2bfloat16(v);
    g_qh[oidx] = qh; g_ql[oidx] = __float2bfloat16(qn - __bfloat162float(qh));
    g_kh[oidx] = kh; g_kl[oidx] = __float2bfloat16(kn - __bfloat162float(kh));
    g_vh[oidx] = vh; g_vl[oidx] = __float2bfloat16(v  - __bfloat162float(vh));
}

// --------------- flash attention with HMMA (split-bf16, 3 passes) ------------
// BQ=64, BK=64, 4 warps (warp owns 16 q-rows). smem: 6 tiles of 64x136 bf16.
#define AT_STRIDE 136
#define AT_TILE_E (64*AT_STRIDE)     /* 8704 elems = 17408 B */
#define ATT_SMEM  (6*AT_TILE_E*2)    /* 104448 B */

__global__ __launch_bounds__(128) void attn_tc()
{
    extern __shared__ __nv_bfloat16 smb[];
    __nv_bfloat16* Qh = smb;
    __nv_bfloat16* Ql = smb + AT_TILE_E;
    __nv_bfloat16* Kh = smb + 2*AT_TILE_E;
    __nv_bfloat16* Kl = smb + 3*AT_TILE_E;
    __nv_bfloat16* Vh = smb + 4*AT_TILE_E;
    __nv_bfloat16* Vl = smb + 5*AT_TILE_E;

    const int tid = threadIdx.x, lane = tid & 31, wid = tid >> 5;
    const int l3 = lane & 3, l4 = lane >> 2;
    const int qt = blockIdx.x;          // 0..31
    const int bh = blockIdx.y;          // 0..31
    const int b = bh >> 4, h = bh & 15;
    const size_t qmbase = (size_t)b * SEQ + qt * 64;
    const size_t kmbase = (size_t)b * SEQ;
    const int colbase = h * D_HEAD;

    const uint32_t smbase = smem_u32(smb);

    // ---- load Q tile (hi+lo) ----
    {
        const __nv_bfloat16* gq = g_qh + qmbase * D_MODEL + colbase;
        const __nv_bfloat16* gl = g_ql + qmbase * D_MODEL + colbase;
        #pragma unroll
        for (int it = 0; it < 8; ++it) {
            const int c = it * 128 + tid;
            const int row = c >> 4, c16 = c & 15;
            const uint32_t dst = smbase + (uint32_t)(row * 272 + c16 * 16);
            CPA16(dst,                    gq + (size_t)row * D_MODEL + c16 * 8);
            CPA16(dst + AT_TILE_E * 2,    gl + (size_t)row * D_MODEL + c16 * 8);
        }
        asm volatile("cp.async.commit_group;" ::: "memory");
    }

    float O[16][4];
    #pragma unroll
    for (int nt = 0; nt < 16; ++nt)
        #pragma unroll
        for (int j = 0; j < 4; ++j) O[nt][j] = 0.f;
    float m0 = -1e30f, m1 = -1e30f, l0 = 0.f, l1 = 0.f;

    const int ra = wid * 16 + l4;       // q row within tile (for A frags)

    for (int kt = 0; kt < SEQ/64; ++kt) {
        // ---- load K,V (hi+lo) ----
        {
            const size_t mrow = (kmbase + kt * 64) * D_MODEL + colbase;
            const __nv_bfloat16* s0 = g_kh + mrow;
            const __nv_bfloat16* s1 = g_kl + mrow;
            const __nv_bfloat16* s2 = g_vh + mrow;
            const __nv_bfloat16* s3 = g_vl + mrow;
            #pragma unroll
            for (int it = 0; it < 8; ++it) {
                const int c = it * 128 + tid;
                const int row = c >> 4, c16 = c & 15;
                const size_t so = (size_t)row * D_MODEL + c16 * 8;
                const uint32_t dst = smbase + (uint32_t)(row * 272 + c16 * 16);
                CPA16(dst + 2*AT_TILE_E*2, s0 + so);
                CPA16(dst + 3*AT_TILE_E*2, s1 + so);
                CPA16(dst + 4*AT_TILE_E*2, s2 + so);
                CPA16(dst + 5*AT_TILE_E*2, s3 + so);
            }
            asm volatile("cp.async.commit_group;" ::: "memory");
        }
        asm volatile("cp.async.wait_group 0;" ::: "memory");
        __syncthreads();

        // ---- S = Qn Kn^T  (64x64 per CTA; warp strip 16x64) ----
        float s[8][4];
        #pragma unroll
        for (int nt = 0; nt < 8; ++nt)
            #pragma unroll
            for (int j = 0; j < 4; ++j) s[nt][j] = 0.f;

        #pragma unroll
        for (int ks = 0; ks < 8; ++ks) {
            const int dc = ks * 16 + 2 * l3;
            uint32_t ah[4], al[4];
            ah[0] = *(const uint32_t*)&Qh[ra * AT_STRIDE + dc];
            ah[1] = *(const uint32_t*)&Qh[(ra + 8) * AT_STRIDE + dc];
            ah[2] = *(const uint32_t*)&Qh[ra * AT_STRIDE + dc + 8];
            ah[3] = *(const uint32_t*)&Qh[(ra + 8) * AT_STRIDE + dc + 8];
            al[0] = *(const uint32_t*)&Ql[ra * AT_STRIDE + dc];
            al[1] = *(const uint32_t*)&Ql[(ra + 8) * AT_STRIDE + dc];
            al[2] = *(const uint32_t*)&Ql[ra * AT_STRIDE + dc + 8];
            al[3] = *(const uint32_t*)&Ql[(ra + 8) * AT_STRIDE + dc + 8];
            #pragma unroll
            for (int nt = 0; nt < 8; ++nt) {
                const int kr = nt * 8 + l4;
                uint32_t bh2[2], bl2[2];
                bh2[0] = *(const uint32_t*)&Kh[kr * AT_STRIDE + dc];
                bh2[1] = *(const uint32_t*)&Kh[kr * AT_STRIDE + dc + 8];
                bl2[0] = *(const uint32_t*)&Kl[kr * AT_STRIDE + dc];
                bl2[1] = *(const uint32_t*)&Kl[kr * AT_STRIDE + dc + 8];
                MMA(s[nt], ah, bh2);
                MMA(s[nt], ah, bl2);
                MMA(s[nt], al, bh2);
            }
        }

        // ---- online softmax on fragments ----
        float mx0 = -1e30f, mx1 = -1e30f;
        #pragma unroll
        for (int nt = 0; nt < 8; ++nt) {
            mx0 = fmaxf(mx0, fmaxf(s[nt][0], s[nt][1]));
            mx1 = fmaxf(mx1, fmaxf(s[nt][2], s[nt][3]));
        }
        mx0 = fmaxf(mx0, __shfl_xor_sync(0xffffffffu, mx0, 1));
        mx0 = fmaxf(mx0, __shfl_xor_sync(0xffffffffu, mx0, 2));
        mx1 = fmaxf(mx1, __shfl_xor_sync(0xffffffffu, mx1, 1));
        mx1 = fmaxf(mx1, __shfl_xor_sync(0xffffffffu, mx1, 2));
        const float mn0 = fmaxf(m0, mx0), mn1 = fmaxf(m1, mx1);
        const float corr0 = __expf(m0 - mn0), corr1 = __expf(m1 - mn1);
        m0 = mn0; m1 = mn1;

        uint32_t ph[8][2], pl[8][2];
        float rs0 = 0.f, rs1 = 0.f;
        #pragma unroll
        for (int nt = 0; nt < 8; ++nt) {
            float p0 = __expf(s[nt][0] - mn0);
            float p1 = __expf(s[nt][1] - mn0);
            float p2 = __expf(s[nt][2] - mn1);
            float p3 = __expf(s[nt][3] - mn1);
            rs0 += p0 + p1; rs1 += p2 + p3;
            __nv_bfloat162 h01, h23, lo01, lo23;
            h01.x = __float2bfloat16(p0); h01.y = __float2bfloat16(p1);
            h23.x = __float2bfloat16(p2); h23.y = __float2bfloat16(p3);
            lo01.x = __float2bfloat16(p0 - __bfloat162float(h01.x));
            lo01.y = __float2bfloat16(p1 - __bfloat162float(h01.y));
            lo23.x = __float2bfloat16(p2 - __bfloat162float(h23.x));
            lo23.y = __float2bfloat16(p3 - __bfloat162float(h23.y));
            ph[nt][0] = *(uint32_t*)&h01;  ph[nt][1] = *(uint32_t*)&h23;
            pl[nt][0] = *(uint32_t*)&lo01; pl[nt][1] = *(uint32_t*)&lo23;
        }
        rs0 += __shfl_xor_sync(0xffffffffu, rs0, 1);
        rs0 += __shfl_xor_sync(0xffffffffu, rs0, 2);
        rs1 += __shfl_xor_sync(0xffffffffu, rs1, 1);
        rs1 += __shfl_xor_sync(0xffffffffu, rs1, 2);
        l0 = l0 * corr0 + rs0;
        l1 = l1 * corr1 + rs1;
        #pragma unroll
        for (int nt = 0; nt < 16; ++nt) {
            O[nt][0] *= corr0; O[nt][1] *= corr0;
            O[nt][2] *= corr1; O[nt][3] *= corr1;
        }

        // ---- O += P V  (k-dim = 64 keys, n-dim = 128 d) ----
        #pragma unroll
        for (int ks = 0; ks < 4; ++ks) {
            uint32_t a_h[4] = { ph[2*ks][0], ph[2*ks][1], ph[2*ks+1][0], ph[2*ks+1][1] };
            uint32_t a_l[4] = { pl[2*ks][0], pl[2*ks][1], pl[2*ks+1][0], pl[2*ks+1][1] };
            const int kb = ks * 16 + 2 * l3;
            #pragma unroll
            for (int nt = 0; nt < 16; ++nt) {
                const int dcol = nt * 8 + l4;
                const __nv_bfloat16* v0 = Vh + kb * AT_STRIDE + dcol;
                uint32_t bbh[2], bbl[2];
                {
                    uint32_t x0 = *(const uint16_t*)(v0);
                    uint32_t x1 = *(const uint16_t*)(v0 + AT_STRIDE);
                    bbh[0] = x0 | (x1 << 16);
                    uint32_t y0 = *(const uint16_t*)(v0 + 8*AT_STRIDE);
                    uint32_t y1 = *(const uint16_t*)(v0 + 9*AT_STRIDE);
                    bbh[1] = y0 | (y1 << 16);
                }
                const __nv_bfloat16* w0 = Vl + kb * AT_STRIDE + dcol;
                {
                    uint32_t x0 = *(const uint16_t*)(w0);
                    uint32_t x1 = *(const uint16_t*)(w0 + AT_STRIDE);
                    bbl[0] = x0 | (x1 << 16);
                    uint32_t y0 = *(const uint16_t*)(w0 + 8*AT_STRIDE);
                    uint32_t y1 = *(const uint16_t*)(w0 + 9*AT_STRIDE);
                    bbl[1] = y0 | (y1 << 16);
                }
                MMA(O[nt], a_h, bbh);
                MMA(O[nt], a_l, bbh);
                MMA(O[nt], a_h, bbl);
            }
        }
        __syncthreads();   // all warps done with K/V before next tile load
    }

    // ---- epilogue: O/l -> z bf16 hi/lo ----
    const float inv0 = 1.f / l0, inv1 = 1.f / l1;
    const size_t r0g = qmbase + wid * 16 + l4;
    const size_t r1g = r0g + 8;
    #pragma unroll
    for (int nt = 0; nt < 16; ++nt) {
        const int col = colbase + nt * 8 + 2 * l3;
        const float o0 = O[nt][0] * inv0, o1 = O[nt][1] * inv0;
        const float o2 = O[nt][2] * inv1, o3 = O[nt][3] * inv1;
        __nv_bfloat162 h01, h23, lo01, lo23;
        h01.x = __float2bfloat16(o0); h01.y = __float2bfloat16(o1);
        h23.x = __float2bfloat16(o2); h23.y = __float2bfloat16(o3);
        lo01.x = __float2bfloat16(o0 - __bfloat162float(h01.x));
        lo01.y = __float2bfloat16(o1 - __bfloat162float(h01.y));
        lo23.x = __float2bfloat16(o2 - __bfloat162float(h23.x));
        lo23.y = __float2bfloat16(o3 - __bfloat162float(h23.y));
        *(uint32_t*)&g_zh[r0g * D_MODEL + col] = *(uint32_t*)&h01;
        *(uint32_t*)&g_zl[r0g * D_MODEL + col] = *(uint32_t*)&lo01;
        *(uint32_t*)&g_zh[r1g * D_MODEL + col] = *(uint32_t*)&h23;
        *(uint32_t*)&g_zl[r1g * D_MODEL + col] = *(uint32_t*)&lo23;
    }
}

// -----------------------------------------------------------------------------
extern "C" void kernel_launch(void* const* d_in, const int* in_sizes, int n_in,
                              void* d_out, int out_size)
{
    const float* x     = (const float*)d_in[0];
    const float* W_qkv = (const float*)d_in[1];
    const float* b_qkv = (const float*)d_in[2];
    const float* W_o   = (const float*)d_in[3];
    const float* b_o   = (const float*)d_in[4];
    const float* wq    = (const float*)d_in[5];
    const float* wk    = (const float*)d_in[6];

    float* out   = (float*)d_out;
    float* k_out = out   + (size_t)M_TOT * D_MODEL;
    float* v_out = k_out + (size_t)M_TOT * D_MODEL;

    float* qkv;
    cudaGetSymbolAddress((void**)&qkv, g_qkv);
    __nv_bfloat16 *xh, *xl, *wqh, *wql, *woh, *wol, *zh, *zl;
    cudaGetSymbolAddress((void**)&xh,  g_xh);
    cudaGetSymbolAddress((void**)&xl,  g_xl);
    cudaGetSymbolAddress((void**)&wqh, g_wqkvh);
    cudaGetSymbolAddress((void**)&wql, g_wqkvl);
    cudaGetSymbolAddress((void**)&woh, g_woh);
    cudaGetSymbolAddress((void**)&wol, g_wol);
    cudaGetSymbolAddress((void**)&zh,  g_zh);
    cudaGetSymbolAddress((void**)&zl,  g_zl);

    static bool attr_set = false;
    if (!attr_set) {
        cudaFuncSetAttribute(gemm_tc, cudaFuncAttributeMaxDynamicSharedMemorySize, GEMM_SMEM);
        cudaFuncSetAttribute(attn_tc, cudaFuncAttributeMaxDynamicSharedMemorySize, ATT_SMEM);
        attr_set = true;
    }

    // 0) split fp32 operands to bf16 hi/lo
    conv_split<<<(M_TOT*D_MODEL/4 + 255)/256, 256>>>(x, xh, xl, M_TOT*D_MODEL/4);
    conv_split<<<(NQKV*D_MODEL/4 + 255)/256, 256>>>(W_qkv, wqh, wql, NQKV*D_MODEL/4);
    conv_split<<<(D_MODEL*D_MODEL/4 + 255)/256, 256>>>(W_o, woh, wol, D_MODEL*D_MODEL/4);

    // 1) qkv = x @ W_qkv^T + b_qkv
    gemm_tc<<<dim3(NQKV/128, M_TOT/128), 256, GEMM_SMEM>>>(xh, xl, wqh, wql, b_qkv, qkv, NQKV, D_MODEL);

    // 2) split + rms-norm -> bf16 hi/lo q/k/v (+ fp32 k_out, v_out)
    norm_split<<<dim3(M_TOT, N_HEADS), 128>>>(wq, wk, k_out, v_out);

    // 3) attention (HMMA) -> g_zh/g_zl
    attn_tc<<<dim3(SEQ/64, BATCH*N_HEADS), 128, ATT_SMEM>>>();

    // 4) out = z @ W_o^T + b_o
    gemm_tc<<<dim3(D_MODEL/128, M_TOT/128), 256, GEMM_SMEM>>>(zh, zl, woh, wol, b_o, out, D_MODEL, D_MODEL);
}

// round 8
// speedup vs baseline: 3.6556x; 1.9193x over previous
#include <cuda_runtime.h>
#include <cuda_bf16.h>
#include <math.h>
#include <stdint.h>

#define D_MODEL 2048
#define N_HEADS 16
#define D_HEAD  128
#define BATCH   2
#define SEQ     2048
#define M_TOT   (BATCH*SEQ)      /* 4096 */
#define NQKV    (3*D_MODEL)      /* 6144 */
#define EPSF    1e-6f

// ---------------- scratch (device globals; no allocs allowed) ----------------
__device__ float g_qkv[(size_t)M_TOT * NQKV];     // 100 MB

__device__ __nv_bfloat16 g_xh[(size_t)M_TOT * D_MODEL];
__device__ __nv_bfloat16 g_xl[(size_t)M_TOT * D_MODEL];
__device__ __nv_bfloat16 g_wqkvh[(size_t)NQKV * D_MODEL];
__device__ __nv_bfloat16 g_wqkvl[(size_t)NQKV * D_MODEL];
__device__ __nv_bfloat16 g_woh[(size_t)D_MODEL * D_MODEL];
__device__ __nv_bfloat16 g_wol[(size_t)D_MODEL * D_MODEL];
__device__ __nv_bfloat16 g_zh[(size_t)M_TOT * D_MODEL];
__device__ __nv_bfloat16 g_zl[(size_t)M_TOT * D_MODEL];

__device__ __nv_bfloat16 g_qh[(size_t)M_TOT * D_MODEL];
__device__ __nv_bfloat16 g_ql[(size_t)M_TOT * D_MODEL];
__device__ __nv_bfloat16 g_kh[(size_t)M_TOT * D_MODEL];
__device__ __nv_bfloat16 g_kl[(size_t)M_TOT * D_MODEL];
__device__ __nv_bfloat16 g_vh[(size_t)M_TOT * D_MODEL];
__device__ __nv_bfloat16 g_vl[(size_t)M_TOT * D_MODEL];

// ---------------- helpers ----------------------------------------------------
__device__ __forceinline__ uint32_t smem_u32(const void* p) {
    uint32_t a;
    asm("{ .reg .u64 t; cvta.to.shared.u64 t, %1; cvt.u32.u64 %0, t; }"
        : "=r"(a) : "l"(p));
    return a;
}

#define MMA(c, a, b) \
    asm volatile("mma.sync.aligned.m16n8k16.row.col.f32.bf16.bf16.f32 " \
                 "{%0,%1,%2,%3},{%4,%5,%6,%7},{%8,%9},{%0,%1,%2,%3};" \
                 : "+f"((c)[0]), "+f"((c)[1]), "+f"((c)[2]), "+f"((c)[3]) \
                 : "r"((a)[0]), "r"((a)[1]), "r"((a)[2]), "r"((a)[3]), \
                   "r"((b)[0]), "r"((b)[1]))

#define CPA16(dst, src) \
    asm volatile("cp.async.cg.shared.global [%0], [%1], 16;" :: "r"(dst), "l"(src))

#define LDSM4(r0_, r1_, r2_, r3_, a_) \
    asm volatile("ldmatrix.sync.aligned.m8n8.x4.shared.b16 {%0,%1,%2,%3},[%4];" \
                 : "=r"(r0_), "=r"(r1_), "=r"(r2_), "=r"(r3_) : "r"(a_))

#define LDSM4T(r0_, r1_, r2_, r3_, a_) \
    asm volatile("ldmatrix.sync.aligned.m8n8.x4.trans.shared.b16 {%0,%1,%2,%3},[%4];" \
                 : "=r"(r0_), "=r"(r1_), "=r"(r2_), "=r"(r3_) : "r"(a_))

// ---------------- fp32 -> bf16 hi/lo split ----------------------------------
__global__ __launch_bounds__(256) void conv_split(
    const float* __restrict__ s, __nv_bfloat16* __restrict__ hi,
    __nv_bfloat16* __restrict__ lo, int n4)
{
    int i = blockIdx.x * blockDim.x + threadIdx.x;
    if (i >= n4) return;
    float4 v = ((const float4*)s)[i];
    __nv_bfloat162 h01, h23, l01, l23;
    h01.x = __float2bfloat16(v.x); h01.y = __float2bfloat16(v.y);
    h23.x = __float2bfloat16(v.z); h23.y = __float2bfloat16(v.w);
    l01.x = __float2bfloat16(v.x - __bfloat162float(h01.x));
    l01.y = __float2bfloat16(v.y - __bfloat162float(h01.y));
    l23.x = __float2bfloat16(v.z - __bfloat162float(h23.x));
    l23.y = __float2bfloat16(v.w - __bfloat162float(h23.y));
    ((__nv_bfloat162*)hi)[i*2]   = h01;
    ((__nv_bfloat162*)hi)[i*2+1] = h23;
    ((__nv_bfloat162*)lo)[i*2]   = l01;
    ((__nv_bfloat162*)lo)[i*2+1] = l23;
}

// ---------------- HMMA split-bf16 GEMM (ldmatrix + 2 CTAs/SM) ----------------
#define TILE_E 5120
#define STG_E  (4*TILE_E)
#define GEMM_SMEM (2*STG_E*2)

__global__ __launch_bounds__(256, 2) void gemm_tc(
    const __nv_bfloat16* __restrict__ pAh, const __nv_bfloat16* __restrict__ pAl,
    const __nv_bfloat16* __restrict__ pBh, const __nv_bfloat16* __restrict__ pBl,
    const float* __restrict__ bias, float* __restrict__ C, int N, int K)
{
    extern __shared__ __nv_bfloat16 sm[];
    const int tid = threadIdx.x, lane = tid & 31, wid = tid >> 5;
    const int wm = wid >> 1, wn = wid & 1;
    const int bm = blockIdx.y * 128, bn = blockIdx.x * 128;
    const uint32_t smb = smem_u32(sm);

    const int rr = lane & 7, sub = lane >> 3;
    const uint32_t offA = (uint32_t)((rr + (sub & 1) * 8) * 80 + (sub >> 1) * 16);
    const uint32_t offB = (uint32_t)((rr + (sub >> 1) * 8) * 80 + (sub & 1) * 16);

    float acc[2][8][4];
    #pragma unroll
    for (int mt = 0; mt < 2; ++mt)
        #pragma unroll
        for (int nt = 0; nt < 8; ++nt)
            #pragma unroll
            for (int j = 0; j < 4; ++j) acc[mt][nt][j] = 0.f;

    const int nch = K / 32;
    const __nv_bfloat16* srcs[4] = {
        pAh + (size_t)bm * K, pAl + (size_t)bm * K,
        pBh + (size_t)bn * K, pBl + (size_t)bn * K };

    const int lrow = tid >> 2, lcc = tid & 3;
    const int lrow2 = (tid + 256) >> 2;

    #define ISSUE(st, ch) do {                                             \
        const int _k0 = (ch) * 32;                                         \
        _Pragma("unroll")                                                  \
        for (int _t = 0; _t < 4; ++_t) {                                   \
            const __nv_bfloat16* _s0 = srcs[_t] + _k0 + lcc * 8;           \
            uint32_t _d0 = smb + (uint32_t)(((st)*4 + _t) * (TILE_E*2));   \
            const void* _sp1 = _s0 + (size_t)lrow * K;                     \
            uint32_t _dp1 = _d0 + (uint32_t)(lrow * 80 + lcc * 16);        \
            CPA16(_dp1, _sp1);                                             \
            const void* _sp2 = _s0 + (size_t)lrow2 * K;                    \
            uint32_t _dp2 = _d0 + (uint32_t)(lrow2 * 80 + lcc * 16);       \
            CPA16(_dp2, _sp2);                                             \
        }                                                                  \
        asm volatile("cp.async.commit_group;" ::: "memory");               \
    } while (0)

    ISSUE(0, 0);

    for (int ch = 0; ch < nch; ++ch) {
        const int st = ch & 1;
        if (ch + 1 < nch) {
            ISSUE(st ^ 1, ch + 1);
            asm volatile("cp.async.wait_group 1;" ::: "memory");
        } else {
            asm volatile("cp.async.wait_group 0;" ::: "memory");
        }
        __syncthreads();

        const uint32_t stbase = smb + (uint32_t)(st * (STG_E * 2));
        const uint32_t aBase = stbase + (uint32_t)(wm * 32 * 80) + offA;
        const uint32_t bBase = stbase + (uint32_t)(2 * TILE_E * 2) +
                               (uint32_t)(wn * 64 * 80) + offB;

        #pragma unroll
        for (int k16 = 0; k16 < 2; ++k16) {
            const uint32_t cb = (uint32_t)(k16 * 32);
            uint32_t ah[2][4], al[2][4], bh[8][2], bl[8][2];
            #pragma unroll
            for (int mt = 0; mt < 2; ++mt) {
                LDSM4(ah[mt][0], ah[mt][1], ah[mt][2], ah[mt][3],
                      aBase + (uint32_t)(mt * 1280) + cb);
                LDSM4(al[mt][0], al[mt][1], al[mt][2], al[mt][3],
                      aBase + (uint32_t)(TILE_E * 2 + mt * 1280) + cb);
            }
            #pragma unroll
            for (int p = 0; p < 4; ++p) {
                LDSM4(bh[2*p][0], bh[2*p][1], bh[2*p+1][0], bh[2*p+1][1],
                      bBase + (uint32_t)(p * 1280) + cb);
                LDSM4(bl[2*p][0], bl[2*p][1], bl[2*p+1][0], bl[2*p+1][1],
                      bBase + (uint32_t)(TILE_E * 2 + p * 1280) + cb);
            }
            #pragma unroll
            for (int mt = 0; mt < 2; ++mt)
                #pragma unroll
                for (int nt = 0; nt < 8; ++nt) {
                    MMA(acc[mt][nt], ah[mt], bh[nt]);
                    MMA(acc[mt][nt], ah[mt], bl[nt]);
                    MMA(acc[mt][nt], al[mt], bh[nt]);
                }
        }
        __syncthreads();
    }

    #pragma unroll
    for (int mt = 0; mt < 2; ++mt) {
        const int r1 = bm + wm * 32 + mt * 16 + (lane >> 2);
        const int r2 = r1 + 8;
        #pragma unroll
        for (int nt = 0; nt < 8; ++nt) {
            const int cb = bn + wn * 64 + nt * 8 + (lane & 3) * 2;
            const float b0 = bias[cb], b1 = bias[cb + 1];
            float2 o1, o2;
            o1.x = acc[mt][nt][0] + b0; o1.y = acc[mt][nt][1] + b1;
            o2.x = acc[mt][nt][2] + b0; o2.y = acc[mt][nt][3] + b1;
            *(float2*)&C[(size_t)r1 * N + cb] = o1;
            *(float2*)&C[(size_t)r2 * N + cb] = o2;
        }
    }
}

// --------------- norm/split -> bf16 hi/lo operands + fp32 k/v outputs --------
__global__ __launch_bounds__(128) void norm_split(
    const float* __restrict__ wq, const float* __restrict__ wk,
    float* __restrict__ k_out, float* __restrict__ v_out)
{
    const int m = blockIdx.x;
    const int h = blockIdx.y;
    const int t = threadIdx.x;
    const float* row = g_qkv + (size_t)m * NQKV;
    const float q = row[h*D_HEAD + t];
    const float k = row[D_MODEL   + h*D_HEAD + t];
    const float v = row[2*D_MODEL + h*D_HEAD + t];

    const size_t oidx = (size_t)m * D_MODEL + h*D_HEAD + t;
    k_out[oidx] = k;
    v_out[oidx] = v;

    float sq = q*q, sk = k*k;
    #pragma unroll
    for (int off = 16; off > 0; off >>= 1) {
        sq += __shfl_xor_sync(0xffffffffu, sq, off);
        sk += __shfl_xor_sync(0xffffffffu, sk, off);
    }
    __shared__ float bufq[4], bufk[4];
    if ((t & 31) == 0) { bufq[t>>5] = sq; bufk[t>>5] = sk; }
    __syncthreads();
    sq = bufq[0] + bufq[1] + bufq[2] + bufq[3];
    sk = bufk[0] + bufk[1] + bufk[2] + bufk[3];
    const float rq = rsqrtf(sq * (1.f/128.f) + EPSF);
    const float rk = rsqrtf(sk * (1.f/128.f) + EPSF);
    const float qn = q * rq * wq[t];
    const float kn = k * rk * wk[t];

    __nv_bfloat16 qh = __float2bfloat16(qn);
    __nv_bfloat16 kh = __float2bfloat16(kn);
    __nv_bfloat16 vh = __float2bfloat16(v);
    g_qh[oidx] = qh; g_ql[oidx] = __float2bfloat16(qn - __bfloat162float(qh));
    g_kh[oidx] = kh; g_kl[oidx] = __float2bfloat16(kn - __bfloat162float(kh));
    g_vh[oidx] = vh; g_vl[oidx] = __float2bfloat16(v  - __bfloat162float(vh));
}

// --------------- flash attention with HMMA + ldmatrix ------------------------
#define AT_STRIDE 136
#define AT_TILE_E (64*AT_STRIDE)     /* 8704 elems = 17408 B */
#define ATT_SMEM  (6*AT_TILE_E*2)    /* 104448 B */

__global__ __launch_bounds__(128, 2) void attn_tc()
{
    extern __shared__ __nv_bfloat16 smb[];
    const int tid = threadIdx.x, lane = tid & 31, wid = tid >> 5;
    const int l3 = lane & 3, l4 = lane >> 2;
    const int rr = lane & 7, sub = lane >> 3;
    const int qt = blockIdx.x;
    const int bh = blockIdx.y;
    const int b = bh >> 4, h = bh & 15;
    const size_t qmbase = (size_t)b * SEQ + qt * 64;
    const size_t kmbase = (size_t)b * SEQ;
    const int colbase = h * D_HEAD;

    const uint32_t smbase = smem_u32(smb);

    // per-thread ldmatrix offsets (272-byte row stride)
    const uint32_t offA  = (uint32_t)((rr + (sub & 1) * 8) * 272 + (sub >> 1) * 16);
    const uint32_t offB  = (uint32_t)((rr + (sub >> 1) * 8) * 272 + (sub & 1) * 16);
    const uint32_t offVT = offA;   // same sub-pattern for trans V loads

    // ---- load Q tile (hi+lo) ----
    {
        const __nv_bfloat16* gq = g_qh + qmbase * D_MODEL + colbase;
        const __nv_bfloat16* gl = g_ql + qmbase * D_MODEL + colbase;
        #pragma unroll
        for (int it = 0; it < 8; ++it) {
            const int c = it * 128 + tid;
            const int row = c >> 4, c16 = c & 15;
            const uint32_t dst = smbase + (uint32_t)(row * 272 + c16 * 16);
            CPA16(dst,                    gq + (size_t)row * D_MODEL + c16 * 8);
            CPA16(dst + AT_TILE_E * 2,    gl + (size_t)row * D_MODEL + c16 * 8);
        }
        asm volatile("cp.async.commit_group;" ::: "memory");
    }

    float O[16][4];
    #pragma unroll
    for (int nt = 0; nt < 16; ++nt)
        #pragma unroll
        for (int j = 0; j < 4; ++j) O[nt][j] = 0.f;
    float m0 = -1e30f, m1 = -1e30f, l0 = 0.f, l1 = 0.f;

    const uint32_t qBaseH = smbase + (uint32_t)(wid * 16 * 272) + offA;
    const uint32_t qBaseL = qBaseH + (uint32_t)(AT_TILE_E * 2);
    const uint32_t kBaseH = smbase + (uint32_t)(2 * AT_TILE_E * 2) + offB;
    const uint32_t kBaseL = kBaseH + (uint32_t)(AT_TILE_E * 2);
    const uint32_t vBaseH = smbase + (uint32_t)(4 * AT_TILE_E * 2) + offVT;
    const uint32_t vBaseL = vBaseH + (uint32_t)(AT_TILE_E * 2);

    for (int kt = 0; kt < SEQ/64; ++kt) {
        // ---- load K,V (hi+lo) ----
        {
            const size_t mrow = (kmbase + kt * 64) * D_MODEL + colbase;
            const __nv_bfloat16* s0 = g_kh + mrow;
            const __nv_bfloat16* s1 = g_kl + mrow;
            const __nv_bfloat16* s2 = g_vh + mrow;
            const __nv_bfloat16* s3 = g_vl + mrow;
            #pragma unroll
            for (int it = 0; it < 8; ++it) {
                const int c = it * 128 + tid;
                const int row = c >> 4, c16 = c & 15;
                const size_t so = (size_t)row * D_MODEL + c16 * 8;
                const uint32_t dst = smbase + (uint32_t)(row * 272 + c16 * 16);
                CPA16(dst + 2*AT_TILE_E*2, s0 + so);
                CPA16(dst + 3*AT_TILE_E*2, s1 + so);
                CPA16(dst + 4*AT_TILE_E*2, s2 + so);
                CPA16(dst + 5*AT_TILE_E*2, s3 + so);
            }
            asm volatile("cp.async.commit_group;" ::: "memory");
        }
        asm volatile("cp.async.wait_group 0;" ::: "memory");
        __syncthreads();

        // ---- S = Qn Kn^T (warp strip 16x64) ----
        float s[8][4];
        #pragma unroll
        for (int nt = 0; nt < 8; ++nt)
            #pragma unroll
            for (int j = 0; j < 4; ++j) s[nt][j] = 0.f;

        #pragma unroll
        for (int ks = 0; ks < 8; ++ks) {
            const uint32_t cb = (uint32_t)(ks * 32);
            uint32_t ah[4], al[4], bh2[8][2], bl2[8][2];
            LDSM4(ah[0], ah[1], ah[2], ah[3], qBaseH + cb);
            LDSM4(al[0], al[1], al[2], al[3], qBaseL + cb);
            #pragma unroll
            for (int p = 0; p < 4; ++p) {
                LDSM4(bh2[2*p][0], bh2[2*p][1], bh2[2*p+1][0], bh2[2*p+1][1],
                      kBaseH + (uint32_t)(p * 16 * 272) + cb);
                LDSM4(bl2[2*p][0], bl2[2*p][1], bl2[2*p+1][0], bl2[2*p+1][1],
                      kBaseL + (uint32_t)(p * 16 * 272) + cb);
            }
            #pragma unroll
            for (int nt = 0; nt < 8; ++nt) {
                MMA(s[nt], ah, bh2[nt]);
                MMA(s[nt], ah, bl2[nt]);
                MMA(s[nt], al, bh2[nt]);
            }
        }

        // ---- online softmax on fragments ----
        float mx0 = -1e30f, mx1 = -1e30f;
        #pragma unroll
        for (int nt = 0; nt < 8; ++nt) {
            mx0 = fmaxf(mx0, fmaxf(s[nt][0], s[nt][1]));
            mx1 = fmaxf(mx1, fmaxf(s[nt][2], s[nt][3]));
        }
        mx0 = fmaxf(mx0, __shfl_xor_sync(0xffffffffu, mx0, 1));
        mx0 = fmaxf(mx0, __shfl_xor_sync(0xffffffffu, mx0, 2));
        mx1 = fmaxf(mx1, __shfl_xor_sync(0xffffffffu, mx1, 1));
        mx1 = fmaxf(mx1, __shfl_xor_sync(0xffffffffu, mx1, 2));
        const float mn0 = fmaxf(m0, mx0), mn1 = fmaxf(m1, mx1);
        const float corr0 = __expf(m0 - mn0), corr1 = __expf(m1 - mn1);
        m0 = mn0; m1 = mn1;

        uint32_t ph[8][2], pl[8][2];
        float rs0 = 0.f, rs1 = 0.f;
        #pragma unroll
        for (int nt = 0; nt < 8; ++nt) {
            float p0 = __expf(s[nt][0] - mn0);
            float p1 = __expf(s[nt][1] - mn0);
            float p2 = __expf(s[nt][2] - mn1);
            float p3 = __expf(s[nt][3] - mn1);
            rs0 += p0 + p1; rs1 += p2 + p3;
            __nv_bfloat162 h01, h23, lo01, lo23;
            h01.x = __float2bfloat16(p0); h01.y = __float2bfloat16(p1);
            h23.x = __float2bfloat16(p2); h23.y = __float2bfloat16(p3);
            lo01.x = __float2bfloat16(p0 - __bfloat162float(h01.x));
            lo01.y = __float2bfloat16(p1 - __bfloat162float(h01.y));
            lo23.x = __float2bfloat16(p2 - __bfloat162float(h23.x));
            lo23.y = __float2bfloat16(p3 - __bfloat162float(h23.y));
            ph[nt][0] = *(uint32_t*)&h01;  ph[nt][1] = *(uint32_t*)&h23;
            pl[nt][0] = *(uint32_t*)&lo01; pl[nt][1] = *(uint32_t*)&lo23;
        }
        rs0 += __shfl_xor_sync(0xffffffffu, rs0, 1);
        rs0 += __shfl_xor_sync(0xffffffffu, rs0, 2);
        rs1 += __shfl_xor_sync(0xffffffffu, rs1, 1);
        rs1 += __shfl_xor_sync(0xffffffffu, rs1, 2);
        l0 = l0 * corr0 + rs0;
        l1 = l1 * corr1 + rs1;
        #pragma unroll
        for (int nt = 0; nt < 16; ++nt) {
            O[nt][0] *= corr0; O[nt][1] *= corr0;
            O[nt][2] *= corr1; O[nt][3] *= corr1;
        }

        // ---- O += P V  via ldmatrix.trans ----
        #pragma unroll
        for (int ks = 0; ks < 4; ++ks) {
            uint32_t a_h[4] = { ph[2*ks][0], ph[2*ks][1], ph[2*ks+1][0], ph[2*ks+1][1] };
            uint32_t a_l[4] = { pl[2*ks][0], pl[2*ks][1], pl[2*ks+1][0], pl[2*ks+1][1] };
            const uint32_t krow = (uint32_t)(ks * 16 * 272);
            #pragma unroll
            for (int ntp = 0; ntp < 8; ++ntp) {
                uint32_t vh0, vh1, vh2, vh3, wl0, wl1, wl2, wl3;
                LDSM4T(vh0, vh1, vh2, vh3, vBaseH + krow + (uint32_t)(ntp * 32));
                LDSM4T(wl0, wl1, wl2, wl3, vBaseL + krow + (uint32_t)(ntp * 32));
                uint32_t b0[2] = { vh0, vh1 }, b1[2] = { vh2, vh3 };
                uint32_t c0[2] = { wl0, wl1 }, c1[2] = { wl2, wl3 };
                MMA(O[2*ntp],   a_h, b0);
                MMA(O[2*ntp],   a_l, b0);
                MMA(O[2*ntp],   a_h, c0);
                MMA(O[2*ntp+1], a_h, b1);
                MMA(O[2*ntp+1], a_l, b1);
                MMA(O[2*ntp+1], a_h, c1);
            }
        }
        __syncthreads();
    }

    // ---- epilogue: O/l -> z bf16 hi/lo ----
    const float inv0 = 1.f / l0, inv1 = 1.f / l1;
    const size_t r0g = qmbase + wid * 16 + l4;
    const size_t r1g = r0g + 8;
    #pragma unroll
    for (int nt = 0; nt < 16; ++nt) {
        const int col = colbase + nt * 8 + 2 * l3;
        const float o0 = O[nt][0] * inv0, o1 = O[nt][1] * inv0;
        const float o2 = O[nt][2] * inv1, o3 = O[nt][3] * inv1;
        __nv_bfloat162 h01, h23, lo01, lo23;
        h01.x = __float2bfloat16(o0); h01.y = __float2bfloat16(o1);
        h23.x = __float2bfloat16(o2); h23.y = __float2bfloat16(o3);
        lo01.x = __float2bfloat16(o0 - __bfloat162float(h01.x));
        lo01.y = __float2bfloat16(o1 - __bfloat162float(h01.y));
        lo23.x = __float2bfloat16(o2 - __bfloat162float(h23.x));
        lo23.y = __float2bfloat16(o3 - __bfloat162float(h23.y));
        *(uint32_t*)&g_zh[r0g * D_MODEL + col] = *(uint32_t*)&h01;
        *(uint32_t*)&g_zl[r0g * D_MODEL + col] = *(uint32_t*)&lo01;
        *(uint32_t*)&g_zh[r1g * D_MODEL + col] = *(uint32_t*)&h23;
        *(uint32_t*)&g_zl[r1g * D_MODEL + col] = *(uint32_t*)&lo23;
    }
}

// -----------------------------------------------------------------------------
extern "C" void kernel_launch(void* const* d_in, const int* in_sizes, int n_in,
                              void* d_out, int out_size)
{
    const float* x     = (const float*)d_in[0];
    const float* W_qkv = (const float*)d_in[1];
    const float* b_qkv = (const float*)d_in[2];
    const float* W_o   = (const float*)d_in[3];
    const float* b_o   = (const float*)d_in[4];
    const float* wq    = (const float*)d_in[5];
    const float* wk    = (const float*)d_in[6];

    float* out   = (float*)d_out;
    float* k_out = out   + (size_t)M_TOT * D_MODEL;
    float* v_out = k_out + (size_t)M_TOT * D_MODEL;

    float* qkv;
    cudaGetSymbolAddress((void**)&qkv, g_qkv);
    __nv_bfloat16 *xh, *xl, *wqh, *wql, *woh, *wol, *zh, *zl;
    cudaGetSymbolAddress((void**)&xh,  g_xh);
    cudaGetSymbolAddress((void**)&xl,  g_xl);
    cudaGetSymbolAddress((void**)&wqh, g_wqkvh);
    cudaGetSymbolAddress((void**)&wql, g_wqkvl);
    cudaGetSymbolAddress((void**)&woh, g_woh);
    cudaGetSymbolAddress((void**)&wol, g_wol);
    cudaGetSymbolAddress((void**)&zh,  g_zh);
    cudaGetSymbolAddress((void**)&zl,  g_zl);

    static bool attr_set = false;
    if (!attr_set) {
        cudaFuncSetAttribute(gemm_tc, cudaFuncAttributeMaxDynamicSharedMemorySize, GEMM_SMEM);
        cudaFuncSetAttribute(attn_tc, cudaFuncAttributeMaxDynamicSharedMemorySize, ATT_SMEM);
        attr_set = true;
    }

    // 0) split fp32 operands to bf16 hi/lo
    conv_split<<<(M_TOT*D_MODEL/4 + 255)/256, 256>>>(x, xh, xl, M_TOT*D_MODEL/4);
    conv_split<<<(NQKV*D_MODEL/4 + 255)/256, 256>>>(W_qkv, wqh, wql, NQKV*D_MODEL/4);
    conv_split<<<(D_MODEL*D_MODEL/4 + 255)/256, 256>>>(W_o, woh, wol, D_MODEL*D_MODEL/4);

    // 1) qkv = x @ W_qkv^T + b_qkv
    gemm_tc<<<dim3(NQKV/128, M_TOT/128), 256, GEMM_SMEM>>>(xh, xl, wqh, wql, b_qkv, qkv, NQKV, D_MODEL);

    // 2) split + rms-norm -> bf16 hi/lo q/k/v (+ fp32 k_out, v_out)
    norm_split<<<dim3(M_TOT, N_HEADS), 128>>>(wq, wk, k_out, v_out);

    // 3) attention (HMMA + ldmatrix) -> g_zh/g_zl
    attn_tc<<<dim3(SEQ/64, BATCH*N_HEADS), 128, ATT_SMEM>>>();

    // 4) out = z @ W_o^T + b_o
    gemm_tc<<<dim3(D_MODEL/128, M_TOT/128), 256, GEMM_SMEM>>>(zh, zl, woh, wol, b_o, out, D_MODEL, D_MODEL);
}

// round 10
// speedup vs baseline: 4.1446x; 1.1338x over previous
#include <cuda_runtime.h>
#include <cuda_fp16.h>
#include <math.h>
#include <stdint.h>

#define D_MODEL 2048
#define N_HEADS 16
#define D_HEAD  128
#define BATCH   2
#define SEQ     2048
#define M_TOT   (BATCH*SEQ)      /* 4096 */
#define NQKV    (3*D_MODEL)      /* 6144 */
#define EPSF    1e-6f

// ---------------- scratch (device globals; no allocs allowed) ----------------
__device__ float g_qkv[(size_t)M_TOT * NQKV];     // 100 MB

__device__ __half g_xh[(size_t)M_TOT * D_MODEL];
__device__ __half g_xl[(size_t)M_TOT * D_MODEL];
__device__ __half g_wqkvh[(size_t)NQKV * D_MODEL];
__device__ __half g_wqkvl[(size_t)NQKV * D_MODEL];
__device__ __half g_woh[(size_t)D_MODEL * D_MODEL];
__device__ __half g_zh[(size_t)M_TOT * D_MODEL];
__device__ __half g_zl[(size_t)M_TOT * D_MODEL];

__device__ __half g_qh[(size_t)M_TOT * D_MODEL];
__device__ __half g_ql[(size_t)M_TOT * D_MODEL];
__device__ __half g_kh[(size_t)M_TOT * D_MODEL];
__device__ __half g_kl[(size_t)M_TOT * D_MODEL];
__device__ __half g_vh[(size_t)M_TOT * D_MODEL];

// ---------------- helpers ----------------------------------------------------
__device__ __forceinline__ uint32_t smem_u32(const void* p) {
    uint32_t a;
    asm("{ .reg .u64 t; cvta.to.shared.u64 t, %1; cvt.u32.u64 %0, t; }"
        : "=r"(a) : "l"(p));
    return a;
}

#define MMA(c, a, b) \
    asm volatile("mma.sync.aligned.m16n8k16.row.col.f32.f16.f16.f32 " \
                 "{%0,%1,%2,%3},{%4,%5,%6,%7},{%8,%9},{%0,%1,%2,%3};" \
                 : "+f"((c)[0]), "+f"((c)[1]), "+f"((c)[2]), "+f"((c)[3]) \
                 : "r"((a)[0]), "r"((a)[1]), "r"((a)[2]), "r"((a)[3]), \
                   "r"((b)[0]), "r"((b)[1]))

#define CPA16(dst, src) \
    asm volatile("cp.async.cg.shared.global [%0], [%1], 16;" :: "r"(dst), "l"(src))

#define LDSM4(r0_, r1_, r2_, r3_, a_) \
    asm volatile("ldmatrix.sync.aligned.m8n8.x4.shared.b16 {%0,%1,%2,%3},[%4];" \
                 : "=r"(r0_), "=r"(r1_), "=r"(r2_), "=r"(r3_) : "r"(a_))

#define LDSM4T(r0_, r1_, r2_, r3_, a_) \
    asm volatile("ldmatrix.sync.aligned.m8n8.x4.trans.shared.b16 {%0,%1,%2,%3},[%4];" \
                 : "=r"(r0_), "=r"(r1_), "=r"(r2_), "=r"(r3_) : "r"(a_))

// ---------------- fp32 -> fp16 hi/lo split -----------------------------------
__global__ __launch_bounds__(256) void conv_split(
    const float* __restrict__ s, __half* __restrict__ hi,
    __half* __restrict__ lo, int n4)
{
    int i = blockIdx.x * blockDim.x + threadIdx.x;
    if (i >= n4) return;
    float4 v = ((const float4*)s)[i];
    __half2 h01, h23, l01, l23;
    h01.x = __float2half_rn(v.x); h01.y = __float2half_rn(v.y);
    h23.x = __float2half_rn(v.z); h23.y = __float2half_rn(v.w);
    l01.x = __float2half_rn(v.x - __half2float(h01.x));
    l01.y = __float2half_rn(v.y - __half2float(h01.y));
    l23.x = __float2half_rn(v.z - __half2float(h23.x));
    l23.y = __float2half_rn(v.w - __half2float(h23.y));
    ((__half2*)hi)[i*2]   = h01;
    ((__half2*)hi)[i*2+1] = h23;
    ((__half2*)lo)[i*2]   = l01;
    ((__half2*)lo)[i*2+1] = l23;
}

__global__ __launch_bounds__(256) void conv_hi(
    const float* __restrict__ s, __half* __restrict__ hi, int n4)
{
    int i = blockIdx.x * blockDim.x + threadIdx.x;
    if (i >= n4) return;
    float4 v = ((const float4*)s)[i];
    __half2 h01, h23;
    h01.x = __float2half_rn(v.x); h01.y = __float2half_rn(v.y);
    h23.x = __float2half_rn(v.z); h23.y = __float2half_rn(v.w);
    ((__half2*)hi)[i*2]   = h01;
    ((__half2*)hi)[i*2+1] = h23;
}

// ---------------- HMMA split-fp16 GEMM, per-CTA 2- or 3-pass ------------------
// C[M,N] = A[M,K]*B[N,K]^T + bias.
// CTAs with bn < n3 run 3-pass (Ah*Bh + Al*Bh + Ah*Bl); others 2-pass (no Bl).
#define TILE_E 5120
#define STG_E  (4*TILE_E)
#define GEMM_SMEM (2*STG_E*2)    /* 81920 B */

__global__ __launch_bounds__(256, 2) void gemm_tc(
    const __half* __restrict__ pAh, const __half* __restrict__ pAl,
    const __half* __restrict__ pBh, const __half* __restrict__ pBl,
    const float* __restrict__ bias, float* __restrict__ C,
    int N, int K, int n3)
{
    extern __shared__ __half sm[];
    const int tid = threadIdx.x, lane = tid & 31, wid = tid >> 5;
    const int wm = wid >> 1, wn = wid & 1;
    const int bm = blockIdx.y * 128, bn = blockIdx.x * 128;
    const bool three = (bn < n3);
    const uint32_t smb = smem_u32(sm);

    const int rr = lane & 7, sub = lane >> 3;
    const uint32_t offA = (uint32_t)((rr + (sub & 1) * 8) * 80 + (sub >> 1) * 16);
    const uint32_t offB = (uint32_t)((rr + (sub >> 1) * 8) * 80 + (sub & 1) * 16);

    float acc[2][8][4];
    #pragma unroll
    for (int mt = 0; mt < 2; ++mt)
        #pragma unroll
        for (int nt = 0; nt < 8; ++nt)
            #pragma unroll
            for (int j = 0; j < 4; ++j) acc[mt][nt][j] = 0.f;

    const int nch = K / 32;
    const __half* srcs[4] = {
        pAh + (size_t)bm * K, pAl + (size_t)bm * K,
        pBh + (size_t)bn * K, pBl + (size_t)bn * K };
    const int ntl = three ? 4 : 3;

    const int lrow = tid >> 2, lcc = tid & 3;
    const int lrow2 = (tid + 256) >> 2;

    #define ISSUE(st, ch) do {                                             \
        const int _k0 = (ch) * 32;                                         \
        for (int _t = 0; _t < ntl; ++_t) {                                 \
            const __half* _s0 = srcs[_t] + _k0 + lcc * 8;                  \
            uint32_t _d0 = smb + (uint32_t)(((st)*4 + _t) * (TILE_E*2));   \
            const void* _sp1 = _s0 + (size_t)lrow * K;                     \
            uint32_t _dp1 = _d0 + (uint32_t)(lrow * 80 + lcc * 16);        \
            CPA16(_dp1, _sp1);                                             \
            const void* _sp2 = _s0 + (size_t)lrow2 * K;                    \
            uint32_t _dp2 = _d0 + (uint32_t)(lrow2 * 80 + lcc * 16);       \
            CPA16(_dp2, _sp2);                                             \
        }                                                                  \
        asm volatile("cp.async.commit_group;" ::: "memory");               \
    } while (0)

    ISSUE(0, 0);

    for (int ch = 0; ch < nch; ++ch) {
        const int st = ch & 1;
        asm volatile("cp.async.wait_group 0;" ::: "memory");
        __syncthreads();
        if (ch + 1 < nch) ISSUE(st ^ 1, ch + 1);

        const uint32_t stbase = smb + (uint32_t)(st * (STG_E * 2));
        const uint32_t aBase = stbase + (uint32_t)(wm * 32 * 80) + offA;
        const uint32_t bBase = stbase + (uint32_t)(2 * TILE_E * 2) +
                               (uint32_t)(wn * 64 * 80) + offB;

        #pragma unroll
        for (int k16 = 0; k16 < 2; ++k16) {
            const uint32_t cb = (uint32_t)(k16 * 32);
            uint32_t ah[2][4], al[2][4], bh[8][2], bl[8][2];
            #pragma unroll
            for (int mt = 0; mt < 2; ++mt) {
                LDSM4(ah[mt][0], ah[mt][1], ah[mt][2], ah[mt][3],
                      aBase + (uint32_t)(mt * 1280) + cb);
                LDSM4(al[mt][0], al[mt][1], al[mt][2], al[mt][3],
                      aBase + (uint32_t)(TILE_E * 2 + mt * 1280) + cb);
            }
            #pragma unroll
            for (int p = 0; p < 4; ++p)
                LDSM4(bh[2*p][0], bh[2*p][1], bh[2*p+1][0], bh[2*p+1][1],
                      bBase + (uint32_t)(p * 1280) + cb);
            if (three) {
                #pragma unroll
                for (int p = 0; p < 4; ++p)
                    LDSM4(bl[2*p][0], bl[2*p][1], bl[2*p+1][0], bl[2*p+1][1],
                          bBase + (uint32_t)(TILE_E * 2 + p * 1280) + cb);
            }
            #pragma unroll
            for (int mt = 0; mt < 2; ++mt)
                #pragma unroll
                for (int nt = 0; nt < 8; ++nt) {
                    MMA(acc[mt][nt], ah[mt], bh[nt]);
                    MMA(acc[mt][nt], al[mt], bh[nt]);
                }
            if (three) {
                #pragma unroll
                for (int mt = 0; mt < 2; ++mt)
                    #pragma unroll
                    for (int nt = 0; nt < 8; ++nt)
                        MMA(acc[mt][nt], ah[mt], bl[nt]);
            }
        }
        __syncthreads();
    }

    #pragma unroll
    for (int mt = 0; mt < 2; ++mt) {
        const int r1 = bm + wm * 32 + mt * 16 + (lane >> 2);
        const int r2 = r1 + 8;
        #pragma unroll
        for (int nt = 0; nt < 8; ++nt) {
            const int cb = bn + wn * 64 + nt * 8 + (lane & 3) * 2;
            const float b0 = bias[cb], b1 = bias[cb + 1];
            float2 o1, o2;
            o1.x = acc[mt][nt][0] + b0; o1.y = acc[mt][nt][1] + b1;
            o2.x = acc[mt][nt][2] + b0; o2.y = acc[mt][nt][3] + b1;
            *(float2*)&C[(size_t)r1 * N + cb] = o1;
            *(float2*)&C[(size_t)r2 * N + cb] = o2;
        }
    }
}

// --------------- norm/split -> fp16 operands + fp32 k/v outputs --------------
__global__ __launch_bounds__(128) void norm_split(
    const float* __restrict__ wq, const float* __restrict__ wk,
    float* __restrict__ k_out, float* __restrict__ v_out)
{
    const int m = blockIdx.x;
    const int h = blockIdx.y;
    const int t = threadIdx.x;
    const float* row = g_qkv + (size_t)m * NQKV;
    const float q = row[h*D_HEAD + t];
    const float k = row[D_MODEL   + h*D_HEAD + t];
    const float v = row[2*D_MODEL + h*D_HEAD + t];

    const size_t oidx = (size_t)m * D_MODEL + h*D_HEAD + t;
    k_out[oidx] = k;
    v_out[oidx] = v;

    float sq = q*q, sk = k*k;
    #pragma unroll
    for (int off = 16; off > 0; off >>= 1) {
        sq += __shfl_xor_sync(0xffffffffu, sq, off);
        sk += __shfl_xor_sync(0xffffffffu, sk, off);
    }
    __shared__ float bufq[4], bufk[4];
    if ((t & 31) == 0) { bufq[t>>5] = sq; bufk[t>>5] = sk; }
    __syncthreads();
    sq = bufq[0] + bufq[1] + bufq[2] + bufq[3];
    sk = bufk[0] + bufk[1] + bufk[2] + bufk[3];
    const float rq = rsqrtf(sq * (1.f/128.f) + EPSF);
    const float rk = rsqrtf(sk * (1.f/128.f) + EPSF);
    const float qn = q * rq * wq[t];
    const float kn = k * rk * wk[t];

    __half qh = __float2half_rn(qn);
    __half kh = __float2half_rn(kn);
    g_qh[oidx] = qh;
    g_ql[oidx] = __float2half_rn(qn - __half2float(qh));
    g_kh[oidx] = kh;
    g_kl[oidx] = __float2half_rn(kn - __half2float(kh));
    g_vh[oidx] = __float2half_rn(v);
}

// --------------- flash attention: S 3-pass, PV 2-pass ------------------------
// smem tiles: Qh | Ql | Kh | Kl | Vh, each 64 x 136 half
#define AT_STRIDE 136
#define AT_TILE_E (64*AT_STRIDE)     /* 8704 elems = 17408 B */
#define ATT_SMEM  (5*AT_TILE_E*2)    /* 87040 B */

__global__ __launch_bounds__(128, 2) void attn_tc()
{
    extern __shared__ __half smb[];
    const int tid = threadIdx.x, lane = tid & 31, wid = tid >> 5;
    const int l3 = lane & 3, l4 = lane >> 2;
    const int rr = lane & 7, sub = lane >> 3;
    const int qt = blockIdx.x;
    const int bh = blockIdx.y;
    const int b = bh >> 4, h = bh & 15;
    const size_t qmbase = (size_t)b * SEQ + qt * 64;
    const size_t kmbase = (size_t)b * SEQ;
    const int colbase = h * D_HEAD;

    const uint32_t smbase = smem_u32(smb);

    const uint32_t offA  = (uint32_t)((rr + (sub & 1) * 8) * 272 + (sub >> 1) * 16);
    const uint32_t offB  = (uint32_t)((rr + (sub >> 1) * 8) * 272 + (sub & 1) * 16);

    // ---- load Q tile (hi+lo) ----
    {
        const __half* gq = g_qh + qmbase * D_MODEL + colbase;
        const __half* gl = g_ql + qmbase * D_MODEL + colbase;
        #pragma unroll
        for (int it = 0; it < 8; ++it) {
            const int c = it * 128 + tid;
            const int row = c >> 4, c16 = c & 15;
            const uint32_t dst = smbase + (uint32_t)(row * 272 + c16 * 16);
            CPA16(dst,                 gq + (size_t)row * D_MODEL + c16 * 8);
            CPA16(dst + AT_TILE_E * 2, gl + (size_t)row * D_MODEL + c16 * 8);
        }
        asm volatile("cp.async.commit_group;" ::: "memory");
    }

    float O[16][4];
    #pragma unroll
    for (int nt = 0; nt < 16; ++nt)
        #pragma unroll
        for (int j = 0; j < 4; ++j) O[nt][j] = 0.f;
    float m0 = -1e30f, m1 = -1e30f, l0 = 0.f, l1 = 0.f;

    const uint32_t qBaseH = smbase + (uint32_t)(wid * 16 * 272) + offA;
    const uint32_t qBaseL = qBaseH + (uint32_t)(AT_TILE_E * 2);
    const uint32_t kBaseH = smbase + (uint32_t)(2 * AT_TILE_E * 2) + offB;
    const uint32_t kBaseL = kBaseH + (uint32_t)(AT_TILE_E * 2);
    const uint32_t vBaseH = smbase + (uint32_t)(4 * AT_TILE_E * 2) + offA;

    for (int kt = 0; kt < SEQ/64; ++kt) {
        // ---- load K hi/lo + V hi ----
        {
            const size_t mrow = (kmbase + kt * 64) * D_MODEL + colbase;
            const __half* s0 = g_kh + mrow;
            const __half* s1 = g_kl + mrow;
            const __half* s2 = g_vh + mrow;
            #pragma unroll
            for (int it = 0; it < 8; ++it) {
                const int c = it * 128 + tid;
                const int row = c >> 4, c16 = c & 15;
                const size_t so = (size_t)row * D_MODEL + c16 * 8;
                const uint32_t dst = smbase + (uint32_t)(row * 272 + c16 * 16);
                CPA16(dst + 2*AT_TILE_E*2, s0 + so);
                CPA16(dst + 3*AT_TILE_E*2, s1 + so);
                CPA16(dst + 4*AT_TILE_E*2, s2 + so);
            }
            asm volatile("cp.async.commit_group;" ::: "memory");
        }
        asm volatile("cp.async.wait_group 0;" ::: "memory");
        __syncthreads();

        // ---- S = Qn Kn^T, 3-pass (drop Ql*Kl) ----
        float s[8][4];
        #pragma unroll
        for (int nt = 0; nt < 8; ++nt)
            #pragma unroll
            for (int j = 0; j < 4; ++j) s[nt][j] = 0.f;

        #pragma unroll
        for (int ks = 0; ks < 8; ++ks) {
            const uint32_t cb = (uint32_t)(ks * 32);
            uint32_t ah[4], al[4], bh2[8][2], bl2[8][2];
            LDSM4(ah[0], ah[1], ah[2], ah[3], qBaseH + cb);
            LDSM4(al[0], al[1], al[2], al[3], qBaseL + cb);
            #pragma unroll
            for (int p = 0; p < 4; ++p) {
                LDSM4(bh2[2*p][0], bh2[2*p][1], bh2[2*p+1][0], bh2[2*p+1][1],
                      kBaseH + (uint32_t)(p * 16 * 272) + cb);
                LDSM4(bl2[2*p][0], bl2[2*p][1], bl2[2*p+1][0], bl2[2*p+1][1],
                      kBaseL + (uint32_t)(p * 16 * 272) + cb);
            }
            #pragma unroll
            for (int nt = 0; nt < 8; ++nt) {
                MMA(s[nt], ah, bh2[nt]);
                MMA(s[nt], ah, bl2[nt]);
                MMA(s[nt], al, bh2[nt]);
            }
        }

        // ---- online softmax on fragments ----
        float mx0 = -1e30f, mx1 = -1e30f;
        #pragma unroll
        for (int nt = 0; nt < 8; ++nt) {
            mx0 = fmaxf(mx0, fmaxf(s[nt][0], s[nt][1]));
            mx1 = fmaxf(mx1, fmaxf(s[nt][2], s[nt][3]));
        }
        mx0 = fmaxf(mx0, __shfl_xor_sync(0xffffffffu, mx0, 1));
        mx0 = fmaxf(mx0, __shfl_xor_sync(0xffffffffu, mx0, 2));
        mx1 = fmaxf(mx1, __shfl_xor_sync(0xffffffffu, mx1, 1));
        mx1 = fmaxf(mx1, __shfl_xor_sync(0xffffffffu, mx1, 2));
        const float mn0 = fmaxf(m0, mx0), mn1 = fmaxf(m1, mx1);
        const float corr0 = __expf(m0 - mn0), corr1 = __expf(m1 - mn1);
        m0 = mn0; m1 = mn1;

        uint32_t ph[8][2], pl[8][2];
        float rs0 = 0.f, rs1 = 0.f;
        #pragma unroll
        for (int nt = 0; nt < 8; ++nt) {
            float p0 = __expf(s[nt][0] - mn0);
            float p1 = __expf(s[nt][1] - mn0);
            float p2 = __expf(s[nt][2] - mn1);
            float p3 = __expf(s[nt][3] - mn1);
            rs0 += p0 + p1; rs1 += p2 + p3;
            __half2 h01, h23, lo01, lo23;
            h01.x = __float2half_rn(p0); h01.y = __float2half_rn(p1);
            h23.x = __float2half_rn(p2); h23.y = __float2half_rn(p3);
            lo01.x = __float2half_rn(p0 - __half2float(h01.x));
            lo01.y = __float2half_rn(p1 - __half2float(h01.y));
            lo23.x = __float2half_rn(p2 - __half2float(h23.x));
            lo23.y = __float2half_rn(p3 - __half2float(h23.y));
            ph[nt][0] = *(uint32_t*)&h01;  ph[nt][1] = *(uint32_t*)&h23;
            pl[nt][0] = *(uint32_t*)&lo01; pl[nt][1] = *(uint32_t*)&lo23;
        }
        rs0 += __shfl_xor_sync(0xffffffffu, rs0, 1);
        rs0 += __shfl_xor_sync(0xffffffffu, rs0, 2);
        rs1 += __shfl_xor_sync(0xffffffffu, rs1, 1);
        rs1 += __shfl_xor_sync(0xffffffffu, rs1, 2);
        l0 = l0 * corr0 + rs0;
        l1 = l1 * corr1 + rs1;
        #pragma unroll
        for (int nt = 0; nt < 16; ++nt) {
            O[nt][0] *= corr0; O[nt][1] *= corr0;
            O[nt][2] *= corr1; O[nt][3] *= corr1;
        }

        // ---- O += (Ph+Pl) Vh  via ldmatrix.trans ----
        #pragma unroll
        for (int ks = 0; ks < 4; ++ks) {
            uint32_t a_h[4] = { ph[2*ks][0], ph[2*ks][1], ph[2*ks+1][0], ph[2*ks+1][1] };
            uint32_t a_l[4] = { pl[2*ks][0], pl[2*ks][1], pl[2*ks+1][0], pl[2*ks+1][1] };
            const uint32_t krow = (uint32_t)(ks * 16 * 272);
            #pragma unroll
            for (int ntp = 0; ntp < 8; ++ntp) {
                uint32_t vh0, vh1, vh2, vh3;
                LDSM4T(vh0, vh1, vh2, vh3, vBaseH + krow + (uint32_t)(ntp * 32));
                uint32_t b0[2] = { vh0, vh1 }, b1[2] = { vh2, vh3 };
                MMA(O[2*ntp],   a_h, b0);
                MMA(O[2*ntp],   a_l, b0);
                MMA(O[2*ntp+1], a_h, b1);
                MMA(O[2*ntp+1], a_l, b1);
            }
        }
        __syncthreads();
    }

    // ---- epilogue: O/l -> z fp16 hi/lo ----
    const float inv0 = 1.f / l0, inv1 = 1.f / l1;
    const size_t r0g = qmbase + wid * 16 + l4;
    const size_t r1g = r0g + 8;
    #pragma unroll
    for (int nt = 0; nt < 16; ++nt) {
        const int col = colbase + nt * 8 + 2 * l3;
        const float o0 = O[nt][0] * inv0, o1 = O[nt][1] * inv0;
        const float o2 = O[nt][2] * inv1, o3 = O[nt][3] * inv1;
        __half2 h01, h23, lo01, lo23;
        h01.x = __float2half_rn(o0); h01.y = __float2half_rn(o1);
        h23.x = __float2half_rn(o2); h23.y = __float2half_rn(o3);
        lo01.x = __float2half_rn(o0 - __half2float(h01.x));
        lo01.y = __float2half_rn(o1 - __half2float(h01.y));
        lo23.x = __float2half_rn(o2 - __half2float(h23.x));
        lo23.y = __float2half_rn(o3 - __half2float(h23.y));
        *(uint32_t*)&g_zh[r0g * D_MODEL + col] = *(uint32_t*)&h01;
        *(uint32_t*)&g_zl[r0g * D_MODEL + col] = *(uint32_t*)&lo01;
        *(uint32_t*)&g_zh[r1g * D_MODEL + col] = *(uint32_t*)&h23;
        *(uint32_t*)&g_zl[r1g * D_MODEL + col] = *(uint32_t*)&lo23;
    }
}

// -----------------------------------------------------------------------------
extern "C" void kernel_launch(void* const* d_in, const int* in_sizes, int n_in,
                              void* d_out, int out_size)
{
    const float* x     = (const float*)d_in[0];
    const float* W_qkv = (const float*)d_in[1];
    const float* b_qkv = (const float*)d_in[2];
    const float* W_o   = (const float*)d_in[3];
    const float* b_o   = (const float*)d_in[4];
    const float* wq    = (const float*)d_in[5];
    const float* wk    = (const float*)d_in[6];

    float* out   = (float*)d_out;
    float* k_out = out   + (size_t)M_TOT * D_MODEL;
    float* v_out = k_out + (size_t)M_TOT * D_MODEL;

    float* qkv;
    cudaGetSymbolAddress((void**)&qkv, g_qkv);
    __half *xh, *xl, *wqh, *wql, *woh, *zh, *zl;
    cudaGetSymbolAddress((void**)&xh,  g_xh);
    cudaGetSymbolAddress((void**)&xl,  g_xl);
    cudaGetSymbolAddress((void**)&wqh, g_wqkvh);
    cudaGetSymbolAddress((void**)&wql, g_wqkvl);
    cudaGetSymbolAddress((void**)&woh, g_woh);
    cudaGetSymbolAddress((void**)&zh,  g_zh);
    cudaGetSymbolAddress((void**)&zl,  g_zl);

    static bool attr_set = false;
    if (!attr_set) {
        cudaFuncSetAttribute(gemm_tc, cudaFuncAttributeMaxDynamicSharedMemorySize, GEMM_SMEM);
        cudaFuncSetAttribute(attn_tc, cudaFuncAttributeMaxDynamicSharedMemorySize, ATT_SMEM);
        attr_set = true;
    }

    // 0) operand conversion
    conv_split<<<(M_TOT*D_MODEL/4 + 255)/256, 256>>>(x, xh, xl, M_TOT*D_MODEL/4);
    conv_split<<<(NQKV*D_MODEL/4 + 255)/256, 256>>>(W_qkv, wqh, wql, NQKV*D_MODEL/4);
    conv_hi<<<(D_MODEL*D_MODEL/4 + 255)/256, 256>>>(W_o, woh, D_MODEL*D_MODEL/4);

    // 1) qkv: q,k columns 3-pass (n3 = 4096), v columns 2-pass
    gemm_tc<<<dim3(NQKV/128, M_TOT/128), 256, GEMM_SMEM>>>(
        xh, xl, wqh, wql, b_qkv, qkv, NQKV, D_MODEL, 2*D_MODEL);

    // 2) split + rms-norm -> fp16 q(hi/lo), k(hi/lo), v(hi) + fp32 k_out, v_out
    norm_split<<<dim3(M_TOT, N_HEADS), 128>>>(wq, wk, k_out, v_out);

    // 3) attention -> g_zh/g_zl
    attn_tc<<<dim3(SEQ/64, BATCH*N_HEADS), 128, ATT_SMEM>>>();

    // 4) out = z @ W_o^T + b_o   (2-pass everywhere)
    gemm_tc<<<dim3(D_MODEL/128, M_TOT/128), 256, GEMM_SMEM>>>(
        zh, zl, woh, woh, b_o, out, D_MODEL, D_MODEL, 0);
}

// round 11
// speedup vs baseline: 4.3701x; 1.0544x over previous
#include <cuda_runtime.h>
#include <cuda_fp16.h>
#include <math.h>
#include <stdint.h>

#define D_MODEL 2048
#define N_HEADS 16
#define D_HEAD  128
#define BATCH   2
#define SEQ     2048
#define M_TOT   (BATCH*SEQ)      /* 4096 */
#define NQKV    (3*D_MODEL)      /* 6144 */
#define EPSF    1e-6f

// ---------------- scratch (device globals; no allocs allowed) ----------------
__device__ __half g_xh[(size_t)M_TOT * D_MODEL];
__device__ __half g_xl[(size_t)M_TOT * D_MODEL];
__device__ __half g_wqkvh[(size_t)NQKV * D_MODEL];
__device__ __half g_wqkvl[(size_t)NQKV * D_MODEL];
__device__ __half g_woh[(size_t)D_MODEL * D_MODEL];
__device__ __half g_zh[(size_t)M_TOT * D_MODEL];
__device__ __half g_zl[(size_t)M_TOT * D_MODEL];

__device__ __half g_qh[(size_t)M_TOT * D_MODEL];
__device__ __half g_ql[(size_t)M_TOT * D_MODEL];
__device__ __half g_kh[(size_t)M_TOT * D_MODEL];
__device__ __half g_kl[(size_t)M_TOT * D_MODEL];
__device__ __half g_vh[(size_t)M_TOT * D_MODEL];

// ---------------- helpers ----------------------------------------------------
__device__ __forceinline__ uint32_t smem_u32(const void* p) {
    uint32_t a;
    asm("{ .reg .u64 t; cvta.to.shared.u64 t, %1; cvt.u32.u64 %0, t; }"
        : "=r"(a) : "l"(p));
    return a;
}

#define MMA(c, a, b) \
    asm volatile("mma.sync.aligned.m16n8k16.row.col.f32.f16.f16.f32 " \
                 "{%0,%1,%2,%3},{%4,%5,%6,%7},{%8,%9},{%0,%1,%2,%3};" \
                 : "+f"((c)[0]), "+f"((c)[1]), "+f"((c)[2]), "+f"((c)[3]) \
                 : "r"((a)[0]), "r"((a)[1]), "r"((a)[2]), "r"((a)[3]), \
                   "r"((b)[0]), "r"((b)[1]))

#define CPA16(dst, src) \
    asm volatile("cp.async.cg.shared.global [%0], [%1], 16;" :: "r"(dst), "l"(src))

#define LDSM4(r0_, r1_, r2_, r3_, a_) \
    asm volatile("ldmatrix.sync.aligned.m8n8.x4.shared.b16 {%0,%1,%2,%3},[%4];" \
                 : "=r"(r0_), "=r"(r1_), "=r"(r2_), "=r"(r3_) : "r"(a_))

#define LDSM4T(r0_, r1_, r2_, r3_, a_) \
    asm volatile("ldmatrix.sync.aligned.m8n8.x4.trans.shared.b16 {%0,%1,%2,%3},[%4];" \
                 : "=r"(r0_), "=r"(r1_), "=r"(r2_), "=r"(r3_) : "r"(a_))

// ---------------- fp32 -> fp16 hi/lo split -----------------------------------
__global__ __launch_bounds__(256) void conv_split(
    const float* __restrict__ s, __half* __restrict__ hi,
    __half* __restrict__ lo, int n4)
{
    int i = blockIdx.x * blockDim.x + threadIdx.x;
    if (i >= n4) return;
    float4 v = ((const float4*)s)[i];
    __half2 h01, h23, l01, l23;
    h01.x = __float2half_rn(v.x); h01.y = __float2half_rn(v.y);
    h23.x = __float2half_rn(v.z); h23.y = __float2half_rn(v.w);
    l01.x = __float2half_rn(v.x - __half2float(h01.x));
    l01.y = __float2half_rn(v.y - __half2float(h01.y));
    l23.x = __float2half_rn(v.z - __half2float(h23.x));
    l23.y = __float2half_rn(v.w - __half2float(h23.y));
    ((__half2*)hi)[i*2]   = h01;
    ((__half2*)hi)[i*2+1] = h23;
    ((__half2*)lo)[i*2]   = l01;
    ((__half2*)lo)[i*2+1] = l23;
}

__global__ __launch_bounds__(256) void conv_hi(
    const float* __restrict__ s, __half* __restrict__ hi, int n4)
{
    int i = blockIdx.x * blockDim.x + threadIdx.x;
    if (i >= n4) return;
    float4 v = ((const float4*)s)[i];
    __half2 h01, h23;
    h01.x = __float2half_rn(v.x); h01.y = __float2half_rn(v.y);
    h23.x = __float2half_rn(v.z); h23.y = __float2half_rn(v.w);
    ((__half2*)hi)[i*2]   = h01;
    ((__half2*)hi)[i*2+1] = h23;
}

// ---------------- HMMA split-fp16 GEMM, optional fused rms-norm epilogue -----
// C[M,N] = A[M,K]*B[N,K]^T + bias. bn < n3 -> 3-pass, else 2-pass.
// fuse=1 (qkv): each 128-col tile is one head; epilogue does rms-norm and
// writes q/k/v operands + k_out/v_out instead of C.
#define TILE_E 5120
#define STG_E  (4*TILE_E)
#define GEMM_SMEM (2*STG_E*2)    /* 81920 B */

__global__ __launch_bounds__(256, 2) void gemm_tc(
    const __half* __restrict__ pAh, const __half* __restrict__ pAl,
    const __half* __restrict__ pBh, const __half* __restrict__ pBl,
    const float* __restrict__ bias, float* __restrict__ C,
    int N, int K, int n3, int fuse,
    float* __restrict__ k_out, float* __restrict__ v_out,
    const float* __restrict__ wq, const float* __restrict__ wk)
{
    extern __shared__ __half sm[];
    const int tid = threadIdx.x, lane = tid & 31, wid = tid >> 5;
    const int wm = wid >> 1, wn = wid & 1;
    const int bm = blockIdx.y * 128, bn = blockIdx.x * 128;
    const bool three = (bn < n3);
    const uint32_t smb = smem_u32(sm);

    const int rr = lane & 7, sub = lane >> 3;
    const int l3 = lane & 3, l4 = lane >> 2;
    const uint32_t offA = (uint32_t)((rr + (sub & 1) * 8) * 80 + (sub >> 1) * 16);
    const uint32_t offB = (uint32_t)((rr + (sub >> 1) * 8) * 80 + (sub & 1) * 16);

    float acc[2][8][4];
    #pragma unroll
    for (int mt = 0; mt < 2; ++mt)
        #pragma unroll
        for (int nt = 0; nt < 8; ++nt)
            #pragma unroll
            for (int j = 0; j < 4; ++j) acc[mt][nt][j] = 0.f;

    const int nch = K / 32;
    const __half* srcs[4] = {
        pAh + (size_t)bm * K, pAl + (size_t)bm * K,
        pBh + (size_t)bn * K, pBl + (size_t)bn * K };
    const int ntl = three ? 4 : 3;

    const int lrow = tid >> 2, lcc = tid & 3;
    const int lrow2 = (tid + 256) >> 2;

    #define ISSUE(st, ch) do {                                             \
        const int _k0 = (ch) * 32;                                         \
        for (int _t = 0; _t < ntl; ++_t) {                                 \
            const __half* _s0 = srcs[_t] + _k0 + lcc * 8;                  \
            uint32_t _d0 = smb + (uint32_t)(((st)*4 + _t) * (TILE_E*2));   \
            const void* _sp1 = _s0 + (size_t)lrow * K;                     \
            uint32_t _dp1 = _d0 + (uint32_t)(lrow * 80 + lcc * 16);        \
            CPA16(_dp1, _sp1);                                             \
            const void* _sp2 = _s0 + (size_t)lrow2 * K;                    \
            uint32_t _dp2 = _d0 + (uint32_t)(lrow2 * 80 + lcc * 16);       \
            CPA16(_dp2, _sp2);                                             \
        }                                                                  \
        asm volatile("cp.async.commit_group;" ::: "memory");               \
    } while (0)

    ISSUE(0, 0);

    for (int ch = 0; ch < nch; ++ch) {
        const int st = ch & 1;
        asm volatile("cp.async.wait_group 0;" ::: "memory");
        __syncthreads();
        if (ch + 1 < nch) ISSUE(st ^ 1, ch + 1);

        const uint32_t stbase = smb + (uint32_t)(st * (STG_E * 2));
        const uint32_t aBase = stbase + (uint32_t)(wm * 32 * 80) + offA;
        const uint32_t bBase = stbase + (uint32_t)(2 * TILE_E * 2) +
                               (uint32_t)(wn * 64 * 80) + offB;

        #pragma unroll
        for (int k16 = 0; k16 < 2; ++k16) {
            const uint32_t cb = (uint32_t)(k16 * 32);
            uint32_t ah[2][4], al[2][4], bh[8][2], bl[8][2];
            #pragma unroll
            for (int mt = 0; mt < 2; ++mt) {
                LDSM4(ah[mt][0], ah[mt][1], ah[mt][2], ah[mt][3],
                      aBase + (uint32_t)(mt * 1280) + cb);
                LDSM4(al[mt][0], al[mt][1], al[mt][2], al[mt][3],
                      aBase + (uint32_t)(TILE_E * 2 + mt * 1280) + cb);
            }
            #pragma unroll
            for (int p = 0; p < 4; ++p)
                LDSM4(bh[2*p][0], bh[2*p][1], bh[2*p+1][0], bh[2*p+1][1],
                      bBase + (uint32_t)(p * 1280) + cb);
            if (three) {
                #pragma unroll
                for (int p = 0; p < 4; ++p)
                    LDSM4(bl[2*p][0], bl[2*p][1], bl[2*p+1][0], bl[2*p+1][1],
                          bBase + (uint32_t)(TILE_E * 2 + p * 1280) + cb);
            }
            #pragma unroll
            for (int mt = 0; mt < 2; ++mt)
                #pragma unroll
                for (int nt = 0; nt < 8; ++nt) {
                    MMA(acc[mt][nt], ah[mt], bh[nt]);
                    MMA(acc[mt][nt], al[mt], bh[nt]);
                }
            if (three) {
                #pragma unroll
                for (int mt = 0; mt < 2; ++mt)
                    #pragma unroll
                    for (int nt = 0; nt < 8; ++nt)
                        MMA(acc[mt][nt], ah[mt], bl[nt]);
            }
        }
        __syncthreads();
    }

    // ---- add bias ----
    #pragma unroll
    for (int mt = 0; mt < 2; ++mt)
        #pragma unroll
        for (int nt = 0; nt < 8; ++nt) {
            const int cbl = wn * 64 + nt * 8 + l3 * 2;
            const float b0 = bias[bn + cbl], b1 = bias[bn + cbl + 1];
            acc[mt][nt][0] += b0; acc[mt][nt][1] += b1;
            acc[mt][nt][2] += b0; acc[mt][nt][3] += b1;
        }

    if (!fuse) {
        #pragma unroll
        for (int mt = 0; mt < 2; ++mt) {
            const int r1 = bm + wm * 32 + mt * 16 + l4;
            const int r2 = r1 + 8;
            #pragma unroll
            for (int nt = 0; nt < 8; ++nt) {
                const int cbg = bn + wn * 64 + nt * 8 + l3 * 2;
                float2 o1, o2;
                o1.x = acc[mt][nt][0]; o1.y = acc[mt][nt][1];
                o2.x = acc[mt][nt][2]; o2.y = acc[mt][nt][3];
                *(float2*)&C[(size_t)r1 * N + cbg] = o1;
                *(float2*)&C[(size_t)r2 * N + cbg] = o2;
            }
        }
        return;
    }

    // ---- fused qkv epilogue: tile = one head ----
    const int kind = (bn < D_MODEL) ? 0 : (bn < 2*D_MODEL ? 1 : 2);

    if (kind == 2) {
        // v: write v_out fp32 + g_vh fp16
        #pragma unroll
        for (int mt = 0; mt < 2; ++mt) {
            const int r1 = bm + wm * 32 + mt * 16 + l4;
            const int r2 = r1 + 8;
            #pragma unroll
            for (int nt = 0; nt < 8; ++nt) {
                const int col = (bn - 2*D_MODEL) + wn * 64 + nt * 8 + l3 * 2;
                float2 o1, o2;
                o1.x = acc[mt][nt][0]; o1.y = acc[mt][nt][1];
                o2.x = acc[mt][nt][2]; o2.y = acc[mt][nt][3];
                *(float2*)&v_out[(size_t)r1 * D_MODEL + col] = o1;
                *(float2*)&v_out[(size_t)r2 * D_MODEL + col] = o2;
                __half2 h1, h2;
                h1.x = __float2half_rn(o1.x); h1.y = __float2half_rn(o1.y);
                h2.x = __float2half_rn(o2.x); h2.y = __float2half_rn(o2.y);
                *(__half2*)&g_vh[(size_t)r1 * D_MODEL + col] = h1;
                *(__half2*)&g_vh[(size_t)r2 * D_MODEL + col] = h2;
            }
        }
        return;
    }

    // q or k: rms-norm across the tile's 128 cols
    float* rsum = (float*)sm;   // [2][128] reuse of tile smem
    float ss[2][2] = {{0.f,0.f},{0.f,0.f}};
    #pragma unroll
    for (int mt = 0; mt < 2; ++mt)
        #pragma unroll
        for (int nt = 0; nt < 8; ++nt) {
            ss[mt][0] += acc[mt][nt][0]*acc[mt][nt][0] + acc[mt][nt][1]*acc[mt][nt][1];
            ss[mt][1] += acc[mt][nt][2]*acc[mt][nt][2] + acc[mt][nt][3]*acc[mt][nt][3];
        }
    #pragma unroll
    for (int mt = 0; mt < 2; ++mt)
        #pragma unroll
        for (int hf = 0; hf < 2; ++hf) {
            ss[mt][hf] += __shfl_xor_sync(0xffffffffu, ss[mt][hf], 1);
            ss[mt][hf] += __shfl_xor_sync(0xffffffffu, ss[mt][hf], 2);
        }
    if (l3 == 0) {
        #pragma unroll
        for (int mt = 0; mt < 2; ++mt) {
            rsum[wn*128 + wm*32 + mt*16 + l4]     = ss[mt][0];
            rsum[wn*128 + wm*32 + mt*16 + l4 + 8] = ss[mt][1];
        }
    }
    __syncthreads();

    const float* wv = (kind == 0) ? wq : wk;
    __half* dst_h = (kind == 0) ? g_qh : g_kh;
    __half* dst_l = (kind == 0) ? g_ql : g_kl;
    const int colbase = (kind == 0) ? bn : bn - D_MODEL;

    #pragma unroll
    for (int mt = 0; mt < 2; ++mt) {
        const int rl1 = wm*32 + mt*16 + l4;
        const int rl2 = rl1 + 8;
        const float fac1 = rsqrtf((rsum[rl1] + rsum[128 + rl1]) * (1.f/128.f) + EPSF);
        const float fac2 = rsqrtf((rsum[rl2] + rsum[128 + rl2]) * (1.f/128.f) + EPSF);
        const int r1 = bm + rl1, r2 = bm + rl2;
        #pragma unroll
        for (int nt = 0; nt < 8; ++nt) {
            const int cbl = wn * 64 + nt * 8 + l3 * 2;
            const int col = colbase + cbl;
            if (kind == 1) {   // k_out: pre-norm fp32
                float2 o1, o2;
                o1.x = acc[mt][nt][0]; o1.y = acc[mt][nt][1];
                o2.x = acc[mt][nt][2]; o2.y = acc[mt][nt][3];
                *(float2*)&k_out[(size_t)r1 * D_MODEL + col] = o1;
                *(float2*)&k_out[(size_t)r2 * D_MODEL + col] = o2;
            }
            const float w0 = wv[cbl], w1 = wv[cbl + 1];
            const float n0 = acc[mt][nt][0] * fac1 * w0;
            const float n1 = acc[mt][nt][1] * fac1 * w1;
            const float n2 = acc[mt][nt][2] * fac2 * w0;
            const float n3v = acc[mt][nt][3] * fac2 * w1;
            __half2 h1, h2, lo1, lo2;
            h1.x = __float2half_rn(n0);  h1.y = __float2half_rn(n1);
            h2.x = __float2half_rn(n2);  h2.y = __float2half_rn(n3v);
            lo1.x = __float2half_rn(n0 - __half2float(h1.x));
            lo1.y = __float2half_rn(n1 - __half2float(h1.y));
            lo2.x = __float2half_rn(n2 - __half2float(h2.x));
            lo2.y = __float2half_rn(n3v - __half2float(h2.y));
            *(__half2*)&dst_h[(size_t)r1 * D_MODEL + col] = h1;
            *(__half2*)&dst_l[(size_t)r1 * D_MODEL + col] = lo1;
            *(__half2*)&dst_h[(size_t)r2 * D_MODEL + col] = h2;
            *(__half2*)&dst_l[(size_t)r2 * D_MODEL + col] = lo2;
        }
    }
}

// --------------- flash attention: BQ=128, double-buffered K/V ----------------
// smem: Qh|Ql (128x136) + 2 stages of (Kh|Kl|Vh) (64x136 each)
#define AT_STRIDE 136
#define KV_TILE_B (64*AT_STRIDE*2)    /* 17408 B */
#define QT_TILE_B (128*AT_STRIDE*2)   /* 34816 B */
#define KV_STG_B  (3*KV_TILE_B)       /* 52224 B */
#define KV_BASE_B (2*QT_TILE_B)       /* 69632 B */
#define ATT_SMEM  (KV_BASE_B + 2*KV_STG_B)  /* 174080 B */

__global__ __launch_bounds__(256, 1) void attn_tc()
{
    extern __shared__ __half smb[];
    const int tid = threadIdx.x, lane = tid & 31, wid = tid >> 5;
    const int l3 = lane & 3, l4 = lane >> 2;
    const int rr = lane & 7, sub = lane >> 3;
    const int qt = blockIdx.x;          // 0..15
    const int bh = blockIdx.y;          // 0..31
    const int b = bh >> 4, h = bh & 15;
    const size_t qmbase = (size_t)b * SEQ + qt * 128;
    const size_t kmbase = (size_t)b * SEQ;
    const int colbase = h * D_HEAD;

    const uint32_t smbase = smem_u32(smb);

    const uint32_t offA  = (uint32_t)((rr + (sub & 1) * 8) * 272 + (sub >> 1) * 16);
    const uint32_t offB  = (uint32_t)((rr + (sub >> 1) * 8) * 272 + (sub & 1) * 16);

    // ---- load Q tile (hi+lo, 128 rows) ----
    {
        const __half* gq = g_qh + qmbase * D_MODEL + colbase;
        const __half* gl = g_ql + qmbase * D_MODEL + colbase;
        #pragma unroll
        for (int it = 0; it < 8; ++it) {
            const int c = it * 256 + tid;
            const int row = c >> 4, c16 = c & 15;
            const uint32_t dst = smbase + (uint32_t)(row * 272 + c16 * 16);
            CPA16(dst,             gq + (size_t)row * D_MODEL + c16 * 8);
            CPA16(dst + QT_TILE_B, gl + (size_t)row * D_MODEL + c16 * 8);
        }
        asm volatile("cp.async.commit_group;" ::: "memory");
    }
    // ---- load KV stage 0 ----
    {
        const size_t mrow = kmbase * D_MODEL + colbase;
        #pragma unroll
        for (int it = 0; it < 4; ++it) {
            const int c = it * 256 + tid;
            const int row = c >> 4, c16 = c & 15;
            const size_t so = (size_t)row * D_MODEL + c16 * 8;
            const uint32_t dst = smbase + (uint32_t)(KV_BASE_B + row * 272 + c16 * 16);
            CPA16(dst,                 g_kh + mrow + so);
            CPA16(dst + KV_TILE_B,     g_kl + mrow + so);
            CPA16(dst + 2*KV_TILE_B,   g_vh + mrow + so);
        }
        asm volatile("cp.async.commit_group;" ::: "memory");
    }
    asm volatile("cp.async.wait_group 0;" ::: "memory");
    __syncthreads();

    float O[16][4];
    #pragma unroll
    for (int nt = 0; nt < 16; ++nt)
        #pragma unroll
        for (int j = 0; j < 4; ++j) O[nt][j] = 0.f;
    float m0 = -1e30f, m1 = -1e30f, l0 = 0.f, l1 = 0.f;

    const uint32_t qBaseH = smbase + (uint32_t)(wid * 16 * 272) + offA;
    const uint32_t qBaseL = qBaseH + QT_TILE_B;

    for (int kt = 0; kt < SEQ/64; ++kt) {
        const int st = kt & 1;
        // prefetch next KV into other stage
        if (kt + 1 < SEQ/64) {
            const size_t mrow = (kmbase + (kt + 1) * 64) * D_MODEL + colbase;
            const uint32_t sb = (uint32_t)(KV_BASE_B + (st ^ 1) * KV_STG_B);
            #pragma unroll
            for (int it = 0; it < 4; ++it) {
                const int c = it * 256 + tid;
                const int row = c >> 4, c16 = c & 15;
                const size_t so = (size_t)row * D_MODEL + c16 * 8;
                const uint32_t dst = smbase + sb + (uint32_t)(row * 272 + c16 * 16);
                CPA16(dst,               g_kh + mrow + so);
                CPA16(dst + KV_TILE_B,   g_kl + mrow + so);
                CPA16(dst + 2*KV_TILE_B, g_vh + mrow + so);
            }
            asm volatile("cp.async.commit_group;" ::: "memory");
        }

        const uint32_t kBaseH = smbase + (uint32_t)(KV_BASE_B + st * KV_STG_B) + offB;
        const uint32_t kBaseL = kBaseH + KV_TILE_B;
        const uint32_t vBaseH = smbase + (uint32_t)(KV_BASE_B + st * KV_STG_B + 2*KV_TILE_B) + offA;

        // ---- S = Qn Kn^T, 3-pass ----
        float s[8][4];
        #pragma unroll
        for (int nt = 0; nt < 8; ++nt)
            #pragma unroll
            for (int j = 0; j < 4; ++j) s[nt][j] = 0.f;

        #pragma unroll
        for (int ks = 0; ks < 8; ++ks) {
            const uint32_t cb = (uint32_t)(ks * 32);
            uint32_t ah[4], al[4], bh2[8][2], bl2[8][2];
            LDSM4(ah[0], ah[1], ah[2], ah[3], qBaseH + cb);
            LDSM4(al[0], al[1], al[2], al[3], qBaseL + cb);
            #pragma unroll
            for (int p = 0; p < 4; ++p) {
                LDSM4(bh2[2*p][0], bh2[2*p][1], bh2[2*p+1][0], bh2[2*p+1][1],
                      kBaseH + (uint32_t)(p * 16 * 272) + cb);
                LDSM4(bl2[2*p][0], bl2[2*p][1], bl2[2*p+1][0], bl2[2*p+1][1],
                      kBaseL + (uint32_t)(p * 16 * 272) + cb);
            }
            #pragma unroll
            for (int nt = 0; nt < 8; ++nt) {
                MMA(s[nt], ah, bh2[nt]);
                MMA(s[nt], ah, bl2[nt]);
                MMA(s[nt], al, bh2[nt]);
            }
        }

        // ---- online softmax ----
        float mx0 = -1e30f, mx1 = -1e30f;
        #pragma unroll
        for (int nt = 0; nt < 8; ++nt) {
            mx0 = fmaxf(mx0, fmaxf(s[nt][0], s[nt][1]));
            mx1 = fmaxf(mx1, fmaxf(s[nt][2], s[nt][3]));
        }
        mx0 = fmaxf(mx0, __shfl_xor_sync(0xffffffffu, mx0, 1));
        mx0 = fmaxf(mx0, __shfl_xor_sync(0xffffffffu, mx0, 2));
        mx1 = fmaxf(mx1, __shfl_xor_sync(0xffffffffu, mx1, 1));
        mx1 = fmaxf(mx1, __shfl_xor_sync(0xffffffffu, mx1, 2));
        const float mn0 = fmaxf(m0, mx0), mn1 = fmaxf(m1, mx1);
        const float corr0 = __expf(m0 - mn0), corr1 = __expf(m1 - mn1);
        m0 = mn0; m1 = mn1;

        uint32_t ph[8][2], pl[8][2];
        float rs0 = 0.f, rs1 = 0.f;
        #pragma unroll
        for (int nt = 0; nt < 8; ++nt) {
            float p0 = __expf(s[nt][0] - mn0);
            float p1 = __expf(s[nt][1] - mn0);
            float p2 = __expf(s[nt][2] - mn1);
            float p3 = __expf(s[nt][3] - mn1);
            rs0 += p0 + p1; rs1 += p2 + p3;
            __half2 h01, h23, lo01, lo23;
            h01.x = __float2half_rn(p0); h01.y = __float2half_rn(p1);
            h23.x = __float2half_rn(p2); h23.y = __float2half_rn(p3);
            lo01.x = __float2half_rn(p0 - __half2float(h01.x));
            lo01.y = __float2half_rn(p1 - __half2float(h01.y));
            lo23.x = __float2half_rn(p2 - __half2float(h23.x));
            lo23.y = __float2half_rn(p3 - __half2float(h23.y));
            ph[nt][0] = *(uint32_t*)&h01;  ph[nt][1] = *(uint32_t*)&h23;
            pl[nt][0] = *(uint32_t*)&lo01; pl[nt][1] = *(uint32_t*)&lo23;
        }
        rs0 += __shfl_xor_sync(0xffffffffu, rs0, 1);
        rs0 += __shfl_xor_sync(0xffffffffu, rs0, 2);
        rs1 += __shfl_xor_sync(0xffffffffu, rs1, 1);
        rs1 += __shfl_xor_sync(0xffffffffu, rs1, 2);
        l0 = l0 * corr0 + rs0;
        l1 = l1 * corr1 + rs1;
        #pragma unroll
        for (int nt = 0; nt < 16; ++nt) {
            O[nt][0] *= corr0; O[nt][1] *= corr0;
            O[nt][2] *= corr1; O[nt][3] *= corr1;
        }

        // ---- O += (Ph+Pl) Vh ----
        #pragma unroll
        for (int ks = 0; ks < 4; ++ks) {
            uint32_t a_h[4] = { ph[2*ks][0], ph[2*ks][1], ph[2*ks+1][0], ph[2*ks+1][1] };
            uint32_t a_l[4] = { pl[2*ks][0], pl[2*ks][1], pl[2*ks+1][0], pl[2*ks+1][1] };
            const uint32_t krow = (uint32_t)(ks * 16 * 272);
            #pragma unroll
            for (int ntp = 0; ntp < 8; ++ntp) {
                uint32_t vh0, vh1, vh2, vh3;
                LDSM4T(vh0, vh1, vh2, vh3, vBaseH + krow + (uint32_t)(ntp * 32));
                uint32_t b0[2] = { vh0, vh1 }, b1[2] = { vh2, vh3 };
                MMA(O[2*ntp],   a_h, b0);
                MMA(O[2*ntp],   a_l, b0);
                MMA(O[2*ntp+1], a_h, b1);
                MMA(O[2*ntp+1], a_l, b1);
            }
        }
        asm volatile("cp.async.wait_group 0;" ::: "memory");
        __syncthreads();
    }

    // ---- epilogue: O/l -> z fp16 hi/lo ----
    const float inv0 = 1.f / l0, inv1 = 1.f / l1;
    const size_t r0g = qmbase + wid * 16 + l4;
    const size_t r1g = r0g + 8;
    #pragma unroll
    for (int nt = 0; nt < 16; ++nt) {
        const int col = colbase + nt * 8 + 2 * l3;
        const float o0 = O[nt][0] * inv0, o1 = O[nt][1] * inv0;
        const float o2 = O[nt][2] * inv1, o3 = O[nt][3] * inv1;
        __half2 h01, h23, lo01, lo23;
        h01.x = __float2half_rn(o0); h01.y = __float2half_rn(o1);
        h23.x = __float2half_rn(o2); h23.y = __float2half_rn(o3);
        lo01.x = __float2half_rn(o0 - __half2float(h01.x));
        lo01.y = __float2half_rn(o1 - __half2float(h01.y));
        lo23.x = __float2half_rn(o2 - __half2float(h23.x));
        lo23.y = __float2half_rn(o3 - __half2float(h23.y));
        *(uint32_t*)&g_zh[r0g * D_MODEL + col] = *(uint32_t*)&h01;
        *(uint32_t*)&g_zl[r0g * D_MODEL + col] = *(uint32_t*)&lo01;
        *(uint32_t*)&g_zh[r1g * D_MODEL + col] = *(uint32_t*)&h23;
        *(uint32_t*)&g_zl[r1g * D_MODEL + col] = *(uint32_t*)&lo23;
    }
}

// -----------------------------------------------------------------------------
extern "C" void kernel_launch(void* const* d_in, const int* in_sizes, int n_in,
                              void* d_out, int out_size)
{
    const float* x     = (const float*)d_in[0];
    const float* W_qkv = (const float*)d_in[1];
    const float* b_qkv = (const float*)d_in[2];
    const float* W_o   = (const float*)d_in[3];
    const float* b_o   = (const float*)d_in[4];
    const float* wq    = (const float*)d_in[5];
    const float* wk    = (const float*)d_in[6];

    float* out   = (float*)d_out;
    float* k_out = out   + (size_t)M_TOT * D_MODEL;
    float* v_out = k_out + (size_t)M_TOT * D_MODEL;

    __half *xh, *xl, *wqh, *wql, *woh, *zh, *zl;
    cudaGetSymbolAddress((void**)&xh,  g_xh);
    cudaGetSymbolAddress((void**)&xl,  g_xl);
    cudaGetSymbolAddress((void**)&wqh, g_wqkvh);
    cudaGetSymbolAddress((void**)&wql, g_wqkvl);
    cudaGetSymbolAddress((void**)&woh, g_woh);
    cudaGetSymbolAddress((void**)&zh,  g_zh);
    cudaGetSymbolAddress((void**)&zl,  g_zl);

    static bool attr_set = false;
    if (!attr_set) {
        cudaFuncSetAttribute(gemm_tc, cudaFuncAttributeMaxDynamicSharedMemorySize, GEMM_SMEM);
        cudaFuncSetAttribute(attn_tc, cudaFuncAttributeMaxDynamicSharedMemorySize, ATT_SMEM);
        attr_set = true;
    }

    // 0) operand conversion
    conv_split<<<(M_TOT*D_MODEL/4 + 255)/256, 256>>>(x, xh, xl, M_TOT*D_MODEL/4);
    conv_split<<<(NQKV*D_MODEL/4 + 255)/256, 256>>>(W_qkv, wqh, wql, NQKV*D_MODEL/4);
    conv_hi<<<(D_MODEL*D_MODEL/4 + 255)/256, 256>>>(W_o, woh, D_MODEL*D_MODEL/4);

    // 1) qkv GEMM with fused rms-norm epilogue (q,k cols 3-pass; v cols 2-pass)
    gemm_tc<<<dim3(NQKV/128, M_TOT/128), 256, GEMM_SMEM>>>(
        xh, xl, wqh, wql, b_qkv, nullptr, NQKV, D_MODEL, 2*D_MODEL, 1,
        k_out, v_out, wq, wk);

    // 2) attention -> g_zh/g_zl
    attn_tc<<<dim3(SEQ/128, BATCH*N_HEADS), 256, ATT_SMEM>>>();

    // 3) out = z @ W_o^T + b_o   (2-pass)
    gemm_tc<<<dim3(D_MODEL/128, M_TOT/128), 256, GEMM_SMEM>>>(
        zh, zl, woh, woh, b_o, out, D_MODEL, D_MODEL, 0, 0,
        nullptr, nullptr, nullptr, nullptr);
}

// round 14
// speedup vs baseline: 4.4403x; 1.0161x over previous
#include <cuda_runtime.h>
#include <cuda_fp16.h>
#include <math.h>
#include <stdint.h>

#define D_MODEL 2048
#define N_HEADS 16
#define D_HEAD  128
#define BATCH   2
#define SEQ     2048
#define M_TOT   (BATCH*SEQ)      /* 4096 */
#define NQKV    (3*D_MODEL)      /* 6144 */
#define EPSF    1e-6f

// ---------------- scratch (device globals; no allocs allowed) ----------------
__device__ __half g_xh[(size_t)M_TOT * D_MODEL];
__device__ __half g_xl[(size_t)M_TOT * D_MODEL];
__device__ __half g_wqkvh[(size_t)NQKV * D_MODEL];
__device__ __half g_wqkvl[(size_t)NQKV * D_MODEL];
__device__ __half g_woh[(size_t)D_MODEL * D_MODEL];
__device__ __half g_zh[(size_t)M_TOT * D_MODEL];
__device__ __half g_zl[(size_t)M_TOT * D_MODEL];

__device__ __half g_qh[(size_t)M_TOT * D_MODEL];
__device__ __half g_ql[(size_t)M_TOT * D_MODEL];
__device__ __half g_kh[(size_t)M_TOT * D_MODEL];
__device__ __half g_kl[(size_t)M_TOT * D_MODEL];
__device__ __half g_vh[(size_t)M_TOT * D_MODEL];

// ---------------- helpers ----------------------------------------------------
__device__ __forceinline__ uint32_t smem_u32(const void* p) {
    uint32_t a;
    asm("{ .reg .u64 t; cvta.to.shared.u64 t, %1; cvt.u32.u64 %0, t; }"
        : "=r"(a) : "l"(p));
    return a;
}

#define MMA(c, a, b) \
    asm volatile("mma.sync.aligned.m16n8k16.row.col.f32.f16.f16.f32 " \
                 "{%0,%1,%2,%3},{%4,%5,%6,%7},{%8,%9},{%0,%1,%2,%3};" \
                 : "+f"((c)[0]), "+f"((c)[1]), "+f"((c)[2]), "+f"((c)[3]) \
                 : "r"((a)[0]), "r"((a)[1]), "r"((a)[2]), "r"((a)[3]), \
                   "r"((b)[0]), "r"((b)[1]))

#define CPA16(dst, src) \
    asm volatile("cp.async.cg.shared.global [%0], [%1], 16;" :: "r"(dst), "l"(src))

#define LDSM4(r0_, r1_, r2_, r3_, a_) \
    asm volatile("ldmatrix.sync.aligned.m8n8.x4.shared.b16 {%0,%1,%2,%3},[%4];" \
                 : "=r"(r0_), "=r"(r1_), "=r"(r2_), "=r"(r3_) : "r"(a_))

#define LDSM4T(r0_, r1_, r2_, r3_, a_) \
    asm volatile("ldmatrix.sync.aligned.m8n8.x4.trans.shared.b16 {%0,%1,%2,%3},[%4];" \
                 : "=r"(r0_), "=r"(r1_), "=r"(r2_), "=r"(r3_) : "r"(a_))

// ---------------- fused fp32 -> fp16 conversion (one launch) -----------------
#define N4X (M_TOT*D_MODEL/4)          /* 2097152 -> 8192 blocks */
#define N4W (NQKV*D_MODEL/4)           /* 3145728 -> 12288 blocks */
#define N4O (D_MODEL*D_MODEL/4)        /* 1048576 -> 4096 blocks  */
#define BX  (N4X/256)
#define BW  (N4W/256)
#define BO  (N4O/256)

__global__ __launch_bounds__(256) void conv_all(
    const float* __restrict__ x, const float* __restrict__ wqkv,
    const float* __restrict__ wo)
{
    const int bid = blockIdx.x;
    const float* src;
    __half *hi, *lo;
    int i;
    if (bid < BX) {
        i = bid * 256 + threadIdx.x; src = x; hi = g_xh; lo = g_xl;
    } else if (bid < BX + BW) {
        i = (bid - BX) * 256 + threadIdx.x; src = wqkv; hi = g_wqkvh; lo = g_wqkvl;
    } else {
        i = (bid - BX - BW) * 256 + threadIdx.x; src = wo; hi = g_woh; lo = nullptr;
    }
    float4 v = ((const float4*)src)[i];
    __half2 h01, h23;
    h01.x = __float2half_rn(v.x); h01.y = __float2half_rn(v.y);
    h23.x = __float2half_rn(v.z); h23.y = __float2half_rn(v.w);
    ((__half2*)hi)[i*2]   = h01;
    ((__half2*)hi)[i*2+1] = h23;
    if (lo) {
        __half2 l01, l23;
        l01.x = __float2half_rn(v.x - __half2float(h01.x));
        l01.y = __float2half_rn(v.y - __half2float(h01.y));
        l23.x = __float2half_rn(v.z - __half2float(h23.x));
        l23.y = __float2half_rn(v.w - __half2float(h23.y));
        ((__half2*)lo)[i*2]   = l01;
        ((__half2*)lo)[i*2+1] = l23;
    }
}

// ---------------- HMMA split-fp16 GEMM, optional fused rms-norm epilogue -----
// C[M,N] = A[M,K]*B[N,K]^T + bias. bn < n3 -> 3-pass, else 2-pass.
// fuse=1 (qkv): each 128-col tile is one head; epilogue does rms-norm and
// writes q/k/v operands + k_out/v_out instead of C.
#define TILE_E 5120
#define STG_E  (4*TILE_E)
#define GEMM_SMEM (2*STG_E*2)    /* 81920 B */

__global__ __launch_bounds__(256, 2) void gemm_tc(
    const __half* __restrict__ pAh, const __half* __restrict__ pAl,
    const __half* __restrict__ pBh, const __half* __restrict__ pBl,
    const float* __restrict__ bias, float* __restrict__ C,
    int N, int K, int n3, int fuse,
    float* __restrict__ k_out, float* __restrict__ v_out,
    const float* __restrict__ wq, const float* __restrict__ wk)
{
    extern __shared__ __half sm[];
    const int tid = threadIdx.x, lane = tid & 31, wid = tid >> 5;
    const int wm = wid >> 1, wn = wid & 1;
    const int bm = blockIdx.y * 128, bn = blockIdx.x * 128;
    const bool three = (bn < n3);
    const uint32_t smb = smem_u32(sm);

    const int rr = lane & 7, sub = lane >> 3;
    const int l3 = lane & 3, l4 = lane >> 2;
    const uint32_t offA = (uint32_t)((rr + (sub & 1) * 8) * 80 + (sub >> 1) * 16);
    const uint32_t offB = (uint32_t)((rr + (sub >> 1) * 8) * 80 + (sub & 1) * 16);

    float acc[2][8][4];
    #pragma unroll
    for (int mt = 0; mt < 2; ++mt)
        #pragma unroll
        for (int nt = 0; nt < 8; ++nt)
            #pragma unroll
            for (int j = 0; j < 4; ++j) acc[mt][nt][j] = 0.f;

    const int nch = K / 32;
    const __half* srcs[4] = {
        pAh + (size_t)bm * K, pAl + (size_t)bm * K,
        pBh + (size_t)bn * K, pBl + (size_t)bn * K };
    const int ntl = three ? 4 : 3;

    const int lrow = tid >> 2, lcc = tid & 3;
    const int lrow2 = (tid + 256) >> 2;

    #define ISSUE(st, ch) do {                                             \
        const int _k0 = (ch) * 32;                                         \
        for (int _t = 0; _t < ntl; ++_t) {                                 \
            const __half* _s0 = srcs[_t] + _k0 + lcc * 8;                  \
            uint32_t _d0 = smb + (uint32_t)(((st)*4 + _t) * (TILE_E*2));   \
            const void* _sp1 = _s0 + (size_t)lrow * K;                     \
            uint32_t _dp1 = _d0 + (uint32_t)(lrow * 80 + lcc * 16);        \
            CPA16(_dp1, _sp1);                                             \
            const void* _sp2 = _s0 + (size_t)lrow2 * K;                    \
            uint32_t _dp2 = _d0 + (uint32_t)(lrow2 * 80 + lcc * 16);       \
            CPA16(_dp2, _sp2);                                             \
        }                                                                  \
        asm volatile("cp.async.commit_group;" ::: "memory");               \
    } while (0)

    // one k16 sub-step: loads fragments at column offset cb and does the MMAs
    #define K16_BLOCK(cb_) do {                                            \
        const uint32_t cb = (uint32_t)(cb_);                               \
        uint32_t ah[2][4], al[2][4], bh[8][2], bl[8][2];                   \
        _Pragma("unroll")                                                  \
        for (int mt = 0; mt < 2; ++mt) {                                   \
            LDSM4(ah[mt][0], ah[mt][1], ah[mt][2], ah[mt][3],              \
                  aBase + (uint32_t)(mt * 1280) + cb);                     \
            LDSM4(al[mt][0], al[mt][1], al[mt][2], al[mt][3],              \
                  aBase + (uint32_t)(TILE_E * 2 + mt * 1280) + cb);        \
        }                                                                  \
        _Pragma("unroll")                                                  \
        for (int p = 0; p < 4; ++p)                                        \
            LDSM4(bh[2*p][0], bh[2*p][1], bh[2*p+1][0], bh[2*p+1][1],      \
                  bBase + (uint32_t)(p * 1280) + cb);                      \
        if (three) {                                                       \
            _Pragma("unroll")                                              \
            for (int p = 0; p < 4; ++p)                                    \
                LDSM4(bl[2*p][0], bl[2*p][1], bl[2*p+1][0], bl[2*p+1][1],  \
                      bBase + (uint32_t)(TILE_E * 2 + p * 1280) + cb);     \
        }                                                                  \
        _Pragma("unroll")                                                  \
        for (int mt = 0; mt < 2; ++mt)                                     \
            _Pragma("unroll")                                              \
            for (int nt = 0; nt < 8; ++nt) {                               \
                MMA(acc[mt][nt], ah[mt], bh[nt]);                          \
                MMA(acc[mt][nt], al[mt], bh[nt]);                          \
            }                                                              \
        if (three) {                                                       \
            _Pragma("unroll")                                              \
            for (int mt = 0; mt < 2; ++mt)                                 \
                _Pragma("unroll")                                          \
                for (int nt = 0; nt < 8; ++nt)                             \
                    MMA(acc[mt][nt], ah[mt], bl[nt]);                      \
        }                                                                  \
    } while (0)

    ISSUE(0, 0);

    for (int ch = 0; ch < nch; ++ch) {
        const int st = ch & 1;
        asm volatile("cp.async.wait_group 0;" ::: "memory");
        __syncthreads();

        const uint32_t stbase = smb + (uint32_t)(st * (STG_E * 2));
        const uint32_t aBase = stbase + (uint32_t)(wm * 32 * 80) + offA;
        const uint32_t bBase = stbase + (uint32_t)(2 * TILE_E * 2) +
                               (uint32_t)(wn * 64 * 80) + offB;

        K16_BLOCK(0);                       // compute starts immediately
        if (ch + 1 < nch) ISSUE(st ^ 1, ch + 1);   // prefetch off the critical path
        K16_BLOCK(32);
        // no trailing barrier: next iteration's top sync fences stage reuse
    }

    // ---- add bias ----
    #pragma unroll
    for (int mt = 0; mt < 2; ++mt)
        #pragma unroll
        for (int nt = 0; nt < 8; ++nt) {
            const int cbl = wn * 64 + nt * 8 + l3 * 2;
            const float b0 = bias[bn + cbl], b1 = bias[bn + cbl + 1];
            acc[mt][nt][0] += b0; acc[mt][nt][1] += b1;
            acc[mt][nt][2] += b0; acc[mt][nt][3] += b1;
        }

    if (!fuse) {
        #pragma unroll
        for (int mt = 0; mt < 2; ++mt) {
            const int r1 = bm + wm * 32 + mt * 16 + l4;
            const int r2 = r1 + 8;
            #pragma unroll
            for (int nt = 0; nt < 8; ++nt) {
                const int cbg = bn + wn * 64 + nt * 8 + l3 * 2;
                float2 o1, o2;
                o1.x = acc[mt][nt][0]; o1.y = acc[mt][nt][1];
                o2.x = acc[mt][nt][2]; o2.y = acc[mt][nt][3];
                *(float2*)&C[(size_t)r1 * N + cbg] = o1;
                *(float2*)&C[(size_t)r2 * N + cbg] = o2;
            }
        }
        return;
    }

    // ---- fused qkv epilogue: tile = one head ----
    const int kind = (bn < D_MODEL) ? 0 : (bn < 2*D_MODEL ? 1 : 2);

    if (kind == 2) {
        #pragma unroll
        for (int mt = 0; mt < 2; ++mt) {
            const int r1 = bm + wm * 32 + mt * 16 + l4;
            const int r2 = r1 + 8;
            #pragma unroll
            for (int nt = 0; nt < 8; ++nt) {
                const int col = (bn - 2*D_MODEL) + wn * 64 + nt * 8 + l3 * 2;
                float2 o1, o2;
                o1.x = acc[mt][nt][0]; o1.y = acc[mt][nt][1];
                o2.x = acc[mt][nt][2]; o2.y = acc[mt][nt][3];
                *(float2*)&v_out[(size_t)r1 * D_MODEL + col] = o1;
                *(float2*)&v_out[(size_t)r2 * D_MODEL + col] = o2;
                __half2 h1, h2;
                h1.x = __float2half_rn(o1.x); h1.y = __float2half_rn(o1.y);
                h2.x = __float2half_rn(o2.x); h2.y = __float2half_rn(o2.y);
                *(__half2*)&g_vh[(size_t)r1 * D_MODEL + col] = h1;
                *(__half2*)&g_vh[(size_t)r2 * D_MODEL + col] = h2;
            }
        }
        return;
    }

    // q or k: rms-norm across the tile's 128 cols
    __syncthreads();                    // mainloop has no trailing sync now
    float* rsum = (float*)sm;
    float ss[2][2] = {{0.f,0.f},{0.f,0.f}};
    #pragma unroll
    for (int mt = 0; mt < 2; ++mt)
        #pragma unroll
        for (int nt = 0; nt < 8; ++nt) {
            ss[mt][0] += acc[mt][nt][0]*acc[mt][nt][0] + acc[mt][nt][1]*acc[mt][nt][1];
            ss[mt][1] += acc[mt][nt][2]*acc[mt][nt][2] + acc[mt][nt][3]*acc[mt][nt][3];
        }
    #pragma unroll
    for (int mt = 0; mt < 2; ++mt)
        #pragma unroll
        for (int hf = 0; hf < 2; ++hf) {
            ss[mt][hf] += __shfl_xor_sync(0xffffffffu, ss[mt][hf], 1);
            ss[mt][hf] += __shfl_xor_sync(0xffffffffu, ss[mt][hf], 2);
        }
    if (l3 == 0) {
        #pragma unroll
        for (int mt = 0; mt < 2; ++mt) {
            rsum[wn*128 + wm*32 + mt*16 + l4]     = ss[mt][0];
            rsum[wn*128 + wm*32 + mt*16 + l4 + 8] = ss[mt][1];
        }
    }
    __syncthreads();

    const float* wv = (kind == 0) ? wq : wk;
    __half* dst_h = (kind == 0) ? g_qh : g_kh;
    __half* dst_l = (kind == 0) ? g_ql : g_kl;
    const int colbase = (kind == 0) ? bn : bn - D_MODEL;

    #pragma unroll
    for (int mt = 0; mt < 2; ++mt) {
        const int rl1 = wm*32 + mt*16 + l4;
        const int rl2 = rl1 + 8;
        const float fac1 = rsqrtf((rsum[rl1] + rsum[128 + rl1]) * (1.f/128.f) + EPSF);
        const float fac2 = rsqrtf((rsum[rl2] + rsum[128 + rl2]) * (1.f/128.f) + EPSF);
        const int r1 = bm + rl1, r2 = bm + rl2;
        #pragma unroll
        for (int nt = 0; nt < 8; ++nt) {
            const int cbl = wn * 64 + nt * 8 + l3 * 2;
            const int col = colbase + cbl;
            if (kind == 1) {
                float2 o1, o2;
                o1.x = acc[mt][nt][0]; o1.y = acc[mt][nt][1];
                o2.x = acc[mt][nt][2]; o2.y = acc[mt][nt][3];
                *(float2*)&k_out[(size_t)r1 * D_MODEL + col] = o1;
                *(float2*)&k_out[(size_t)r2 * D_MODEL + col] = o2;
            }
            const float w0 = wv[cbl], w1 = wv[cbl + 1];
            const float n0 = acc[mt][nt][0] * fac1 * w0;
            const float n1 = acc[mt][nt][1] * fac1 * w1;
            const float n2 = acc[mt][nt][2] * fac2 * w0;
            const float n3v = acc[mt][nt][3] * fac2 * w1;
            __half2 h1, h2, lo1, lo2;
            h1.x = __float2half_rn(n0);  h1.y = __float2half_rn(n1);
            h2.x = __float2half_rn(n2);  h2.y = __float2half_rn(n3v);
            lo1.x = __float2half_rn(n0 - __half2float(h1.x));
            lo1.y = __float2half_rn(n1 - __half2float(h1.y));
            lo2.x = __float2half_rn(n2 - __half2float(h2.x));
            lo2.y = __float2half_rn(n3v - __half2float(h2.y));
            *(__half2*)&dst_h[(size_t)r1 * D_MODEL + col] = h1;
            *(__half2*)&dst_l[(size_t)r1 * D_MODEL + col] = lo1;
            *(__half2*)&dst_h[(size_t)r2 * D_MODEL + col] = h2;
            *(__half2*)&dst_l[(size_t)r2 * D_MODEL + col] = lo2;
        }
    }
}

// --------------- flash attention: BQ=128, double-buffered K/V ----------------
#define AT_STRIDE 136
#define KV_TILE_B (64*AT_STRIDE*2)    /* 17408 B */
#define QT_TILE_B (128*AT_STRIDE*2)   /* 34816 B */
#define KV_STG_B  (3*KV_TILE_B)       /* 52224 B */
#define KV_BASE_B (2*QT_TILE_B)       /* 69632 B */
#define ATT_SMEM  (KV_BASE_B + 2*KV_STG_B)  /* 174080 B */

__global__ __launch_bounds__(256, 1) void attn_tc()
{
    extern __shared__ __half smb[];
    const int tid = threadIdx.x, lane = tid & 31, wid = tid >> 5;
    const int l3 = lane & 3, l4 = lane >> 2;
    const int rr = lane & 7, sub = lane >> 3;
    const int qt = blockIdx.x;          // 0..15
    const int bh = blockIdx.y;          // 0..31
    const int b = bh >> 4, h = bh & 15;
    const size_t qmbase = (size_t)b * SEQ + qt * 128;
    const size_t kmbase = (size_t)b * SEQ;
    const int colbase = h * D_HEAD;

    const uint32_t smbase = smem_u32(smb);

    const uint32_t offA  = (uint32_t)((rr + (sub & 1) * 8) * 272 + (sub >> 1) * 16);
    const uint32_t offB  = (uint32_t)((rr + (sub >> 1) * 8) * 272 + (sub & 1) * 16);

    // ---- load Q tile (hi+lo, 128 rows) ----
    {
        const __half* gq = g_qh + qmbase * D_MODEL + colbase;
        const __half* gl = g_ql + qmbase * D_MODEL + colbase;
        #pragma unroll
        for (int it = 0; it < 8; ++it) {
            const int c = it * 256 + tid;
            const int row = c >> 4, c16 = c & 15;
            const uint32_t dst = smbase + (uint32_t)(row * 272 + c16 * 16);
            CPA16(dst,             gq + (size_t)row * D_MODEL + c16 * 8);
            CPA16(dst + QT_TILE_B, gl + (size_t)row * D_MODEL + c16 * 8);
        }
        asm volatile("cp.async.commit_group;" ::: "memory");
    }
    // ---- load KV stage 0 ----
    {
        const size_t mrow = kmbase * D_MODEL + colbase;
        #pragma unroll
        for (int it = 0; it < 4; ++it) {
            const int c = it * 256 + tid;
            const int row = c >> 4, c16 = c & 15;
            const size_t so = (size_t)row * D_MODEL + c16 * 8;
            const uint32_t dst = smbase + (uint32_t)(KV_BASE_B + row * 272 + c16 * 16);
            CPA16(dst,                 g_kh + mrow + so);
            CPA16(dst + KV_TILE_B,     g_kl + mrow + so);
            CPA16(dst + 2*KV_TILE_B,   g_vh + mrow + so);
        }
        asm volatile("cp.async.commit_group;" ::: "memory");
    }
    asm volatile("cp.async.wait_group 0;" ::: "memory");
    __syncthreads();

    float O[16][4];
    #pragma unroll
    for (int nt = 0; nt < 16; ++nt)
        #pragma unroll
        for (int j = 0; j < 4; ++j) O[nt][j] = 0.f;
    float m0 = -1e30f, m1 = -1e30f, l0 = 0.f, l1 = 0.f;

    const uint32_t qBaseH = smbase + (uint32_t)(wid * 16 * 272) + offA;
    const uint32_t qBaseL = qBaseH + QT_TILE_B;

    for (int kt = 0; kt < SEQ/64; ++kt) {
        const int st = kt & 1;
        const uint32_t kBaseH = smbase + (uint32_t)(KV_BASE_B + st * KV_STG_B) + offB;
        const uint32_t kBaseL = kBaseH + KV_TILE_B;
        const uint32_t vBaseH = smbase + (uint32_t)(KV_BASE_B + st * KV_STG_B + 2*KV_TILE_B) + offA;

        // ---- S = Qn Kn^T, 3-pass (starts immediately after barrier) ----
        float s[8][4];
        #pragma unroll
        for (int nt = 0; nt < 8; ++nt)
            #pragma unroll
            for (int j = 0; j < 4; ++j) s[nt][j] = 0.f;

        #pragma unroll
        for (int ks = 0; ks < 8; ++ks) {
            const uint32_t cb = (uint32_t)(ks * 32);
            uint32_t ah[4], al[4], bh2[8][2], bl2[8][2];
            LDSM4(ah[0], ah[1], ah[2], ah[3], qBaseH + cb);
            LDSM4(al[0], al[1], al[2], al[3], qBaseL + cb);
            #pragma unroll
            for (int p = 0; p < 4; ++p) {
                LDSM4(bh2[2*p][0], bh2[2*p][1], bh2[2*p+1][0], bh2[2*p+1][1],
                      kBaseH + (uint32_t)(p * 16 * 272) + cb);
                LDSM4(bl2[2*p][0], bl2[2*p][1], bl2[2*p+1][0], bl2[2*p+1][1],
                      kBaseL + (uint32_t)(p * 16 * 272) + cb);
            }
            #pragma unroll
            for (int nt = 0; nt < 8; ++nt) {
                MMA(s[nt], ah, bh2[nt]);
                MMA(s[nt], ah, bl2[nt]);
                MMA(s[nt], al, bh2[nt]);
            }
        }

        // ---- prefetch next KV (off the MMA critical path) ----
        if (kt + 1 < SEQ/64) {
            const size_t mrow = (kmbase + (kt + 1) * 64) * D_MODEL + colbase;
            const uint32_t sb = (uint32_t)(KV_BASE_B + (st ^ 1) * KV_STG_B);
            #pragma unroll
            for (int it = 0; it < 4; ++it) {
                const int c = it * 256 + tid;
                const int row = c >> 4, c16 = c & 15;
                const size_t so = (size_t)row * D_MODEL + c16 * 8;
                const uint32_t dst = smbase + sb + (uint32_t)(row * 272 + c16 * 16);
                CPA16(dst,               g_kh + mrow + so);
                CPA16(dst + KV_TILE_B,   g_kl + mrow + so);
                CPA16(dst + 2*KV_TILE_B, g_vh + mrow + so);
            }
            asm volatile("cp.async.commit_group;" ::: "memory");
        }

        // ---- online softmax ----
        float mx0 = -1e30f, mx1 = -1e30f;
        #pragma unroll
        for (int nt = 0; nt < 8; ++nt) {
            mx0 = fmaxf(mx0, fmaxf(s[nt][0], s[nt][1]));
            mx1 = fmaxf(mx1, fmaxf(s[nt][2], s[nt][3]));
        }
        mx0 = fmaxf(mx0, __shfl_xor_sync(0xffffffffu, mx0, 1));
        mx0 = fmaxf(mx0, __shfl_xor_sync(0xffffffffu, mx0, 2));
        mx1 = fmaxf(mx1, __shfl_xor_sync(0xffffffffu, mx1, 1));
        mx1 = fmaxf(mx1, __shfl_xor_sync(0xffffffffu, mx1, 2));
        const float mn0 = fmaxf(m0, mx0), mn1 = fmaxf(m1, mx1);
        const float corr0 = __expf(m0 - mn0), corr1 = __expf(m1 - mn1);
        m0 = mn0; m1 = mn1;

        uint32_t ph[8][2], pl[8][2];
        float rs0 = 0.f, rs1 = 0.f;
        #pragma unroll
        for (int nt = 0; nt < 8; ++nt) {
            float p0 = __expf(s[nt][0] - mn0);
            float p1 = __expf(s[nt][1] - mn0);
            float p2 = __expf(s[nt][2] - mn1);
            float p3 = __expf(s[nt][3] - mn1);
            rs0 += p0 + p1; rs1 += p2 + p3;
            __half2 h01, h23, lo01, lo23;
            h01.x = __float2half_rn(p0); h01.y = __float2half_rn(p1);
            h23.x = __float2half_rn(p2); h23.y = __float2half_rn(p3);
            lo01.x = __float2half_rn(p0 - __half2float(h01.x));
            lo01.y = __float2half_rn(p1 - __half2float(h01.y));
            lo23.x = __float2half_rn(p2 - __half2float(h23.x));
            lo23.y = __float2half_rn(p3 - __half2float(h23.y));
            ph[nt][0] = *(uint32_t*)&h01;  ph[nt][1] = *(uint32_t*)&h23;
            pl[nt][0] = *(uint32_t*)&lo01; pl[nt][1] = *(uint32_t*)&lo23;
        }
        rs0 += __shfl_xor_sync(0xffffffffu, rs0, 1);
        rs0 += __shfl_xor_sync(0xffffffffu, rs0, 2);
        rs1 += __shfl_xor_sync(0xffffffffu, rs1, 1);
        rs1 += __shfl_xor_sync(0xffffffffu, rs1, 2);
        l0 = l0 * corr0 + rs0;
        l1 = l1 * corr1 + rs1;
        #pragma unroll
        for (int nt = 0; nt < 16; ++nt) {
            O[nt][0] *= corr0; O[nt][1] *= corr0;
            O[nt][2] *= corr1; O[nt][3] *= corr1;
        }

        // ---- O += (Ph+Pl) Vh ----
        #pragma unroll
        for (int ks = 0; ks < 4; ++ks) {
            uint32_t a_h[4] = { ph[2*ks][0], ph[2*ks][1], ph[2*ks+1][0], ph[2*ks+1][1] };
            uint32_t a_l[4] = { pl[2*ks][0], pl[2*ks][1], pl[2*ks+1][0], pl[2*ks+1][1] };
            const uint32_t krow = (uint32_t)(ks * 16 * 272);
            #pragma unroll
            for (int ntp = 0; ntp < 8; ++ntp) {
                uint32_t vh0, vh1, vh2, vh3;
                LDSM4T(vh0, vh1, vh2, vh3, vBaseH + krow + (uint32_t)(ntp * 32));
                uint32_t b0[2] = { vh0, vh1 }, b1[2] = { vh2, vh3 };
                MMA(O[2*ntp],   a_h, b0);
                MMA(O[2*ntp],   a_l, b0);
                MMA(O[2*ntp+1], a_h, b1);
                MMA(O[2*ntp+1], a_l, b1);
            }
        }
        asm volatile("cp.async.wait_group 0;" ::: "memory");
        __syncthreads();
    }

    // ---- epilogue: O/l -> z fp16 hi/lo ----
    const float inv0 = 1.f / l0, inv1 = 1.f / l1;
    const size_t r0g = qmbase + wid * 16 + l4;
    const size_t r1g = r0g + 8;
    #pragma unroll
    for (int nt = 0; nt < 16; ++nt) {
        const int col = colbase + nt * 8 + 2 * l3;
        const float o0 = O[nt][0] * inv0, o1 = O[nt][1] * inv0;
        const float o2 = O[nt][2] * inv1, o3 = O[nt][3] * inv1;
        __half2 h01, h23, lo01, lo23;
        h01.x = __float2half_rn(o0); h01.y = __float2half_rn(o1);
        h23.x = __float2half_rn(o2); h23.y = __float2half_rn(o3);
        lo01.x = __float2half_rn(o0 - __half2float(h01.x));
        lo01.y = __float2half_rn(o1 - __half2float(h01.y));
        lo23.x = __float2half_rn(o2 - __half2float(h23.x));
        lo23.y = __float2half_rn(o3 - __half2float(h23.y));
        *(uint32_t*)&g_zh[r0g * D_MODEL + col] = *(uint32_t*)&h01;
        *(uint32_t*)&g_zl[r0g * D_MODEL + col] = *(uint32_t*)&lo01;
        *(uint32_t*)&g_zh[r1g * D_MODEL + col] = *(uint32_t*)&h23;
        *(uint32_t*)&g_zl[r1g * D_MODEL + col] = *(uint32_t*)&lo23;
    }
}

// -----------------------------------------------------------------------------
extern "C" void kernel_launch(void* const* d_in, const int* in_sizes, int n_in,
                              void* d_out, int out_size)
{
    const float* x     = (const float*)d_in[0];
    const float* W_qkv = (const float*)d_in[1];
    const float* b_qkv = (const float*)d_in[2];
    const float* W_o   = (const float*)d_in[3];
    const float* b_o   = (const float*)d_in[4];
    const float* wq    = (const float*)d_in[5];
    const float* wk    = (const float*)d_in[6];

    float* out   = (float*)d_out;
    float* k_out = out   + (size_t)M_TOT * D_MODEL;
    float* v_out = k_out + (size_t)M_TOT * D_MODEL;

    __half *xh, *xl, *wqh, *wql, *woh, *zh, *zl;
    cudaGetSymbolAddress((void**)&xh,  g_xh);
    cudaGetSymbolAddress((void**)&xl,  g_xl);
    cudaGetSymbolAddress((void**)&wqh, g_wqkvh);
    cudaGetSymbolAddress((void**)&wql, g_wqkvl);
    cudaGetSymbolAddress((void**)&woh, g_woh);
    cudaGetSymbolAddress((void**)&zh,  g_zh);
    cudaGetSymbolAddress((void**)&zl,  g_zl);

    static bool attr_set = false;
    if (!attr_set) {
        cudaFuncSetAttribute(gemm_tc, cudaFuncAttributeMaxDynamicSharedMemorySize, GEMM_SMEM);
        cudaFuncSetAttribute(attn_tc, cudaFuncAttributeMaxDynamicSharedMemorySize, ATT_SMEM);
        attr_set = true;
    }

    // 0) all operand conversions in one launch
    conv_all<<<BX + BW + BO, 256>>>(x, W_qkv, W_o);

    // 1) qkv GEMM with fused rms-norm epilogue (q,k cols 3-pass; v cols 2-pass)
    gemm_tc<<<dim3(NQKV/128, M_TOT/128), 256, GEMM_SMEM>>>(
        xh, xl, wqh, wql, b_qkv, nullptr, NQKV, D_MODEL, 2*D_MODEL, 1,
        k_out, v_out, wq, wk);

    // 2) attention -> g_zh/g_zl
    attn_tc<<<dim3(SEQ/128, BATCH*N_HEADS), 256, ATT_SMEM>>>();

    // 3) out = z @ W_o^T + b_o   (2-pass)
    gemm_tc<<<dim3(D_MODEL/128, M_TOT/128), 256, GEMM_SMEM>>>(
        zh, zl, woh, woh, b_o, out, D_MODEL, D_MODEL, 0, 0,
        nullptr, nullptr, nullptr, nullptr);
}

// round 15
// speedup vs baseline: 4.5268x; 1.0195x over previous
#include <cuda_runtime.h>
#include <cuda_fp16.h>
#include <math.h>
#include <stdint.h>

#define D_MODEL 2048
#define N_HEADS 16
#define D_HEAD  128
#define BATCH   2
#define SEQ     2048
#define M_TOT   (BATCH*SEQ)      /* 4096 */
#define NQKV    (3*D_MODEL)      /* 6144 */
#define EPSF    1e-6f

// ---------------- scratch (device globals; no allocs allowed) ----------------
__device__ __half g_xh[(size_t)M_TOT * D_MODEL];
__device__ __half g_xl[(size_t)M_TOT * D_MODEL];
__device__ __half g_wqkvh[(size_t)NQKV * D_MODEL];
__device__ __half g_wqkvl[(size_t)NQKV * D_MODEL];
__device__ __half g_woh[(size_t)D_MODEL * D_MODEL];
__device__ __half g_zh[(size_t)M_TOT * D_MODEL];
__device__ __half g_zl[(size_t)M_TOT * D_MODEL];

__device__ __half g_qh[(size_t)M_TOT * D_MODEL];
__device__ __half g_ql[(size_t)M_TOT * D_MODEL];
__device__ __half g_kh[(size_t)M_TOT * D_MODEL];
__device__ __half g_kl[(size_t)M_TOT * D_MODEL];
__device__ __half g_vh[(size_t)M_TOT * D_MODEL];

// ---------------- helpers ----------------------------------------------------
__device__ __forceinline__ uint32_t smem_u32(const void* p) {
    uint32_t a;
    asm("{ .reg .u64 t; cvta.to.shared.u64 t, %1; cvt.u32.u64 %0, t; }"
        : "=r"(a) : "l"(p));
    return a;
}

#define MMA(c, a, b) \
    asm volatile("mma.sync.aligned.m16n8k16.row.col.f32.f16.f16.f32 " \
                 "{%0,%1,%2,%3},{%4,%5,%6,%7},{%8,%9},{%0,%1,%2,%3};" \
                 : "+f"((c)[0]), "+f"((c)[1]), "+f"((c)[2]), "+f"((c)[3]) \
                 : "r"((a)[0]), "r"((a)[1]), "r"((a)[2]), "r"((a)[3]), \
                   "r"((b)[0]), "r"((b)[1]))

#define CPA16(dst, src) \
    asm volatile("cp.async.cg.shared.global [%0], [%1], 16;" :: "r"(dst), "l"(src))

#define LDSM4(r0_, r1_, r2_, r3_, a_) \
    asm volatile("ldmatrix.sync.aligned.m8n8.x4.shared.b16 {%0,%1,%2,%3},[%4];" \
                 : "=r"(r0_), "=r"(r1_), "=r"(r2_), "=r"(r3_) : "r"(a_))

#define LDSM4T(r0_, r1_, r2_, r3_, a_) \
    asm volatile("ldmatrix.sync.aligned.m8n8.x4.trans.shared.b16 {%0,%1,%2,%3},[%4];" \
                 : "=r"(r0_), "=r"(r1_), "=r"(r2_), "=r"(r3_) : "r"(a_))

// ---------------- fused fp32 -> fp16 conversion (one launch, MLP=4) ----------
#define N4X (M_TOT*D_MODEL/4)
#define N4W (NQKV*D_MODEL/4)
#define N4O (D_MODEL*D_MODEL/4)
#define BX4 (N4X/1024)    /* 2048 blocks */
#define BW4 (N4W/1024)    /* 3072 blocks */
#define BO4 (N4O/1024)    /* 1024 blocks */

__global__ __launch_bounds__(256) void conv_all(
    const float* __restrict__ x, const float* __restrict__ wqkv,
    const float* __restrict__ wo)
{
    const int bid = blockIdx.x;
    const float* src;
    __half *hi, *lo;
    int base;
    if (bid < BX4) {
        base = bid * 1024; src = x; hi = g_xh; lo = g_xl;
    } else if (bid < BX4 + BW4) {
        base = (bid - BX4) * 1024; src = wqkv; hi = g_wqkvh; lo = g_wqkvl;
    } else {
        base = (bid - BX4 - BW4) * 1024; src = wo; hi = g_woh; lo = nullptr;
    }
    #pragma unroll
    for (int j = 0; j < 4; ++j) {
        const int i = base + j * 256 + threadIdx.x;
        float4 v = ((const float4*)src)[i];
        __half2 h01, h23;
        h01.x = __float2half_rn(v.x); h01.y = __float2half_rn(v.y);
        h23.x = __float2half_rn(v.z); h23.y = __float2half_rn(v.w);
        ((__half2*)hi)[i*2]   = h01;
        ((__half2*)hi)[i*2+1] = h23;
        if (lo) {
            __half2 l01, l23;
            l01.x = __float2half_rn(v.x - __half2float(h01.x));
            l01.y = __float2half_rn(v.y - __half2float(h01.y));
            l23.x = __float2half_rn(v.z - __half2float(h23.x));
            l23.y = __float2half_rn(v.w - __half2float(h23.y));
            ((__half2*)lo)[i*2]   = l01;
            ((__half2*)lo)[i*2+1] = l23;
        }
    }
}

// ---------------- HMMA split-fp16 GEMM (templated pipeline depth) ------------
// C[M,N] = A[M,K]*B[N,K]^T + bias. bn < n3 -> 3-pass, else 2-pass.
// fuse=1 (qkv): rms-norm epilogue writing q/k/v operands + k_out/v_out.
#define TILE_E 5120
#define GEMM_SMEM_QKV (2*4*TILE_E*2)   /* 81920 B */
#define GEMM_SMEM_OP  (3*3*TILE_E*2)   /* 92160 B */

template<int NST, int NTILES>
__global__ __launch_bounds__(256, 2) void gemm_tc(
    const __half* __restrict__ pAh, const __half* __restrict__ pAl,
    const __half* __restrict__ pBh, const __half* __restrict__ pBl,
    const float* __restrict__ bias, float* __restrict__ C,
    int N, int K, int n3, int fuse,
    float* __restrict__ k_out, float* __restrict__ v_out,
    const float* __restrict__ wq, const float* __restrict__ wk)
{
    extern __shared__ __half sm[];
    const int tid = threadIdx.x, lane = tid & 31, wid = tid >> 5;
    const int wm = wid >> 1, wn = wid & 1;
    const int bm = blockIdx.y * 128, bn = blockIdx.x * 128;
    const bool three = (bn < n3);
    const uint32_t smb = smem_u32(sm);

    const int rr = lane & 7, sub = lane >> 3;
    const int l3 = lane & 3, l4 = lane >> 2;
    const uint32_t offA = (uint32_t)((rr + (sub & 1) * 8) * 80 + (sub >> 1) * 16);
    const uint32_t offB = (uint32_t)((rr + (sub >> 1) * 8) * 80 + (sub & 1) * 16);

    float acc[2][8][4];
    #pragma unroll
    for (int mt = 0; mt < 2; ++mt)
        #pragma unroll
        for (int nt = 0; nt < 8; ++nt)
            #pragma unroll
            for (int j = 0; j < 4; ++j) acc[mt][nt][j] = 0.f;

    const int nch = K / 32;
    const __half* srcs[4] = {
        pAh + (size_t)bm * K, pAl + (size_t)bm * K,
        pBh + (size_t)bn * K, pBl + (size_t)bn * K };
    const int ntl = three ? 4 : 3;

    const int lrow = tid >> 2, lcc = tid & 3;
    const int lrow2 = (tid + 256) >> 2;

    #define ISSUE(st_, ch_) do {                                           \
        const int _k0 = (ch_) * 32;                                        \
        for (int _t = 0; _t < ntl; ++_t) {                                 \
            const __half* _s0 = srcs[_t] + _k0 + lcc * 8;                  \
            uint32_t _d0 = smb + (uint32_t)(((st_)*NTILES + _t) * (TILE_E*2)); \
            const void* _sp1 = _s0 + (size_t)lrow * K;                     \
            uint32_t _dp1 = _d0 + (uint32_t)(lrow * 80 + lcc * 16);        \
            CPA16(_dp1, _sp1);                                             \
            const void* _sp2 = _s0 + (size_t)lrow2 * K;                    \
            uint32_t _dp2 = _d0 + (uint32_t)(lrow2 * 80 + lcc * 16);       \
            CPA16(_dp2, _sp2);                                             \
        }                                                                  \
        asm volatile("cp.async.commit_group;" ::: "memory");               \
    } while (0)

    // one k16 sub-step; pass-reordered for acc ILP
    #define K16_BLOCK(cb_) do {                                            \
        const uint32_t cb = (uint32_t)(cb_);                               \
        uint32_t ah[2][4], al[2][4], bh[8][2], bl[8][2];                   \
        _Pragma("unroll")                                                  \
        for (int mt = 0; mt < 2; ++mt) {                                   \
            LDSM4(ah[mt][0], ah[mt][1], ah[mt][2], ah[mt][3],              \
                  aBase + (uint32_t)(mt * 1280) + cb);                     \
            LDSM4(al[mt][0], al[mt][1], al[mt][2], al[mt][3],              \
                  aBase + (uint32_t)(TILE_E * 2 + mt * 1280) + cb);        \
        }                                                                  \
        _Pragma("unroll")                                                  \
        for (int p = 0; p < 4; ++p)                                        \
            LDSM4(bh[2*p][0], bh[2*p][1], bh[2*p+1][0], bh[2*p+1][1],      \
                  bBase + (uint32_t)(p * 1280) + cb);                      \
        if (three) {                                                       \
            _Pragma("unroll")                                              \
            for (int p = 0; p < 4; ++p)                                    \
                LDSM4(bl[2*p][0], bl[2*p][1], bl[2*p+1][0], bl[2*p+1][1],  \
                      bBase + (uint32_t)(TILE_E * 2 + p * 1280) + cb);     \
        }                                                                  \
        _Pragma("unroll")                                                  \
        for (int mt = 0; mt < 2; ++mt)                                     \
            _Pragma("unroll")                                              \
            for (int nt = 0; nt < 8; ++nt)                                 \
                MMA(acc[mt][nt], ah[mt], bh[nt]);                          \
        _Pragma("unroll")                                                  \
        for (int mt = 0; mt < 2; ++mt)                                     \
            _Pragma("unroll")                                              \
            for (int nt = 0; nt < 8; ++nt)                                 \
                MMA(acc[mt][nt], al[mt], bh[nt]);                          \
        if (three) {                                                       \
            _Pragma("unroll")                                              \
            for (int mt = 0; mt < 2; ++mt)                                 \
                _Pragma("unroll")                                          \
                for (int nt = 0; nt < 8; ++nt)                             \
                    MMA(acc[mt][nt], ah[mt], bl[nt]);                      \
        }                                                                  \
    } while (0)

    ISSUE(0, 0);
    if (NST == 3 && nch > 1) ISSUE(1, 1);

    int st = 0;
    int ist = (NST - 1) % NST;   // stage that chunk ch+NST-1 lands in
    for (int ch = 0; ch < nch; ++ch) {
        if (NST == 2) {
            asm volatile("cp.async.wait_group 0;" ::: "memory");
        } else {
            if (ch + 1 < nch) asm volatile("cp.async.wait_group 1;" ::: "memory");
            else              asm volatile("cp.async.wait_group 0;" ::: "memory");
        }
        __syncthreads();

        const uint32_t stbase = smb + (uint32_t)(st * (NTILES * TILE_E * 2));
        const uint32_t aBase = stbase + (uint32_t)(wm * 32 * 80) + offA;
        const uint32_t bBase = stbase + (uint32_t)(2 * TILE_E * 2) +
                               (uint32_t)(wn * 64 * 80) + offB;

        K16_BLOCK(0);
        if (ch + NST - 1 < nch) ISSUE(ist, ch + NST - 1);
        K16_BLOCK(32);

        if (++st == NST) st = 0;
        if (++ist == NST) ist = 0;
    }

    // ---- add bias ----
    #pragma unroll
    for (int mt = 0; mt < 2; ++mt)
        #pragma unroll
        for (int nt = 0; nt < 8; ++nt) {
            const int cbl = wn * 64 + nt * 8 + l3 * 2;
            const float b0 = bias[bn + cbl], b1 = bias[bn + cbl + 1];
            acc[mt][nt][0] += b0; acc[mt][nt][1] += b1;
            acc[mt][nt][2] += b0; acc[mt][nt][3] += b1;
        }

    if (!fuse) {
        #pragma unroll
        for (int mt = 0; mt < 2; ++mt) {
            const int r1 = bm + wm * 32 + mt * 16 + l4;
            const int r2 = r1 + 8;
            #pragma unroll
            for (int nt = 0; nt < 8; ++nt) {
                const int cbg = bn + wn * 64 + nt * 8 + l3 * 2;
                float2 o1, o2;
                o1.x = acc[mt][nt][0]; o1.y = acc[mt][nt][1];
                o2.x = acc[mt][nt][2]; o2.y = acc[mt][nt][3];
                *(float2*)&C[(size_t)r1 * N + cbg] = o1;
                *(float2*)&C[(size_t)r2 * N + cbg] = o2;
            }
        }
        return;
    }

    // ---- fused qkv epilogue: tile = one head ----
    const int kind = (bn < D_MODEL) ? 0 : (bn < 2*D_MODEL ? 1 : 2);

    if (kind == 2) {
        #pragma unroll
        for (int mt = 0; mt < 2; ++mt) {
            const int r1 = bm + wm * 32 + mt * 16 + l4;
            const int r2 = r1 + 8;
            #pragma unroll
            for (int nt = 0; nt < 8; ++nt) {
                const int col = (bn - 2*D_MODEL) + wn * 64 + nt * 8 + l3 * 2;
                float2 o1, o2;
                o1.x = acc[mt][nt][0]; o1.y = acc[mt][nt][1];
                o2.x = acc[mt][nt][2]; o2.y = acc[mt][nt][3];
                *(float2*)&v_out[(size_t)r1 * D_MODEL + col] = o1;
                *(float2*)&v_out[(size_t)r2 * D_MODEL + col] = o2;
                __half2 h1, h2;
                h1.x = __float2half_rn(o1.x); h1.y = __float2half_rn(o1.y);
                h2.x = __float2half_rn(o2.x); h2.y = __float2half_rn(o2.y);
                *(__half2*)&g_vh[(size_t)r1 * D_MODEL + col] = h1;
                *(__half2*)&g_vh[(size_t)r2 * D_MODEL + col] = h2;
            }
        }
        return;
    }

    // q or k: rms-norm across the tile's 128 cols
    __syncthreads();
    float* rsum = (float*)sm;
    float ss[2][2] = {{0.f,0.f},{0.f,0.f}};
    #pragma unroll
    for (int mt = 0; mt < 2; ++mt)
        #pragma unroll
        for (int nt = 0; nt < 8; ++nt) {
            ss[mt][0] += acc[mt][nt][0]*acc[mt][nt][0] + acc[mt][nt][1]*acc[mt][nt][1];
            ss[mt][1] += acc[mt][nt][2]*acc[mt][nt][2] + acc[mt][nt][3]*acc[mt][nt][3];
        }
    #pragma unroll
    for (int mt = 0; mt < 2; ++mt)
        #pragma unroll
        for (int hf = 0; hf < 2; ++hf) {
            ss[mt][hf] += __shfl_xor_sync(0xffffffffu, ss[mt][hf], 1);
            ss[mt][hf] += __shfl_xor_sync(0xffffffffu, ss[mt][hf], 2);
        }
    if (l3 == 0) {
        #pragma unroll
        for (int mt = 0; mt < 2; ++mt) {
            rsum[wn*128 + wm*32 + mt*16 + l4]     = ss[mt][0];
            rsum[wn*128 + wm*32 + mt*16 + l4 + 8] = ss[mt][1];
        }
    }
    __syncthreads();

    const float* wv = (kind == 0) ? wq : wk;
    __half* dst_h = (kind == 0) ? g_qh : g_kh;
    __half* dst_l = (kind == 0) ? g_ql : g_kl;
    const int colbase = (kind == 0) ? bn : bn - D_MODEL;

    #pragma unroll
    for (int mt = 0; mt < 2; ++mt) {
        const int rl1 = wm*32 + mt*16 + l4;
        const int rl2 = rl1 + 8;
        const float fac1 = rsqrtf((rsum[rl1] + rsum[128 + rl1]) * (1.f/128.f) + EPSF);
        const float fac2 = rsqrtf((rsum[rl2] + rsum[128 + rl2]) * (1.f/128.f) + EPSF);
        const int r1 = bm + rl1, r2 = bm + rl2;
        #pragma unroll
        for (int nt = 0; nt < 8; ++nt) {
            const int cbl = wn * 64 + nt * 8 + l3 * 2;
            const int col = colbase + cbl;
            if (kind == 1) {
                float2 o1, o2;
                o1.x = acc[mt][nt][0]; o1.y = acc[mt][nt][1];
                o2.x = acc[mt][nt][2]; o2.y = acc[mt][nt][3];
                *(float2*)&k_out[(size_t)r1 * D_MODEL + col] = o1;
                *(float2*)&k_out[(size_t)r2 * D_MODEL + col] = o2;
            }
            const float w0 = wv[cbl], w1 = wv[cbl + 1];
            const float n0 = acc[mt][nt][0] * fac1 * w0;
            const float n1 = acc[mt][nt][1] * fac1 * w1;
            const float n2 = acc[mt][nt][2] * fac2 * w0;
            const float n3v = acc[mt][nt][3] * fac2 * w1;
            __half2 h1, h2, lo1, lo2;
            h1.x = __float2half_rn(n0);  h1.y = __float2half_rn(n1);
            h2.x = __float2half_rn(n2);  h2.y = __float2half_rn(n3v);
            lo1.x = __float2half_rn(n0 - __half2float(h1.x));
            lo1.y = __float2half_rn(n1 - __half2float(h1.y));
            lo2.x = __float2half_rn(n2 - __half2float(h2.x));
            lo2.y = __float2half_rn(n3v - __half2float(h2.y));
            *(__half2*)&dst_h[(size_t)r1 * D_MODEL + col] = h1;
            *(__half2*)&dst_l[(size_t)r1 * D_MODEL + col] = lo1;
            *(__half2*)&dst_h[(size_t)r2 * D_MODEL + col] = h2;
            *(__half2*)&dst_l[(size_t)r2 * D_MODEL + col] = lo2;
        }
    }
}

// --------------- flash attention: BQ=128, double-buffered K/V ----------------
#define AT_STRIDE 136
#define KV_TILE_B (64*AT_STRIDE*2)    /* 17408 B */
#define QT_TILE_B (128*AT_STRIDE*2)   /* 34816 B */
#define KV_STG_B  (3*KV_TILE_B)       /* 52224 B */
#define KV_BASE_B (2*QT_TILE_B)       /* 69632 B */
#define ATT_SMEM  (KV_BASE_B + 2*KV_STG_B)  /* 174080 B */

__global__ __launch_bounds__(256, 1) void attn_tc()
{
    extern __shared__ __half smb[];
    const int tid = threadIdx.x, lane = tid & 31, wid = tid >> 5;
    const int l3 = lane & 3, l4 = lane >> 2;
    const int rr = lane & 7, sub = lane >> 3;
    const int qt = blockIdx.x;
    const int bh = blockIdx.y;
    const int b = bh >> 4, h = bh & 15;
    const size_t qmbase = (size_t)b * SEQ + qt * 128;
    const size_t kmbase = (size_t)b * SEQ;
    const int colbase = h * D_HEAD;

    const uint32_t smbase = smem_u32(smb);

    const uint32_t offA  = (uint32_t)((rr + (sub & 1) * 8) * 272 + (sub >> 1) * 16);
    const uint32_t offB  = (uint32_t)((rr + (sub >> 1) * 8) * 272 + (sub & 1) * 16);

    // ---- load Q tile (hi+lo, 128 rows) ----
    {
        const __half* gq = g_qh + qmbase * D_MODEL + colbase;
        const __half* gl = g_ql + qmbase * D_MODEL + colbase;
        #pragma unroll
        for (int it = 0; it < 8; ++it) {
            const int c = it * 256 + tid;
            const int row = c >> 4, c16 = c & 15;
            const uint32_t dst = smbase + (uint32_t)(row * 272 + c16 * 16);
            CPA16(dst,             gq + (size_t)row * D_MODEL + c16 * 8);
            CPA16(dst + QT_TILE_B, gl + (size_t)row * D_MODEL + c16 * 8);
        }
        asm volatile("cp.async.commit_group;" ::: "memory");
    }
    // ---- load KV stage 0 ----
    {
        const size_t mrow = kmbase * D_MODEL + colbase;
        #pragma unroll
        for (int it = 0; it < 4; ++it) {
            const int c = it * 256 + tid;
            const int row = c >> 4, c16 = c & 15;
            const size_t so = (size_t)row * D_MODEL + c16 * 8;
            const uint32_t dst = smbase + (uint32_t)(KV_BASE_B + row * 272 + c16 * 16);
            CPA16(dst,                 g_kh + mrow + so);
            CPA16(dst + KV_TILE_B,     g_kl + mrow + so);
            CPA16(dst + 2*KV_TILE_B,   g_vh + mrow + so);
        }
        asm volatile("cp.async.commit_group;" ::: "memory");
    }
    asm volatile("cp.async.wait_group 0;" ::: "memory");
    __syncthreads();

    float O[16][4];
    #pragma unroll
    for (int nt = 0; nt < 16; ++nt)
        #pragma unroll
        for (int j = 0; j < 4; ++j) O[nt][j] = 0.f;
    float m0 = -1e30f, m1 = -1e30f, l0 = 0.f, l1 = 0.f;

    const uint32_t qBaseH = smbase + (uint32_t)(wid * 16 * 272) + offA;
    const uint32_t qBaseL = qBaseH + QT_TILE_B;

    for (int kt = 0; kt < SEQ/64; ++kt) {
        const int st = kt & 1;
        const uint32_t kBaseH = smbase + (uint32_t)(KV_BASE_B + st * KV_STG_B) + offB;
        const uint32_t kBaseL = kBaseH + KV_TILE_B;
        const uint32_t vBaseH = smbase + (uint32_t)(KV_BASE_B + st * KV_STG_B + 2*KV_TILE_B) + offA;

        // ---- S = Qn Kn^T, 3-pass (pass-reordered for acc ILP) ----
        float s[8][4];
        #pragma unroll
        for (int nt = 0; nt < 8; ++nt)
            #pragma unroll
            for (int j = 0; j < 4; ++j) s[nt][j] = 0.f;

        #pragma unroll
        for (int ks = 0; ks < 8; ++ks) {
            const uint32_t cb = (uint32_t)(ks * 32);
            uint32_t ah[4], al[4], bh2[8][2], bl2[8][2];
            LDSM4(ah[0], ah[1], ah[2], ah[3], qBaseH + cb);
            LDSM4(al[0], al[1], al[2], al[3], qBaseL + cb);
            #pragma unroll
            for (int p = 0; p < 4; ++p) {
                LDSM4(bh2[2*p][0], bh2[2*p][1], bh2[2*p+1][0], bh2[2*p+1][1],
                      kBaseH + (uint32_t)(p * 16 * 272) + cb);
                LDSM4(bl2[2*p][0], bl2[2*p][1], bl2[2*p+1][0], bl2[2*p+1][1],
                      kBaseL + (uint32_t)(p * 16 * 272) + cb);
            }
            #pragma unroll
            for (int nt = 0; nt < 8; ++nt)
                MMA(s[nt], ah, bh2[nt]);
            #pragma unroll
            for (int nt = 0; nt < 8; ++nt)
                MMA(s[nt], ah, bl2[nt]);
            #pragma unroll
            for (int nt = 0; nt < 8; ++nt)
                MMA(s[nt], al, bh2[nt]);
        }

        // ---- prefetch next KV (off the MMA critical path) ----
        if (kt + 1 < SEQ/64) {
            const size_t mrow = (kmbase + (kt + 1) * 64) * D_MODEL + colbase;
            const uint32_t sb = (uint32_t)(KV_BASE_B + (st ^ 1) * KV_STG_B);
            #pragma unroll
            for (int it = 0; it < 4; ++it) {
                const int c = it * 256 + tid;
                const int row = c >> 4, c16 = c & 15;
                const size_t so = (size_t)row * D_MODEL + c16 * 8;
                const uint32_t dst = smbase + sb + (uint32_t)(row * 272 + c16 * 16);
                CPA16(dst,               g_kh + mrow + so);
                CPA16(dst + KV_TILE_B,   g_kl + mrow + so);
                CPA16(dst + 2*KV_TILE_B, g_vh + mrow + so);
            }
            asm volatile("cp.async.commit_group;" ::: "memory");
        }

        // ---- online softmax ----
        float mx0 = -1e30f, mx1 = -1e30f;
        #pragma unroll
        for (int nt = 0; nt < 8; ++nt) {
            mx0 = fmaxf(mx0, fmaxf(s[nt][0], s[nt][1]));
            mx1 = fmaxf(mx1, fmaxf(s[nt][2], s[nt][3]));
        }
        mx0 = fmaxf(mx0, __shfl_xor_sync(0xffffffffu, mx0, 1));
        mx0 = fmaxf(mx0, __shfl_xor_sync(0xffffffffu, mx0, 2));
        mx1 = fmaxf(mx1, __shfl_xor_sync(0xffffffffu, mx1, 1));
        mx1 = fmaxf(mx1, __shfl_xor_sync(0xffffffffu, mx1, 2));
        const float mn0 = fmaxf(m0, mx0), mn1 = fmaxf(m1, mx1);
        const float corr0 = __expf(m0 - mn0), corr1 = __expf(m1 - mn1);
        m0 = mn0; m1 = mn1;

        uint32_t ph[8][2], pl[8][2];
        float rs0 = 0.f, rs1 = 0.f;
        #pragma unroll
        for (int nt = 0; nt < 8; ++nt) {
            float p0 = __expf(s[nt][0] - mn0);
            float p1 = __expf(s[nt][1] - mn0);
            float p2 = __expf(s[nt][2] - mn1);
            float p3 = __expf(s[nt][3] - mn1);
            rs0 += p0 + p1; rs1 += p2 + p3;
            __half2 h01, h23, lo01, lo23;
            h01.x = __float2half_rn(p0); h01.y = __float2half_rn(p1);
            h23.x = __float2half_rn(p2); h23.y = __float2half_rn(p3);
            lo01.x = __float2half_rn(p0 - __half2float(h01.x));
            lo01.y = __float2half_rn(p1 - __half2float(h01.y));
            lo23.x = __float2half_rn(p2 - __half2float(h23.x));
            lo23.y = __float2half_rn(p3 - __half2float(h23.y));
            ph[nt][0] = *(uint32_t*)&h01;  ph[nt][1] = *(uint32_t*)&h23;
            pl[nt][0] = *(uint32_t*)&lo01; pl[nt][1] = *(uint32_t*)&lo23;
        }
        rs0 += __shfl_xor_sync(0xffffffffu, rs0, 1);
        rs0 += __shfl_xor_sync(0xffffffffu, rs0, 2);
        rs1 += __shfl_xor_sync(0xffffffffu, rs1, 1);
        rs1 += __shfl_xor_sync(0xffffffffu, rs1, 2);
        l0 = l0 * corr0 + rs0;
        l1 = l1 * corr1 + rs1;
        #pragma unroll
        for (int nt = 0; nt < 16; ++nt) {
            O[nt][0] *= corr0; O[nt][1] *= corr0;
            O[nt][2] *= corr1; O[nt][3] *= corr1;
        }

        // ---- O += (Ph+Pl) Vh  (alternating accs for ILP) ----
        #pragma unroll
        for (int ks = 0; ks < 4; ++ks) {
            uint32_t a_h[4] = { ph[2*ks][0], ph[2*ks][1], ph[2*ks+1][0], ph[2*ks+1][1] };
            uint32_t a_l[4] = { pl[2*ks][0], pl[2*ks][1], pl[2*ks+1][0], pl[2*ks+1][1] };
            const uint32_t krow = (uint32_t)(ks * 16 * 272);
            #pragma unroll
            for (int ntp = 0; ntp < 8; ++ntp) {
                uint32_t vh0, vh1, vh2, vh3;
                LDSM4T(vh0, vh1, vh2, vh3, vBaseH + krow + (uint32_t)(ntp * 32));
                uint32_t b0[2] = { vh0, vh1 }, b1[2] = { vh2, vh3 };
                MMA(O[2*ntp],   a_h, b0);
                MMA(O[2*ntp+1], a_h, b1);
                MMA(O[2*ntp],   a_l, b0);
                MMA(O[2*ntp+1], a_l, b1);
            }
        }
        asm volatile("cp.async.wait_group 0;" ::: "memory");
        __syncthreads();
    }

    // ---- epilogue: O/l -> z fp16 hi/lo ----
    const float inv0 = 1.f / l0, inv1 = 1.f / l1;
    const size_t r0g = qmbase + wid * 16 + l4;
    const size_t r1g = r0g + 8;
    #pragma unroll
    for (int nt = 0; nt < 16; ++nt) {
        const int col = colbase + nt * 8 + 2 * l3;
        const float o0 = O[nt][0] * inv0, o1 = O[nt][1] * inv0;
        const float o2 = O[nt][2] * inv1, o3 = O[nt][3] * inv1;
        __half2 h01, h23, lo01, lo23;
        h01.x = __float2half_rn(o0); h01.y = __float2half_rn(o1);
        h23.x = __float2half_rn(o2); h23.y = __float2half_rn(o3);
        lo01.x = __float2half_rn(o0 - __half2float(h01.x));
        lo01.y = __float2half_rn(o1 - __half2float(h01.y));
        lo23.x = __float2half_rn(o2 - __half2float(h23.x));
        lo23.y = __float2half_rn(o3 - __half2float(h23.y));
        *(uint32_t*)&g_zh[r0g * D_MODEL + col] = *(uint32_t*)&h01;
        *(uint32_t*)&g_zl[r0g * D_MODEL + col] = *(uint32_t*)&lo01;
        *(uint32_t*)&g_zh[r1g * D_MODEL + col] = *(uint32_t*)&h23;
        *(uint32_t*)&g_zl[r1g * D_MODEL + col] = *(uint32_t*)&lo23;
    }
}

// -----------------------------------------------------------------------------
extern "C" void kernel_launch(void* const* d_in, const int* in_sizes, int n_in,
                              void* d_out, int out_size)
{
    const float* x     = (const float*)d_in[0];
    const float* W_qkv = (const float*)d_in[1];
    const float* b_qkv = (const float*)d_in[2];
    const float* W_o   = (const float*)d_in[3];
    const float* b_o   = (const float*)d_in[4];
    const float* wq    = (const float*)d_in[5];
    const float* wk    = (const float*)d_in[6];

    float* out   = (float*)d_out;
    float* k_out = out   + (size_t)M_TOT * D_MODEL;
    float* v_out = k_out + (size_t)M_TOT * D_MODEL;

    __half *xh, *xl, *wqh, *wql, *woh, *zh, *zl;
    cudaGetSymbolAddress((void**)&xh,  g_xh);
    cudaGetSymbolAddress((void**)&xl,  g_xl);
    cudaGetSymbolAddress((void**)&wqh, g_wqkvh);
    cudaGetSymbolAddress((void**)&wql, g_wqkvl);
    cudaGetSymbolAddress((void**)&woh, g_woh);
    cudaGetSymbolAddress((void**)&zh,  g_zh);
    cudaGetSymbolAddress((void**)&zl,  g_zl);

    static bool attr_set = false;
    if (!attr_set) {
        cudaFuncSetAttribute(gemm_tc<2,4>, cudaFuncAttributeMaxDynamicSharedMemorySize, GEMM_SMEM_QKV);
        cudaFuncSetAttribute(gemm_tc<3,3>, cudaFuncAttributeMaxDynamicSharedMemorySize, GEMM_SMEM_OP);
        cudaFuncSetAttribute(attn_tc, cudaFuncAttributeMaxDynamicSharedMemorySize, ATT_SMEM);
        attr_set = true;
    }

    // 0) all operand conversions in one launch (MLP=4)
    conv_all<<<BX4 + BW4 + BO4, 256>>>(x, W_qkv, W_o);

    // 1) qkv GEMM with fused rms-norm epilogue (q,k 3-pass; v 2-pass), 2-stage
    gemm_tc<2,4><<<dim3(NQKV/128, M_TOT/128), 256, GEMM_SMEM_QKV>>>(
        xh, xl, wqh, wql, b_qkv, nullptr, NQKV, D_MODEL, 2*D_MODEL, 1,
        k_out, v_out, wq, wk);

    // 2) attention -> g_zh/g_zl
    attn_tc<<<dim3(SEQ/128, BATCH*N_HEADS), 256, ATT_SMEM>>>();

    // 3) out = z @ W_o^T + b_o   (2-pass, 3-stage pipeline)
    gemm_tc<3,3><<<dim3(D_MODEL/128, M_TOT/128), 256, GEMM_SMEM_OP>>>(
        zh, zl, woh, woh, b_o, out, D_MODEL, D_MODEL, 0, 0,
        nullptr, nullptr, nullptr, nullptr);
}